// round 9
// baseline (speedup 1.0000x reference)
#include <cuda_runtime.h>
#include <cuda_bf16.h>
#include <math.h>
#include <stdint.h>

#define BB   4
#define SQL  512
#define SKL  512
#define DD   512
#define HH   8
#define DHH  64
#define BHH  32
#define MR   2048

// ---------------- f32 scratch ----------------
__device__ float g_qh[MR * DD];
__device__ float g_kh[MR * DD];
__device__ float g_vh[MR * DD];
__device__ float g_c [MR * HH];
__device__ float g_att[MR * DD];
__device__ float g_o2 [MR * DD];

// ---------------- bf16 hi/lo scratch ----------------
__device__ __nv_bfloat16 g_qi_h[MR * DD], g_qi_l[MR * DD];
__device__ __nv_bfloat16 g_ki_h[MR * DD], g_ki_l[MR * DD];
__device__ __nv_bfloat16 g_vi_h[MR * DD], g_vi_l[MR * DD];
__device__ __nv_bfloat16 g_wq_h[DD * DD], g_wq_l[DD * DD];
__device__ __nv_bfloat16 g_wk_h[DD * DD], g_wk_l[DD * DD];
__device__ __nv_bfloat16 g_wv_h[DD * DD], g_wv_l[DD * DD];
__device__ __nv_bfloat16 g_wo_h[DD * DD], g_wo_l[DD * DD];
__device__ __nv_bfloat16 g_wr_h[DD * DD], g_wr_l[DD * DD];
__device__ __nv_bfloat16 g_qv_h[MR * DD], g_qv_l[MR * DD];   // split(qh + v_bias)
__device__ __nv_bfloat16 g_qu_h[MR * DD], g_qu_l[MR * DD];   // split(qh + u_bias)
__device__ __nv_bfloat16 g_kh_h[MR * DD], g_kh_l[MR * DD];   // split(kh)
__device__ __nv_bfloat16 g_vt_h[BB * DD * SKL], g_vt_l[BB * DD * SKL]; // [(b*512+dcol)][seq]
__device__ __nv_bfloat16 g_T_h[SQL * BHH * DD], g_T_l[SQL * BHH * DD]; // [q][bh][e]
__device__ __nv_bfloat16 g_at_h[MR * DD], g_at_l[MR * DD];

__device__ unsigned char g_am [SQL * SKL];
__device__ unsigned char g_kpm[BB * SKL];
__device__ unsigned int g_or1, g_or23;

// ===========================================================================
// helpers
// ===========================================================================
__device__ __forceinline__ uint32_t smem_u32(const void* p) {
    uint32_t a;
    asm("{ .reg .u64 t; cvta.to.shared.u64 t, %1; cvt.u32.u64 %0, t; }" : "=r"(a) : "l"(p));
    return a;
}
__device__ __forceinline__ uint32_t pack_bf16x2(float x, float y) {
    uint32_t r;
    asm("cvt.rn.bf16x2.f32 %0, %1, %2;" : "=r"(r) : "f"(y), "f"(x));
    return r;
}
__device__ __forceinline__ float bf_lo(uint32_t w) { return __uint_as_float(w << 16); }
__device__ __forceinline__ float bf_hi(uint32_t w) { return __uint_as_float(w & 0xffff0000u); }

#define MMA_BF16(c, a, b0, b1) \
    asm volatile("mma.sync.aligned.m16n8k16.row.col.f32.bf16.bf16.f32 " \
        "{%0,%1,%2,%3}, {%4,%5,%6,%7}, {%8,%9}, {%0,%1,%2,%3};" \
        : "+f"((c)[0]), "+f"((c)[1]), "+f"((c)[2]), "+f"((c)[3]) \
        : "r"((a)[0]), "r"((a)[1]), "r"((a)[2]), "r"((a)[3]), "r"(b0), "r"(b1))

__device__ __forceinline__ void cpa16(const void* s, const void* g) {
    asm volatile("cp.async.ca.shared.global [%0], [%1], 16;" :: "r"(smem_u32(s)), "l"(g));
}
__device__ __forceinline__ void split2(float x, float y, uint32_t& h, uint32_t& l) {
    h = pack_bf16x2(x, y);
    l = pack_bf16x2(x - bf_lo(h), y - bf_hi(h));
}
__device__ __forceinline__ int bytes_all_nz(unsigned int v)
{
    return (((v - 0x01010101u) & ~v) & 0x80808080u) == 0u;
}

// ===========================================================================
// Conversion kernels
// ===========================================================================
__global__ void conv_inputs(const float* __restrict__ q, const float* __restrict__ k,
                            const float* __restrict__ v)
{
    const float* src = (blockIdx.z == 0) ? q : (blockIdx.z == 1) ? k : v;
    __nv_bfloat16* dh = (blockIdx.z == 0) ? g_qi_h : (blockIdx.z == 1) ? g_ki_h : g_vi_h;
    __nv_bfloat16* dl = (blockIdx.z == 0) ? g_qi_l : (blockIdx.z == 1) ? g_ki_l : g_vi_l;
    int idx = (blockIdx.x * blockDim.x + threadIdx.x) * 4;
    if (idx >= MR * DD) return;
    float4 a = *(const float4*)(src + idx);
    uint32_t h0, l0, h1, l1;
    split2(a.x, a.y, h0, l0);
    split2(a.z, a.w, h1, l1);
    *(uint2*)((uint16_t*)dh + idx) = make_uint2(h0, h1);
    *(uint2*)((uint16_t*)dl + idx) = make_uint2(l0, l1);
}

// W[k][n] -> out[n][k] hi/lo (transpose)
__global__ void conv_w(const float* __restrict__ Wq, const float* __restrict__ Wk,
                       const float* __restrict__ Wv, const float* __restrict__ Wo)
{
    __shared__ float s[32][33];
    const float* W = (blockIdx.z == 0) ? Wq : (blockIdx.z == 1) ? Wk : (blockIdx.z == 2) ? Wv : Wo;
    __nv_bfloat16* dh = (blockIdx.z == 0) ? g_wq_h : (blockIdx.z == 1) ? g_wk_h : (blockIdx.z == 2) ? g_wv_h : g_wo_h;
    __nv_bfloat16* dl = (blockIdx.z == 0) ? g_wq_l : (blockIdx.z == 1) ? g_wk_l : (blockIdx.z == 2) ? g_wv_l : g_wo_l;
    int k0 = blockIdx.y * 32, n0 = blockIdx.x * 32;
    int tx = threadIdx.x, ty = threadIdx.y;
    s[ty][tx] = W[(size_t)(k0 + ty) * DD + n0 + tx];
    __syncthreads();
    float vv = s[tx][ty];
    __nv_bfloat16 hb = __float2bfloat16_rn(vv);
    __nv_bfloat16 lb = __float2bfloat16_rn(vv - __bfloat162float(hb));
    dh[(size_t)(n0 + ty) * DD + k0 + tx] = hb;
    dl[(size_t)(n0 + ty) * DD + k0 + tx] = lb;
}

__global__ void conv_wr(const float* __restrict__ Wr)
{
    int idx = (blockIdx.x * blockDim.x + threadIdx.x) * 4;
    if (idx >= DD * DD) return;
    float4 a = *(const float4*)(Wr + idx);
    uint32_t h0, l0, h1, l1;
    split2(a.x, a.y, h0, l0);
    split2(a.z, a.w, h1, l1);
    *(uint2*)((uint16_t*)g_wr_h + idx) = make_uint2(h0, h1);
    *(uint2*)((uint16_t*)g_wr_l + idx) = make_uint2(l0, l1);
}

// vh[b][seq][dcol] -> vt[b][dcol][seq] hi/lo
__global__ void conv_vt()
{
    __shared__ float s[32][33];
    int b = blockIdx.z;
    int s0 = blockIdx.y * 32, d0 = blockIdx.x * 32;
    int tx = threadIdx.x, ty = threadIdx.y;
    s[ty][tx] = g_vh[((size_t)b * SQL + s0 + ty) * DD + d0 + tx];
    __syncthreads();
    float vv = s[tx][ty];   // vh[seq=s0+tx][d=d0+ty]
    __nv_bfloat16 hb = __float2bfloat16_rn(vv);
    __nv_bfloat16 lb = __float2bfloat16_rn(vv - __bfloat162float(hb));
    size_t di = ((size_t)b * DD + d0 + ty) * SKL + s0 + tx;
    g_vt_h[di] = hb;
    g_vt_l[di] = lb;
}

// ===========================================================================
// Mask normalization
// ===========================================================================
__global__ void zero_flags() { g_or1 = 0; g_or23 = 0; }

__global__ void mask_detect(const unsigned char* __restrict__ am)
{
    unsigned int or1 = 0, or23 = 0;
    const uint4* p = (const uint4*)am;
    int n16 = SQL * SKL / 16;
    for (int i = blockIdx.x * blockDim.x + threadIdx.x; i < n16; i += gridDim.x * blockDim.x) {
        uint4 v = p[i];
        or1  |= (v.x & 0x0000FF00u) | (v.y & 0x0000FF00u) | (v.z & 0x0000FF00u) | (v.w & 0x0000FF00u);
        or23 |= (v.x & 0xFFFF0000u) | (v.y & 0xFFFF0000u) | (v.z & 0xFFFF0000u) | (v.w & 0xFFFF0000u);
    }
    int a1 = __syncthreads_or((int)(or1 != 0));
    int a23 = __syncthreads_or((int)(or23 != 0));
    if (threadIdx.x == 0) {
        if (a1) atomicOr(&g_or1, 1u);
        if (a23) atomicOr(&g_or23, 1u);
    }
}

__global__ void mask_convert(const unsigned char* __restrict__ am,
                             const unsigned char* __restrict__ kpm)
{
    int mode = g_or1 ? 1 : (g_or23 ? 2 : 0);
    int stride = gridDim.x * blockDim.x;
    int tid = blockIdx.x * blockDim.x + threadIdx.x;
    for (int i = tid; i < SQL * SKL; i += stride) {
        unsigned char v;
        if (mode == 1)      v = (am[i] != 0);
        else if (mode == 2) v = (((const float*)am)[i] != 0.0f);
        else                v = (((const int*)am)[i] != 0);
        g_am[i] = v;
    }
    for (int i = tid; i < BB * SKL; i += stride) {
        unsigned char v;
        if (mode == 1)      v = (kpm[i] != 0);
        else if (mode == 2) v = (((const float*)kpm)[i] != 0.0f);
        else                v = (((const int*)kpm)[i] != 0);
        g_kpm[i] = v;
    }
}

// ===========================================================================
// mma2: C[2048,512] = A @ W + bias (+resid). Optional dual split outputs:
//   o2 = split(C + rb2), o3 = split(C + rb3)
// ===========================================================================
__global__ void __launch_bounds__(256, 2)
mma2(const __nv_bfloat16* __restrict__ Ahg, const __nv_bfloat16* __restrict__ Alg,
     const __nv_bfloat16* __restrict__ Bhg, const __nv_bfloat16* __restrict__ Blg,
     const float* __restrict__ bias, const float* __restrict__ resid,
     float* __restrict__ C,
     __nv_bfloat16* __restrict__ o2h, __nv_bfloat16* __restrict__ o2l,
     const float* __restrict__ rb2,
     __nv_bfloat16* __restrict__ o3h, __nv_bfloat16* __restrict__ o3l,
     const float* __restrict__ rb3)
{
    __shared__ __align__(16) __nv_bfloat16 sA[2][2][64][40];
    __shared__ __align__(16) __nv_bfloat16 sB[2][2][64][40];
    int tid = threadIdx.x, lane = tid & 31, wid = tid >> 5;
    int wm = wid >> 2, wn = wid & 3;
    int row0 = blockIdx.y * 64, n0 = blockIdx.x * 64;
    int r = lane >> 2, t4 = lane & 3;
    float acc[2][2][4] = {};
    int lrow = tid >> 2, lco = (tid & 3) * 8;

    {
        int k0 = 0;
        cpa16(&sA[0][0][lrow][lco], (const uint16_t*)Ahg + (size_t)(row0 + lrow) * DD + k0 + lco);
        cpa16(&sA[0][1][lrow][lco], (const uint16_t*)Alg + (size_t)(row0 + lrow) * DD + k0 + lco);
        cpa16(&sB[0][0][lrow][lco], (const uint16_t*)Bhg + (size_t)(n0 + lrow) * DD + k0 + lco);
        cpa16(&sB[0][1][lrow][lco], (const uint16_t*)Blg + (size_t)(n0 + lrow) * DD + k0 + lco);
        asm volatile("cp.async.commit_group;");
    }
    #pragma unroll 1
    for (int it = 0; it < 16; it++) {
        if (it + 1 < 16) {
            int st = (it + 1) & 1, k0 = (it + 1) * 32;
            cpa16(&sA[st][0][lrow][lco], (const uint16_t*)Ahg + (size_t)(row0 + lrow) * DD + k0 + lco);
            cpa16(&sA[st][1][lrow][lco], (const uint16_t*)Alg + (size_t)(row0 + lrow) * DD + k0 + lco);
            cpa16(&sB[st][0][lrow][lco], (const uint16_t*)Bhg + (size_t)(n0 + lrow) * DD + k0 + lco);
            cpa16(&sB[st][1][lrow][lco], (const uint16_t*)Blg + (size_t)(n0 + lrow) * DD + k0 + lco);
            asm volatile("cp.async.commit_group;");
            asm volatile("cp.async.wait_group 1;");
        } else {
            asm volatile("cp.async.wait_group 0;");
        }
        __syncthreads();
        int st = it & 1;
        #pragma unroll
        for (int ks = 0; ks < 2; ks++) {
            uint32_t ah[2][4], al[2][4];
            #pragma unroll
            for (int mi = 0; mi < 2; mi++) {
                int row = wm * 32 + mi * 16 + r;
                const __nv_bfloat16* ph = &sA[st][0][row][ks * 16 + t4 * 2];
                const __nv_bfloat16* pl = &sA[st][1][row][ks * 16 + t4 * 2];
                ah[mi][0] = *(const uint32_t*)ph;
                ah[mi][1] = *(const uint32_t*)(ph + 8 * 40);
                ah[mi][2] = *(const uint32_t*)(ph + 8);
                ah[mi][3] = *(const uint32_t*)(ph + 8 * 40 + 8);
                al[mi][0] = *(const uint32_t*)pl;
                al[mi][1] = *(const uint32_t*)(pl + 8 * 40);
                al[mi][2] = *(const uint32_t*)(pl + 8);
                al[mi][3] = *(const uint32_t*)(pl + 8 * 40 + 8);
            }
            #pragma unroll
            for (int nj = 0; nj < 2; nj++) {
                int n = wn * 16 + nj * 8 + r;
                const __nv_bfloat16* qh = &sB[st][0][n][ks * 16 + t4 * 2];
                const __nv_bfloat16* ql = &sB[st][1][n][ks * 16 + t4 * 2];
                uint32_t bh0 = *(const uint32_t*)qh, bh1 = *(const uint32_t*)(qh + 8);
                uint32_t bl0 = *(const uint32_t*)ql, bl1 = *(const uint32_t*)(ql + 8);
                #pragma unroll
                for (int mi = 0; mi < 2; mi++) {
                    MMA_BF16(acc[mi][nj], ah[mi], bh0, bh1);
                    MMA_BF16(acc[mi][nj], ah[mi], bl0, bl1);
                    MMA_BF16(acc[mi][nj], al[mi], bh0, bh1);
                }
            }
        }
        __syncthreads();
    }
    #pragma unroll
    for (int mi = 0; mi < 2; mi++) {
        #pragma unroll
        for (int nj = 0; nj < 2; nj++) {
            int col = n0 + wn * 16 + nj * 8 + t4 * 2;
            float b0 = bias[col], b1 = bias[col + 1];
            float rb20 = rb2 ? rb2[col] : 0.f;
            float rb21 = rb2 ? rb2[col + 1] : 0.f;
            float rb30 = rb3 ? rb3[col] : 0.f;
            float rb31 = rb3 ? rb3[col + 1] : 0.f;
            #pragma unroll
            for (int rr = 0; rr < 2; rr++) {
                int row = row0 + wm * 32 + mi * 16 + r + rr * 8;
                float v0 = acc[mi][nj][rr * 2 + 0] + b0;
                float v1 = acc[mi][nj][rr * 2 + 1] + b1;
                if (resid) {
                    float2 r2 = *(const float2*)(resid + (size_t)row * DD + col);
                    v0 += r2.x; v1 += r2.y;
                }
                *(float2*)(C + (size_t)row * DD + col) = make_float2(v0, v1);
                if (o2h) {
                    uint32_t h, l;
                    split2(v0 + rb20, v1 + rb21, h, l);
                    *(uint32_t*)((uint16_t*)o2h + (size_t)row * DD + col) = h;
                    *(uint32_t*)((uint16_t*)o2l + (size_t)row * DD + col) = l;
                }
                if (o3h) {
                    uint32_t h, l;
                    split2(v0 + rb30, v1 + rb31, h, l);
                    *(uint32_t*)((uint16_t*)o3h + (size_t)row * DD + col) = h;
                    *(uint32_t*)((uint16_t*)o3l + (size_t)row * DD + col) = l;
                }
            }
        }
    }
}

// ===========================================================================
// t_mma: T[q][bh][e] (hi/lo) = (qh + v_bias) @ Wr_h^T, per head.
// ===========================================================================
__global__ void __launch_bounds__(256, 2)
t_mma()
{
    __shared__ __align__(16) __nv_bfloat16 tA[2][64][72];
    __shared__ __align__(16) __nv_bfloat16 tB[2][64][72];
    int tid = threadIdx.x, lane = tid & 31, wid = tid >> 5;
    int wm = wid >> 2, wn = wid & 3;
    int h = blockIdx.z, hoff = h * DHH;
    int m0 = blockIdx.y * 64, e0 = blockIdx.x * 64;
    int r = lane >> 2, t4 = lane & 3;
    float acc[2][2][4] = {};

    #pragma unroll
    for (int j = 0; j < 2; j++) {
        int c = tid + j * 256;
        int row = c >> 3, off = (c & 7) * 8;
        *(uint4*)&tA[0][row][off] = *(const uint4*)((const uint16_t*)g_qv_h + (size_t)(m0 + row) * DD + hoff + off);
        *(uint4*)&tA[1][row][off] = *(const uint4*)((const uint16_t*)g_qv_l + (size_t)(m0 + row) * DD + hoff + off);
        *(uint4*)&tB[0][row][off] = *(const uint4*)((const uint16_t*)g_wr_h + (size_t)(e0 + row) * DD + hoff + off);
        *(uint4*)&tB[1][row][off] = *(const uint4*)((const uint16_t*)g_wr_l + (size_t)(e0 + row) * DD + hoff + off);
    }
    __syncthreads();

    #pragma unroll
    for (int ks = 0; ks < 4; ks++) {
        uint32_t ah[2][4], al[2][4];
        #pragma unroll
        for (int mi = 0; mi < 2; mi++) {
            int row = wm * 32 + mi * 16 + r;
            const __nv_bfloat16* ph = &tA[0][row][ks * 16 + t4 * 2];
            const __nv_bfloat16* pl = &tA[1][row][ks * 16 + t4 * 2];
            ah[mi][0] = *(const uint32_t*)ph;
            ah[mi][1] = *(const uint32_t*)(ph + 8 * 72);
            ah[mi][2] = *(const uint32_t*)(ph + 8);
            ah[mi][3] = *(const uint32_t*)(ph + 8 * 72 + 8);
            al[mi][0] = *(const uint32_t*)pl;
            al[mi][1] = *(const uint32_t*)(pl + 8 * 72);
            al[mi][2] = *(const uint32_t*)(pl + 8);
            al[mi][3] = *(const uint32_t*)(pl + 8 * 72 + 8);
        }
        #pragma unroll
        for (int nj = 0; nj < 2; nj++) {
            int n = wn * 16 + nj * 8 + r;
            const __nv_bfloat16* qh = &tB[0][n][ks * 16 + t4 * 2];
            const __nv_bfloat16* ql = &tB[1][n][ks * 16 + t4 * 2];
            uint32_t bh0 = *(const uint32_t*)qh, bh1 = *(const uint32_t*)(qh + 8);
            uint32_t bl0 = *(const uint32_t*)ql, bl1 = *(const uint32_t*)(ql + 8);
            #pragma unroll
            for (int mi = 0; mi < 2; mi++) {
                MMA_BF16(acc[mi][nj], ah[mi], bh0, bh1);
                MMA_BF16(acc[mi][nj], ah[mi], bl0, bl1);
                MMA_BF16(acc[mi][nj], al[mi], bh0, bh1);
            }
        }
    }
    #pragma unroll
    for (int mi = 0; mi < 2; mi++) {
        #pragma unroll
        for (int nj = 0; nj < 2; nj++) {
            int e = e0 + wn * 16 + nj * 8 + t4 * 2;
            #pragma unroll
            for (int rr = 0; rr < 2; rr++) {
                int m = m0 + wm * 32 + mi * 16 + r + rr * 8;
                int q = m & 511, b = m >> 9;
                int bh = b * HH + h;
                uint32_t hh, ll;
                split2(acc[mi][nj][rr * 2 + 0], acc[mi][nj][rr * 2 + 1], hh, ll);
                size_t di = ((size_t)q * BHH + bh) * DD + e;
                *(uint32_t*)((uint16_t*)g_T_h + di) = hh;
                *(uint32_t*)((uint16_t*)g_T_l + di) = ll;
            }
        }
    }
}

// c[b,q,h] = sum_d (qh+v_bias)*br_h
__global__ void c_kernel(const float* __restrict__ vb, const float* __restrict__ br)
{
    int idx = blockIdx.x * blockDim.x + threadIdx.x;
    if (idx >= MR * HH) return;
    int h = idx & 7;
    int m = idx >> 3;
    int hoff = h * DHH;
    const float* qrow = g_qh + (size_t)m * DD + hoff;
    float s = 0.f;
    #pragma unroll 8
    for (int d = 0; d < DHH; d++)
        s += (qrow[d] + vb[hoff + d]) * br[hoff + d];
    g_c[idx] = s;
}

// ===========================================================================
// ac_mma: score[bh,q,k] = (qh+u) . kh  (raw).  M=64(q) N=64(k) K=64(d).
// Fragments loaded directly from pre-split gmem buffers.
// ===========================================================================
__global__ void __launch_bounds__(256, 2)
ac_mma(float* __restrict__ score)
{
    int bh = blockIdx.z, b = bh >> 3, h = bh & 7, hoff = h * DHH;
    int q0 = blockIdx.y * 64, k0 = blockIdx.x * 64;
    int tid = threadIdx.x, lane = tid & 31, wid = tid >> 5;
    int wm = wid >> 1, wn = wid & 1;
    int r = lane >> 2, t4 = lane & 3;

    {   // 64x64 full-tile mask check (verified from data; exact)
        const uint4* mp = (const uint4*)(g_am + (size_t)(q0 + (tid >> 1)) * SKL + k0 + (tid & 1) * 32);
        uint4 m1 = mp[0], m2 = mp[1];
        int allm = bytes_all_nz(m1.x) & bytes_all_nz(m1.y) & bytes_all_nz(m1.z) & bytes_all_nz(m1.w)
                 & bytes_all_nz(m2.x) & bytes_all_nz(m2.y) & bytes_all_nz(m2.z) & bytes_all_nz(m2.w);
        if (__syncthreads_and(allm)) return;
    }

    float acc[4][4] = {};
    const uint16_t* Ah = (const uint16_t*)g_qu_h;
    const uint16_t* Al = (const uint16_t*)g_qu_l;
    const uint16_t* Bh = (const uint16_t*)g_kh_h;
    const uint16_t* Bl = (const uint16_t*)g_kh_l;

    #pragma unroll
    for (int ks = 0; ks < 4; ks++) {
        int c = ks * 16 + t4 * 2;
        size_t abase = ((size_t)(b * SQL + q0 + wm * 16 + r)) * DD + hoff + c;
        uint32_t ah[4], al[4];
        ah[0] = *(const uint32_t*)(Ah + abase);
        ah[1] = *(const uint32_t*)(Ah + abase + 8 * DD);
        ah[2] = *(const uint32_t*)(Ah + abase + 8);
        ah[3] = *(const uint32_t*)(Ah + abase + 8 * DD + 8);
        al[0] = *(const uint32_t*)(Al + abase);
        al[1] = *(const uint32_t*)(Al + abase + 8 * DD);
        al[2] = *(const uint32_t*)(Al + abase + 8);
        al[3] = *(const uint32_t*)(Al + abase + 8 * DD + 8);
        #pragma unroll
        for (int nj = 0; nj < 4; nj++) {
            int n = wn * 32 + nj * 8 + r;
            size_t bbase = ((size_t)(b * SQL + k0 + n)) * DD + hoff + c;
            uint32_t bh0 = *(const uint32_t*)(Bh + bbase);
            uint32_t bh1 = *(const uint32_t*)(Bh + bbase + 8);
            uint32_t bl0 = *(const uint32_t*)(Bl + bbase);
            uint32_t bl1 = *(const uint32_t*)(Bl + bbase + 8);
            MMA_BF16(acc[nj], ah, bh0, bh1);
            MMA_BF16(acc[nj], ah, bl0, bl1);
            MMA_BF16(acc[nj], al, bh0, bh1);
        }
    }
    #pragma unroll
    for (int nj = 0; nj < 4; nj++) {
        int k = k0 + wn * 32 + nj * 8 + t4 * 2;
        #pragma unroll
        for (int rr = 0; rr < 2; rr++) {
            int q = q0 + wm * 16 + r + rr * 8;
            *(float2*)(score + ((size_t)bh * SQL + q) * SKL + k) =
                make_float2(acc[nj][rr * 2 + 0], acc[nj][rr * 2 + 1]);
        }
    }
}

// ===========================================================================
// bd_mma: score[bh,q,k] = (ac + T[q,bh,:]@pos_emb[q,k,:] + c)/8 via mma.
// ===========================================================================
__global__ void __launch_bounds__(256)
bd_mma(const float* __restrict__ pos_emb, float* __restrict__ score)
{
    __shared__ __align__(16) __nv_bfloat16 sT[2][32][136];
    int q = blockIdx.x;
    int tid = threadIdx.x, lane = tid & 31, wn = tid >> 5;
    int r = lane >> 2, t4 = lane & 3;

    int k_a = wn * 64 + lane * 2;
    unsigned char ma = g_am[(size_t)q * SKL + k_a];
    unsigned char mb = g_am[(size_t)q * SKL + k_a + 1];
    int act = __ballot_sync(0xffffffffu, (ma == 0) || (mb == 0)) != 0;

    float acc[2][8][4] = {};

    #pragma unroll 1
    for (int ec = 0; ec < 4; ec++) {
        #pragma unroll
        for (int j = 0; j < 2; j++) {
            int c = tid + j * 256;
            int row = c >> 4, off = (c & 15) * 8;
            size_t gi = ((size_t)q * BHH + row) * DD + ec * 128 + off;
            *(uint4*)&sT[0][row][off] = *(const uint4*)((const uint16_t*)g_T_h + gi);
            *(uint4*)&sT[1][row][off] = *(const uint4*)((const uint16_t*)g_T_l + gi);
        }
        __syncthreads();
        if (act) {
            #pragma unroll 1
            for (int ks = 0; ks < 8; ks++) {
                uint32_t ah[2][4], al[2][4];
                #pragma unroll
                for (int mi = 0; mi < 2; mi++) {
                    int row = mi * 16 + r;
                    const __nv_bfloat16* ph = &sT[0][row][ks * 16 + t4 * 2];
                    const __nv_bfloat16* pl = &sT[1][row][ks * 16 + t4 * 2];
                    ah[mi][0] = *(const uint32_t*)ph;
                    ah[mi][1] = *(const uint32_t*)(ph + 8 * 136);
                    ah[mi][2] = *(const uint32_t*)(ph + 8);
                    ah[mi][3] = *(const uint32_t*)(ph + 8 * 136 + 8);
                    al[mi][0] = *(const uint32_t*)pl;
                    al[mi][1] = *(const uint32_t*)(pl + 8 * 136);
                    al[mi][2] = *(const uint32_t*)(pl + 8);
                    al[mi][3] = *(const uint32_t*)(pl + 8 * 136 + 8);
                }
                int eg = ec * 128 + ks * 16 + t4 * 2;
                #pragma unroll
                for (int nj = 0; nj < 8; nj++) {
                    int n = wn * 64 + nj * 8 + r;
                    const float* pp = pos_emb + ((size_t)q * SKL + n) * DD + eg;
                    float2 p0 = *(const float2*)pp;
                    float2 p1 = *(const float2*)(pp + 8);
                    uint32_t bh0, bl0, bh1, bl1;
                    split2(p0.x, p0.y, bh0, bl0);
                    split2(p1.x, p1.y, bh1, bl1);
                    #pragma unroll
                    for (int mi = 0; mi < 2; mi++) {
                        MMA_BF16(acc[mi][nj], ah[mi], bh0, bh1);
                        MMA_BF16(acc[mi][nj], ah[mi], bl0, bl1);
                        MMA_BF16(acc[mi][nj], al[mi], bh0, bh1);
                    }
                }
            }
        }
        __syncthreads();
    }
    if (!act) return;
    #pragma unroll
    for (int mi = 0; mi < 2; mi++) {
        #pragma unroll
        for (int rr = 0; rr < 2; rr++) {
            int bh = mi * 16 + r + rr * 8;
            int b = bh >> 3, h = bh & 7;
            float cc = g_c[((size_t)b * SQL + q) * HH + h];
            float* srow = score + ((size_t)bh * SQL + q) * SKL;
            #pragma unroll
            for (int nj = 0; nj < 8; nj++) {
                int k = wn * 64 + nj * 8 + t4 * 2;
                float2 s2 = *(float2*)(srow + k);
                s2.x = (s2.x + acc[mi][nj][rr * 2 + 0] + cc) * 0.125f;
                s2.y = (s2.y + acc[mi][nj][rr * 2 + 1] + cc) * 0.125f;
                *(float2*)(srow + k) = s2;
            }
        }
    }
}

// ===========================================================================
// softmax: 2 rows per 256-thread block
// ===========================================================================
__global__ void softmax_kernel(float* __restrict__ score)
{
    int sub = threadIdx.x >> 7;           // 0/1
    int t   = threadIdx.x & 127;
    int row = blockIdx.x * 2 + sub;
    int q = row & 511;
    int bh = row >> 9;
    int b = bh >> 3;
    float* s = score + (size_t)row * SKL;

    float4 v4 = *(float4*)(s + t * 4);
    float vals[4] = {v4.x, v4.y, v4.z, v4.w};
    const unsigned char* amr = g_am + (size_t)q * SKL + t * 4;
    const unsigned char* kpr = g_kpm + (size_t)b * SKL + t * 4;
    #pragma unroll
    for (int j = 0; j < 4; j++)
        if (amr[j] || kpr[j]) vals[j] = -INFINITY;

    float mx = fmaxf(fmaxf(vals[0], vals[1]), fmaxf(vals[2], vals[3]));
    #pragma unroll
    for (int off = 16; off; off >>= 1)
        mx = fmaxf(mx, __shfl_xor_sync(0xffffffffu, mx, off));
    __shared__ float sm[2][4], ssum[2][4];
    int wir = t >> 5, lane = t & 31;
    if (lane == 0) sm[sub][wir] = mx;
    __syncthreads();
    mx = fmaxf(fmaxf(sm[sub][0], sm[sub][1]), fmaxf(sm[sub][2], sm[sub][3]));

    float e[4]; float sum = 0.f;
    #pragma unroll
    for (int j = 0; j < 4; j++) {
        e[j] = (vals[j] == -INFINITY) ? 0.f : __expf(vals[j] - mx);
        sum += e[j];
    }
    #pragma unroll
    for (int off = 16; off; off >>= 1)
        sum += __shfl_xor_sync(0xffffffffu, sum, off);
    if (lane == 0) ssum[sub][wir] = sum;
    __syncthreads();
    sum = ssum[sub][0] + ssum[sub][1] + ssum[sub][2] + ssum[sub][3];
    float inv = (sum > 0.f) ? 1.f / sum : 0.f;
    float4 o = {e[0] * inv, e[1] * inv, e[2] * inv, e[3] * inv};
    *(float4*)(s + t * 4) = o;
}

// ===========================================================================
// av_mma: att[b,q,hoff+d] = sum_k w[bh,q,k] * vt[b,hoff+d,k].
// M=64(q) N=64(d) K=512(seq), exact skip of all-masked k16 chunks.
// Weights split on the fly; vt pre-split. Fused hi/lo split of output.
// ===========================================================================
__global__ void __launch_bounds__(256)
av_mma(const float* __restrict__ score)
{
    __shared__ uint32_t actmask;
    int bh = blockIdx.y, b = bh >> 3, h = bh & 7, hoff = h * DHH;
    int q0 = blockIdx.x * 64;
    int tid = threadIdx.x, lane = tid & 31, wid = tid >> 5;
    int wm = wid >> 1, wn = wid & 1;
    int r = lane >> 2, t4 = lane & 3;

    if (tid == 0) actmask = 0;
    __syncthreads();
    {   // chunk activity: chunk=tid&31 (16 k-cols), rows (tid>>5)*8..+8
        int ch = tid & 31;
        int r0 = (tid >> 5) * 8;
        int anyact = 0;
        #pragma unroll
        for (int i = 0; i < 8; i++) {
            const uint4* mp = (const uint4*)(g_am + (size_t)(q0 + r0 + i) * SKL + ch * 16);
            uint4 m = *mp;
            int allnz = bytes_all_nz(m.x) & bytes_all_nz(m.y) & bytes_all_nz(m.z) & bytes_all_nz(m.w);
            anyact |= !allnz;
        }
        if (__ballot_sync(0xffffffffu, anyact) && (lane == 0 ? anyact : 0)) {}
        if (anyact) atomicOr(&actmask, 1u << ch);
    }
    __syncthreads();
    uint32_t amk = actmask;

    float acc[4][4] = {};
    const uint16_t* Bh = (const uint16_t*)g_vt_h;
    const uint16_t* Bl = (const uint16_t*)g_vt_l;

    #pragma unroll 1
    for (int kc = 0; kc < 32; kc++) {
        if (!((amk >> kc) & 1u)) continue;
        int c = kc * 16 + t4 * 2;
        const float* arow = score + ((size_t)(bh * SQL + q0 + wm * 16 + r)) * SKL + c;
        float2 f00 = *(const float2*)arow;
        float2 f10 = *(const float2*)(arow + 8 * SKL);
        float2 f01 = *(const float2*)(arow + 8);
        float2 f11 = *(const float2*)(arow + 8 * SKL + 8);
        uint32_t ah[4], al[4];
        split2(f00.x, f00.y, ah[0], al[0]);
        split2(f10.x, f10.y, ah[1], al[1]);
        split2(f01.x, f01.y, ah[2], al[2]);
        split2(f11.x, f11.y, ah[3], al[3]);
        #pragma unroll
        for (int nj = 0; nj < 4; nj++) {
            int n = wn * 32 + nj * 8 + r;
            size_t bb = ((size_t)(b * DD + hoff + n)) * SKL + c;
            uint32_t bh0 = *(const uint32_t*)(Bh + bb);
            uint32_t bh1 = *(const uint32_t*)(Bh + bb + 8);
            uint32_t bl0 = *(const uint32_t*)(Bl + bb);
            uint32_t bl1 = *(const uint32_t*)(Bl + bb + 8);
            MMA_BF16(acc[nj], ah, bh0, bh1);
            MMA_BF16(acc[nj], ah, bl0, bl1);
            MMA_BF16(acc[nj], al, bh0, bh1);
        }
    }
    #pragma unroll
    for (int nj = 0; nj < 4; nj++) {
        int dcol = hoff + wn * 32 + nj * 8 + t4 * 2;
        #pragma unroll
        for (int rr = 0; rr < 2; rr++) {
            int q = q0 + wm * 16 + r + rr * 8;
            size_t oi = ((size_t)(b * SQL + q)) * DD + dcol;
            float v0 = acc[nj][rr * 2 + 0], v1 = acc[nj][rr * 2 + 1];
            *(float2*)(g_att + oi) = make_float2(v0, v1);
            uint32_t hh, ll;
            split2(v0, v1, hh, ll);
            *(uint32_t*)((uint16_t*)g_at_h + oi) = hh;
            *(uint32_t*)((uint16_t*)g_at_l + oi) = ll;
        }
    }
}

// ===========================================================================
__global__ void ln_kernel(const float* __restrict__ X, const float* __restrict__ gamma,
                          const float* __restrict__ beta, float* __restrict__ out)
{
    int row = blockIdx.x;
    int tid = threadIdx.x;  // 256
    const float* x = X + (size_t)row * DD;
    float2 v = *(const float2*)(x + tid * 2);
    float s = v.x + v.y;
    float s2 = v.x * v.x + v.y * v.y;
    #pragma unroll
    for (int off = 16; off; off >>= 1) {
        s  += __shfl_xor_sync(0xffffffffu, s, off);
        s2 += __shfl_xor_sync(0xffffffffu, s2, off);
    }
    __shared__ float rs[8], rs2[8];
    int wid = tid >> 5, lane = tid & 31;
    if (lane == 0) { rs[wid] = s; rs2[wid] = s2; }
    __syncthreads();
    s = 0.f; s2 = 0.f;
    #pragma unroll
    for (int i = 0; i < 8; i++) { s += rs[i]; s2 += rs2[i]; }
    float mean = s * (1.f / DD);
    float var = s2 * (1.f / DD) - mean * mean;
    float inv = rsqrtf(var + 1e-5f);
    float2 g2 = *(const float2*)(gamma + tid * 2);
    float2 b2 = *(const float2*)(beta + tid * 2);
    float2 o;
    o.x = (v.x - mean) * inv * g2.x + b2.x;
    o.y = (v.y - mean) * inv * g2.y + b2.y;
    *(float2*)(out + (size_t)row * DD + tid * 2) = o;
}

// ===========================================================================
extern "C" void kernel_launch(void* const* d_in, const int* in_sizes, int n_in,
                              void* d_out, int out_size)
{
    const float* q  = (const float*)d_in[0];
    const float* k  = (const float*)d_in[1];
    const float* v  = (const float*)d_in[2];
    const float* pe = (const float*)d_in[3];
    const unsigned char* kpm = (const unsigned char*)d_in[4];
    const unsigned char* am  = (const unsigned char*)d_in[5];
    const float* Wq = (const float*)d_in[6];
    const float* bq = (const float*)d_in[7];
    const float* Wk = (const float*)d_in[8];
    const float* bk = (const float*)d_in[9];
    const float* Wv = (const float*)d_in[10];
    const float* bv = (const float*)d_in[11];
    const float* Wo = (const float*)d_in[12];
    const float* bo = (const float*)d_in[13];
    const float* Wr = (const float*)d_in[14];
    const float* br = (const float*)d_in[15];
    const float* ub = (const float*)d_in[16];
    const float* vb = (const float*)d_in[17];
    const float* lg = (const float*)d_in[18];
    const float* lb = (const float*)d_in[19];

    float* normed = (float*)d_out;
    float* attnw  = normed + (size_t)BB * SQL * DD;

    float *qh, *kh, *vh, *att, *o2;
    cudaGetSymbolAddress((void**)&qh,  g_qh);
    cudaGetSymbolAddress((void**)&kh,  g_kh);
    cudaGetSymbolAddress((void**)&vh,  g_vh);
    cudaGetSymbolAddress((void**)&att, g_att);
    cudaGetSymbolAddress((void**)&o2,  g_o2);

    __nv_bfloat16 *qih, *qil, *kih, *kil, *vih, *vil;
    __nv_bfloat16 *wqh, *wql, *wkh, *wkl, *wvh, *wvl, *woh, *wol;
    __nv_bfloat16 *qvh, *qvl, *quh, *qul, *khh, *khl, *ath, *atl;
    cudaGetSymbolAddress((void**)&qih, g_qi_h); cudaGetSymbolAddress((void**)&qil, g_qi_l);
    cudaGetSymbolAddress((void**)&kih, g_ki_h); cudaGetSymbolAddress((void**)&kil, g_ki_l);
    cudaGetSymbolAddress((void**)&vih, g_vi_h); cudaGetSymbolAddress((void**)&vil, g_vi_l);
    cudaGetSymbolAddress((void**)&wqh, g_wq_h); cudaGetSymbolAddress((void**)&wql, g_wq_l);
    cudaGetSymbolAddress((void**)&wkh, g_wk_h); cudaGetSymbolAddress((void**)&wkl, g_wk_l);
    cudaGetSymbolAddress((void**)&wvh, g_wv_h); cudaGetSymbolAddress((void**)&wvl, g_wv_l);
    cudaGetSymbolAddress((void**)&woh, g_wo_h); cudaGetSymbolAddress((void**)&wol, g_wo_l);
    cudaGetSymbolAddress((void**)&qvh, g_qv_h); cudaGetSymbolAddress((void**)&qvl, g_qv_l);
    cudaGetSymbolAddress((void**)&quh, g_qu_h); cudaGetSymbolAddress((void**)&qul, g_qu_l);
    cudaGetSymbolAddress((void**)&khh, g_kh_h); cudaGetSymbolAddress((void**)&khl, g_kh_l);
    cudaGetSymbolAddress((void**)&ath, g_at_h); cudaGetSymbolAddress((void**)&atl, g_at_l);

    // mask normalization
    zero_flags<<<1, 32>>>();
    mask_detect<<<16, 256>>>(am);
    mask_convert<<<64, 256>>>(am, kpm);

    // operand conversions
    conv_inputs<<<dim3(MR * DD / 4 / 256, 1, 3), 256>>>(q, k, v);
    conv_w<<<dim3(16, 16, 4), dim3(32, 32)>>>(Wq, Wk, Wv, Wo);
    conv_wr<<<DD * DD / 4 / 256, 256>>>(Wr);

    // projections (tensor); Q also emits split(qh+vb) and split(qh+ub); K emits split(kh)
    mma2<<<dim3(8, 32), 256>>>(qih, qil, wqh, wql, bq, nullptr, qh,
                               qvh, qvl, vb, quh, qul, ub);
    mma2<<<dim3(8, 32), 256>>>(kih, kil, wkh, wkl, bk, nullptr, kh,
                               khh, khl, nullptr, nullptr, nullptr, nullptr);
    mma2<<<dim3(8, 32), 256>>>(vih, vil, wvh, wvl, bv, nullptr, vh,
                               nullptr, nullptr, nullptr, nullptr, nullptr, nullptr);

    conv_vt<<<dim3(16, 16, 4), dim3(32, 32)>>>();

    c_kernel<<<(MR * HH + 255) / 256, 256>>>(vb, br);
    t_mma<<<dim3(8, 32, 8), 256>>>();

    ac_mma<<<dim3(8, 8, 32), 256>>>(attnw);
    bd_mma<<<512, 256>>>(pe, attnw);
    softmax_kernel<<<BHH * SQL / 2, 256>>>(attnw);

    av_mma<<<dim3(8, 32), 256>>>(attnw);

    mma2<<<dim3(8, 32), 256>>>(ath, atl, woh, wol, bo, q, o2,
                               nullptr, nullptr, nullptr, nullptr, nullptr, nullptr);
    ln_kernel<<<MR, 256>>>(o2, lg, lb, normed);
}

// round 10
// speedup vs baseline: 1.0754x; 1.0754x over previous
#include <cuda_runtime.h>
#include <cuda_bf16.h>
#include <math.h>
#include <stdint.h>

#define BB   4
#define SQL  512
#define SKL  512
#define DD   512
#define HH   8
#define DHH  64
#define BHH  32
#define MR   2048

// ---------------- f32 scratch ----------------
__device__ float g_qh[MR * DD];
__device__ float g_kh[MR * DD];
__device__ float g_vh[MR * DD];
__device__ float g_c [MR * HH];
__device__ float g_att[MR * DD];
__device__ float g_o2 [MR * DD];

// ---------------- bf16 hi/lo scratch ----------------
__device__ __nv_bfloat16 g_qi_h[MR * DD], g_qi_l[MR * DD];
__device__ __nv_bfloat16 g_ki_h[MR * DD], g_ki_l[MR * DD];
__device__ __nv_bfloat16 g_vi_h[MR * DD], g_vi_l[MR * DD];
__device__ __nv_bfloat16 g_wq_h[DD * DD], g_wq_l[DD * DD];
__device__ __nv_bfloat16 g_wk_h[DD * DD], g_wk_l[DD * DD];
__device__ __nv_bfloat16 g_wv_h[DD * DD], g_wv_l[DD * DD];
__device__ __nv_bfloat16 g_wo_h[DD * DD], g_wo_l[DD * DD];
__device__ __nv_bfloat16 g_wr_h[DD * DD], g_wr_l[DD * DD];
__device__ __nv_bfloat16 g_qv_h[MR * DD], g_qv_l[MR * DD];   // split(qh + v_bias)
__device__ __nv_bfloat16 g_T_h[SQL * BHH * DD], g_T_l[SQL * BHH * DD]; // [q][bh][e]
__device__ __nv_bfloat16 g_at_h[MR * DD], g_at_l[MR * DD];

__device__ unsigned char g_am [SQL * SKL];
__device__ unsigned char g_kpm[BB * SKL];
__device__ unsigned int g_or1, g_or23;

// ===========================================================================
// helpers
// ===========================================================================
__device__ __forceinline__ uint32_t smem_u32(const void* p) {
    uint32_t a;
    asm("{ .reg .u64 t; cvta.to.shared.u64 t, %1; cvt.u32.u64 %0, t; }" : "=r"(a) : "l"(p));
    return a;
}
__device__ __forceinline__ uint32_t pack_bf16x2(float x, float y) {
    uint32_t r;
    asm("cvt.rn.bf16x2.f32 %0, %1, %2;" : "=r"(r) : "f"(y), "f"(x));
    return r;
}
__device__ __forceinline__ float bf_lo(uint32_t w) { return __uint_as_float(w << 16); }
__device__ __forceinline__ float bf_hi(uint32_t w) { return __uint_as_float(w & 0xffff0000u); }

#define MMA_BF16(c, a, b0, b1) \
    asm volatile("mma.sync.aligned.m16n8k16.row.col.f32.bf16.bf16.f32 " \
        "{%0,%1,%2,%3}, {%4,%5,%6,%7}, {%8,%9}, {%0,%1,%2,%3};" \
        : "+f"((c)[0]), "+f"((c)[1]), "+f"((c)[2]), "+f"((c)[3]) \
        : "r"((a)[0]), "r"((a)[1]), "r"((a)[2]), "r"((a)[3]), "r"(b0), "r"(b1))

__device__ __forceinline__ void cpa16(const void* s, const void* g) {
    asm volatile("cp.async.ca.shared.global [%0], [%1], 16;" :: "r"(smem_u32(s)), "l"(g));
}
__device__ __forceinline__ void split2(float x, float y, uint32_t& h, uint32_t& l) {
    h = pack_bf16x2(x, y);
    l = pack_bf16x2(x - bf_lo(h), y - bf_hi(h));
}

// ===========================================================================
// Conversion kernels
// ===========================================================================
__global__ void conv_inputs(const float* __restrict__ q, const float* __restrict__ k,
                            const float* __restrict__ v)
{
    const float* src = (blockIdx.z == 0) ? q : (blockIdx.z == 1) ? k : v;
    __nv_bfloat16* dh = (blockIdx.z == 0) ? g_qi_h : (blockIdx.z == 1) ? g_ki_h : g_vi_h;
    __nv_bfloat16* dl = (blockIdx.z == 0) ? g_qi_l : (blockIdx.z == 1) ? g_ki_l : g_vi_l;
    int idx = (blockIdx.x * blockDim.x + threadIdx.x) * 4;
    if (idx >= MR * DD) return;
    float4 a = *(const float4*)(src + idx);
    uint32_t h0, l0, h1, l1;
    split2(a.x, a.y, h0, l0);
    split2(a.z, a.w, h1, l1);
    *(uint2*)((uint16_t*)dh + idx) = make_uint2(h0, h1);
    *(uint2*)((uint16_t*)dl + idx) = make_uint2(l0, l1);
}

// W[k][n] -> out[n][k] hi/lo (transpose)
__global__ void conv_w(const float* __restrict__ Wq, const float* __restrict__ Wk,
                       const float* __restrict__ Wv, const float* __restrict__ Wo)
{
    __shared__ float s[32][33];
    const float* W = (blockIdx.z == 0) ? Wq : (blockIdx.z == 1) ? Wk : (blockIdx.z == 2) ? Wv : Wo;
    __nv_bfloat16* dh = (blockIdx.z == 0) ? g_wq_h : (blockIdx.z == 1) ? g_wk_h : (blockIdx.z == 2) ? g_wv_h : g_wo_h;
    __nv_bfloat16* dl = (blockIdx.z == 0) ? g_wq_l : (blockIdx.z == 1) ? g_wk_l : (blockIdx.z == 2) ? g_wv_l : g_wo_l;
    int k0 = blockIdx.y * 32, n0 = blockIdx.x * 32;
    int tx = threadIdx.x, ty = threadIdx.y;
    s[ty][tx] = W[(size_t)(k0 + ty) * DD + n0 + tx];
    __syncthreads();
    float vv = s[tx][ty];
    __nv_bfloat16 hb = __float2bfloat16_rn(vv);
    __nv_bfloat16 lb = __float2bfloat16_rn(vv - __bfloat162float(hb));
    dh[(size_t)(n0 + ty) * DD + k0 + tx] = hb;
    dl[(size_t)(n0 + ty) * DD + k0 + tx] = lb;
}

__global__ void conv_wr(const float* __restrict__ Wr)
{
    int idx = (blockIdx.x * blockDim.x + threadIdx.x) * 4;
    if (idx >= DD * DD) return;
    float4 a = *(const float4*)(Wr + idx);
    uint32_t h0, l0, h1, l1;
    split2(a.x, a.y, h0, l0);
    split2(a.z, a.w, h1, l1);
    *(uint2*)((uint16_t*)g_wr_h + idx) = make_uint2(h0, h1);
    *(uint2*)((uint16_t*)g_wr_l + idx) = make_uint2(l0, l1);
}

// ===========================================================================
// Mask normalization (single-block detect, no atomics)
// ===========================================================================
__global__ void mask_detect(const unsigned char* __restrict__ am)
{
    unsigned int or1 = 0, or23 = 0;
    const uint4* p = (const uint4*)am;
    int n16 = SQL * SKL / 16;
    for (int i = threadIdx.x; i < n16; i += blockDim.x) {
        uint4 v = p[i];
        or1  |= (v.x & 0x0000FF00u) | (v.y & 0x0000FF00u) | (v.z & 0x0000FF00u) | (v.w & 0x0000FF00u);
        or23 |= (v.x & 0xFFFF0000u) | (v.y & 0xFFFF0000u) | (v.z & 0xFFFF0000u) | (v.w & 0xFFFF0000u);
    }
    int a1  = __syncthreads_or((int)(or1 != 0));
    int a23 = __syncthreads_or((int)(or23 != 0));
    if (threadIdx.x == 0) { g_or1 = a1 ? 1u : 0u; g_or23 = a23 ? 1u : 0u; }
}

__global__ void mask_convert(const unsigned char* __restrict__ am,
                             const unsigned char* __restrict__ kpm)
{
    int mode = g_or1 ? 1 : (g_or23 ? 2 : 0);
    int stride = gridDim.x * blockDim.x;
    int tid = blockIdx.x * blockDim.x + threadIdx.x;
    for (int i = tid; i < SQL * SKL; i += stride) {
        unsigned char v;
        if (mode == 1)      v = (am[i] != 0);
        else if (mode == 2) v = (((const float*)am)[i] != 0.0f);
        else                v = (((const int*)am)[i] != 0);
        g_am[i] = v;
    }
    for (int i = tid; i < BB * SKL; i += stride) {
        unsigned char v;
        if (mode == 1)      v = (kpm[i] != 0);
        else if (mode == 2) v = (((const float*)kpm)[i] != 0.0f);
        else                v = (((const int*)kpm)[i] != 0);
        g_kpm[i] = v;
    }
}

// ===========================================================================
// Shared mma projection body (BM=64 BN=64 BK=32, cp.async double buffer)
// ===========================================================================
__device__ __forceinline__ void mma_body(
    const __nv_bfloat16* __restrict__ Ahg, const __nv_bfloat16* __restrict__ Alg,
    const __nv_bfloat16* __restrict__ Bhg, const __nv_bfloat16* __restrict__ Blg,
    const float* __restrict__ bias, const float* __restrict__ resid,
    float* __restrict__ C,
    __nv_bfloat16* __restrict__ o2h, __nv_bfloat16* __restrict__ o2l,
    const float* __restrict__ rowbias,
    __nv_bfloat16 (*sA)[2][64][40], __nv_bfloat16 (*sB)[2][64][40],
    int row0, int n0)
{
    int tid = threadIdx.x, lane = tid & 31, wid = tid >> 5;
    int wm = wid >> 2, wn = wid & 3;
    int r = lane >> 2, t4 = lane & 3;
    float acc[2][2][4] = {};
    int lrow = tid >> 2, lco = (tid & 3) * 8;

    {
        int k0 = 0;
        cpa16(&sA[0][0][lrow][lco], (const uint16_t*)Ahg + (size_t)(row0 + lrow) * DD + k0 + lco);
        cpa16(&sA[0][1][lrow][lco], (const uint16_t*)Alg + (size_t)(row0 + lrow) * DD + k0 + lco);
        cpa16(&sB[0][0][lrow][lco], (const uint16_t*)Bhg + (size_t)(n0 + lrow) * DD + k0 + lco);
        cpa16(&sB[0][1][lrow][lco], (const uint16_t*)Blg + (size_t)(n0 + lrow) * DD + k0 + lco);
        asm volatile("cp.async.commit_group;");
    }
    #pragma unroll 1
    for (int it = 0; it < 16; it++) {
        if (it + 1 < 16) {
            int st = (it + 1) & 1, k0 = (it + 1) * 32;
            cpa16(&sA[st][0][lrow][lco], (const uint16_t*)Ahg + (size_t)(row0 + lrow) * DD + k0 + lco);
            cpa16(&sA[st][1][lrow][lco], (const uint16_t*)Alg + (size_t)(row0 + lrow) * DD + k0 + lco);
            cpa16(&sB[st][0][lrow][lco], (const uint16_t*)Bhg + (size_t)(n0 + lrow) * DD + k0 + lco);
            cpa16(&sB[st][1][lrow][lco], (const uint16_t*)Blg + (size_t)(n0 + lrow) * DD + k0 + lco);
            asm volatile("cp.async.commit_group;");
            asm volatile("cp.async.wait_group 1;");
        } else {
            asm volatile("cp.async.wait_group 0;");
        }
        __syncthreads();
        int st = it & 1;
        #pragma unroll
        for (int ks = 0; ks < 2; ks++) {
            uint32_t ah[2][4], al[2][4];
            #pragma unroll
            for (int mi = 0; mi < 2; mi++) {
                int row = wm * 32 + mi * 16 + r;
                const __nv_bfloat16* ph = &sA[st][0][row][ks * 16 + t4 * 2];
                const __nv_bfloat16* pl = &sA[st][1][row][ks * 16 + t4 * 2];
                ah[mi][0] = *(const uint32_t*)ph;
                ah[mi][1] = *(const uint32_t*)(ph + 8 * 40);
                ah[mi][2] = *(const uint32_t*)(ph + 8);
                ah[mi][3] = *(const uint32_t*)(ph + 8 * 40 + 8);
                al[mi][0] = *(const uint32_t*)pl;
                al[mi][1] = *(const uint32_t*)(pl + 8 * 40);
                al[mi][2] = *(const uint32_t*)(pl + 8);
                al[mi][3] = *(const uint32_t*)(pl + 8 * 40 + 8);
            }
            #pragma unroll
            for (int nj = 0; nj < 2; nj++) {
                int n = wn * 16 + nj * 8 + r;
                const __nv_bfloat16* qh = &sB[st][0][n][ks * 16 + t4 * 2];
                const __nv_bfloat16* ql = &sB[st][1][n][ks * 16 + t4 * 2];
                uint32_t bh0 = *(const uint32_t*)qh, bh1 = *(const uint32_t*)(qh + 8);
                uint32_t bl0 = *(const uint32_t*)ql, bl1 = *(const uint32_t*)(ql + 8);
                #pragma unroll
                for (int mi = 0; mi < 2; mi++) {
                    MMA_BF16(acc[mi][nj], ah[mi], bh0, bh1);
                    MMA_BF16(acc[mi][nj], ah[mi], bl0, bl1);
                    MMA_BF16(acc[mi][nj], al[mi], bh0, bh1);
                }
            }
        }
        __syncthreads();
    }
    #pragma unroll
    for (int mi = 0; mi < 2; mi++) {
        #pragma unroll
        for (int nj = 0; nj < 2; nj++) {
            int col = n0 + wn * 16 + nj * 8 + t4 * 2;
            float b0 = bias[col], b1 = bias[col + 1];
            float rb0 = rowbias ? rowbias[col] : 0.f;
            float rb1 = rowbias ? rowbias[col + 1] : 0.f;
            #pragma unroll
            for (int rr = 0; rr < 2; rr++) {
                int row = row0 + wm * 32 + mi * 16 + r + rr * 8;
                float v0 = acc[mi][nj][rr * 2 + 0] + b0;
                float v1 = acc[mi][nj][rr * 2 + 1] + b1;
                if (resid) {
                    float2 r2 = *(const float2*)(resid + (size_t)row * DD + col);
                    v0 += r2.x; v1 += r2.y;
                }
                *(float2*)(C + (size_t)row * DD + col) = make_float2(v0, v1);
                if (o2h) {
                    uint32_t h, l;
                    split2(v0 + rb0, v1 + rb1, h, l);
                    *(uint32_t*)((uint16_t*)o2h + (size_t)row * DD + col) = h;
                    *(uint32_t*)((uint16_t*)o2l + (size_t)row * DD + col) = l;
                }
            }
        }
    }
}

// Fused Q/K/V projections: one launch, z selects the problem.
__global__ void __launch_bounds__(256, 2)
mma_qkv(const float* __restrict__ bq, const float* __restrict__ bk,
        const float* __restrict__ bv, const float* __restrict__ vb)
{
    __shared__ __align__(16) __nv_bfloat16 sA[2][2][64][40];
    __shared__ __align__(16) __nv_bfloat16 sB[2][2][64][40];
    int z = blockIdx.z;
    const __nv_bfloat16 *Ah, *Al, *Bh, *Bl;
    const float* bias;
    float* C;
    __nv_bfloat16 *o2h = nullptr, *o2l = nullptr;
    const float* rb = nullptr;
    if (z == 0) {
        Ah = g_qi_h; Al = g_qi_l; Bh = g_wq_h; Bl = g_wq_l;
        bias = bq; C = g_qh; o2h = g_qv_h; o2l = g_qv_l; rb = vb;
    } else if (z == 1) {
        Ah = g_ki_h; Al = g_ki_l; Bh = g_wk_h; Bl = g_wk_l;
        bias = bk; C = g_kh;
    } else {
        Ah = g_vi_h; Al = g_vi_l; Bh = g_wv_h; Bl = g_wv_l;
        bias = bv; C = g_vh;
    }
    mma_body(Ah, Al, Bh, Bl, bias, nullptr, C, o2h, o2l, rb,
             sA, sB, blockIdx.y * 64, blockIdx.x * 64);
}

// Generic single-GEMM wrapper (used for Wo projection)
__global__ void __launch_bounds__(256, 2)
mma2(const __nv_bfloat16* __restrict__ Ahg, const __nv_bfloat16* __restrict__ Alg,
     const __nv_bfloat16* __restrict__ Bhg, const __nv_bfloat16* __restrict__ Blg,
     const float* __restrict__ bias, const float* __restrict__ resid,
     float* __restrict__ C)
{
    __shared__ __align__(16) __nv_bfloat16 sA[2][2][64][40];
    __shared__ __align__(16) __nv_bfloat16 sB[2][2][64][40];
    mma_body(Ahg, Alg, Bhg, Blg, bias, resid, C, nullptr, nullptr, nullptr,
             sA, sB, blockIdx.y * 64, blockIdx.x * 64);
}

// ===========================================================================
// t_mma: T[q][bh][e] (hi/lo) = (qh + v_bias) @ Wr_h^T, per head.
// ===========================================================================
__global__ void __launch_bounds__(256, 2)
t_mma()
{
    __shared__ __align__(16) __nv_bfloat16 tA[2][64][72];
    __shared__ __align__(16) __nv_bfloat16 tB[2][64][72];
    int tid = threadIdx.x, lane = tid & 31, wid = tid >> 5;
    int wm = wid >> 2, wn = wid & 3;
    int h = blockIdx.z, hoff = h * DHH;
    int m0 = blockIdx.y * 64, e0 = blockIdx.x * 64;
    int r = lane >> 2, t4 = lane & 3;
    float acc[2][2][4] = {};

    #pragma unroll
    for (int j = 0; j < 2; j++) {
        int c = tid + j * 256;
        int row = c >> 3, off = (c & 7) * 8;
        *(uint4*)&tA[0][row][off] = *(const uint4*)((const uint16_t*)g_qv_h + (size_t)(m0 + row) * DD + hoff + off);
        *(uint4*)&tA[1][row][off] = *(const uint4*)((const uint16_t*)g_qv_l + (size_t)(m0 + row) * DD + hoff + off);
        *(uint4*)&tB[0][row][off] = *(const uint4*)((const uint16_t*)g_wr_h + (size_t)(e0 + row) * DD + hoff + off);
        *(uint4*)&tB[1][row][off] = *(const uint4*)((const uint16_t*)g_wr_l + (size_t)(e0 + row) * DD + hoff + off);
    }
    __syncthreads();

    #pragma unroll
    for (int ks = 0; ks < 4; ks++) {
        uint32_t ah[2][4], al[2][4];
        #pragma unroll
        for (int mi = 0; mi < 2; mi++) {
            int row = wm * 32 + mi * 16 + r;
            const __nv_bfloat16* ph = &tA[0][row][ks * 16 + t4 * 2];
            const __nv_bfloat16* pl = &tA[1][row][ks * 16 + t4 * 2];
            ah[mi][0] = *(const uint32_t*)ph;
            ah[mi][1] = *(const uint32_t*)(ph + 8 * 72);
            ah[mi][2] = *(const uint32_t*)(ph + 8);
            ah[mi][3] = *(const uint32_t*)(ph + 8 * 72 + 8);
            al[mi][0] = *(const uint32_t*)pl;
            al[mi][1] = *(const uint32_t*)(pl + 8 * 72);
            al[mi][2] = *(const uint32_t*)(pl + 8);
            al[mi][3] = *(const uint32_t*)(pl + 8 * 72 + 8);
        }
        #pragma unroll
        for (int nj = 0; nj < 2; nj++) {
            int n = wn * 16 + nj * 8 + r;
            const __nv_bfloat16* qh = &tB[0][n][ks * 16 + t4 * 2];
            const __nv_bfloat16* ql = &tB[1][n][ks * 16 + t4 * 2];
            uint32_t bh0 = *(const uint32_t*)qh, bh1 = *(const uint32_t*)(qh + 8);
            uint32_t bl0 = *(const uint32_t*)ql, bl1 = *(const uint32_t*)(ql + 8);
            #pragma unroll
            for (int mi = 0; mi < 2; mi++) {
                MMA_BF16(acc[mi][nj], ah[mi], bh0, bh1);
                MMA_BF16(acc[mi][nj], ah[mi], bl0, bl1);
                MMA_BF16(acc[mi][nj], al[mi], bh0, bh1);
            }
        }
    }
    #pragma unroll
    for (int mi = 0; mi < 2; mi++) {
        #pragma unroll
        for (int nj = 0; nj < 2; nj++) {
            int e = e0 + wn * 16 + nj * 8 + t4 * 2;
            #pragma unroll
            for (int rr = 0; rr < 2; rr++) {
                int m = m0 + wm * 32 + mi * 16 + r + rr * 8;
                int q = m & 511, b = m >> 9;
                int bh = b * HH + h;
                uint32_t hh, ll;
                split2(acc[mi][nj][rr * 2 + 0], acc[mi][nj][rr * 2 + 1], hh, ll);
                size_t di = ((size_t)q * BHH + bh) * DD + e;
                *(uint32_t*)((uint16_t*)g_T_h + di) = hh;
                *(uint32_t*)((uint16_t*)g_T_l + di) = ll;
            }
        }
    }
}

// c[b,q,h] = sum_d (qh+v_bias)*br_h
__global__ void c_kernel(const float* __restrict__ vb, const float* __restrict__ br)
{
    int idx = blockIdx.x * blockDim.x + threadIdx.x;
    if (idx >= MR * HH) return;
    int h = idx & 7;
    int m = idx >> 3;
    int hoff = h * DHH;
    const float* qrow = g_qh + (size_t)m * DD + hoff;
    float s = 0.f;
    #pragma unroll 8
    for (int d = 0; d < DHH; d++)
        s += (qrow[d] + vb[hoff + d]) * br[hoff + d];
    g_c[idx] = s;
}

// ===========================================================================
// ac (scalar, R2): score[bh,q,k] = sum_d (qh+u)*kh
// ===========================================================================
__global__ void ac_kernel(const float* __restrict__ ub, float* __restrict__ score)
{
    __shared__ float As[16][64];
    __shared__ float Ks[16][64];
    int bh = blockIdx.z, b = bh >> 3, h = bh & 7, hoff = h * DHH;
    int q0 = blockIdx.y * 64, k0 = blockIdx.x * 64;
    int tid = threadIdx.x;
    int tx = tid & 15, ty = tid >> 4;

    const unsigned char* rp = g_am + (size_t)(q0 + (tid >> 2)) * SKL + k0 + (tid & 3) * 16;
    int allm = 1;
    #pragma unroll
    for (int j = 0; j < 16; j++) allm &= (rp[j] != 0);
    if (__syncthreads_and(allm)) return;

    int lr = tid >> 2, lc = (tid & 3) * 4;
    float acc[4][4] = {};
    for (int d0 = 0; d0 < DHH; d0 += 16) {
        float4 a4 = *(const float4*)(g_qh + ((size_t)b * SQL + q0 + lr) * DD + hoff + d0 + lc);
        float4 u4 = *(const float4*)(ub + hoff + d0 + lc);
        As[lc + 0][lr] = a4.x + u4.x;
        As[lc + 1][lr] = a4.y + u4.y;
        As[lc + 2][lr] = a4.z + u4.z;
        As[lc + 3][lr] = a4.w + u4.w;
        float4 k4 = *(const float4*)(g_kh + ((size_t)b * SQL + k0 + lr) * DD + hoff + d0 + lc);
        Ks[lc + 0][lr] = k4.x;
        Ks[lc + 1][lr] = k4.y;
        Ks[lc + 2][lr] = k4.z;
        Ks[lc + 3][lr] = k4.w;
        __syncthreads();
        #pragma unroll
        for (int kk = 0; kk < 16; kk++) {
            float a[4], bv[4];
            #pragma unroll
            for (int i = 0; i < 4; i++) a[i] = As[kk][ty * 4 + i];
            #pragma unroll
            for (int j = 0; j < 4; j++) bv[j] = Ks[kk][tx * 4 + j];
            #pragma unroll
            for (int i = 0; i < 4; i++)
                #pragma unroll
                for (int j = 0; j < 4; j++)
                    acc[i][j] += a[i] * bv[j];
        }
        __syncthreads();
    }
    #pragma unroll
    for (int i = 0; i < 4; i++) {
        float4 sv = {acc[i][0], acc[i][1], acc[i][2], acc[i][3]};
        *(float4*)(score + ((size_t)bh * SQL + q0 + ty * 4 + i) * SKL + k0 + tx * 4) = sv;
    }
}

// ===========================================================================
// bd_mma: score[bh,q,k] = (ac + T[q,bh,:]@pos_emb[q,k,:] + c)/8 via mma.
// ===========================================================================
__global__ void __launch_bounds__(256)
bd_mma(const float* __restrict__ pos_emb, float* __restrict__ score)
{
    __shared__ __align__(16) __nv_bfloat16 sT[2][32][136];
    int q = blockIdx.x;
    int tid = threadIdx.x, lane = tid & 31, wn = tid >> 5;
    int r = lane >> 2, t4 = lane & 3;

    int k_a = wn * 64 + lane * 2;
    unsigned char ma = g_am[(size_t)q * SKL + k_a];
    unsigned char mb = g_am[(size_t)q * SKL + k_a + 1];
    int act = __ballot_sync(0xffffffffu, (ma == 0) || (mb == 0)) != 0;

    float acc[2][8][4] = {};

    #pragma unroll 1
    for (int ec = 0; ec < 4; ec++) {
        #pragma unroll
        for (int j = 0; j < 2; j++) {
            int c = tid + j * 256;
            int row = c >> 4, off = (c & 15) * 8;
            size_t gi = ((size_t)q * BHH + row) * DD + ec * 128 + off;
            *(uint4*)&sT[0][row][off] = *(const uint4*)((const uint16_t*)g_T_h + gi);
            *(uint4*)&sT[1][row][off] = *(const uint4*)((const uint16_t*)g_T_l + gi);
        }
        __syncthreads();
        if (act) {
            #pragma unroll 1
            for (int ks = 0; ks < 8; ks++) {
                uint32_t ah[2][4], al[2][4];
                #pragma unroll
                for (int mi = 0; mi < 2; mi++) {
                    int row = mi * 16 + r;
                    const __nv_bfloat16* ph = &sT[0][row][ks * 16 + t4 * 2];
                    const __nv_bfloat16* pl = &sT[1][row][ks * 16 + t4 * 2];
                    ah[mi][0] = *(const uint32_t*)ph;
                    ah[mi][1] = *(const uint32_t*)(ph + 8 * 136);
                    ah[mi][2] = *(const uint32_t*)(ph + 8);
                    ah[mi][3] = *(const uint32_t*)(ph + 8 * 136 + 8);
                    al[mi][0] = *(const uint32_t*)pl;
                    al[mi][1] = *(const uint32_t*)(pl + 8 * 136);
                    al[mi][2] = *(const uint32_t*)(pl + 8);
                    al[mi][3] = *(const uint32_t*)(pl + 8 * 136 + 8);
                }
                int eg = ec * 128 + ks * 16 + t4 * 2;
                #pragma unroll
                for (int nj = 0; nj < 8; nj++) {
                    int n = wn * 64 + nj * 8 + r;
                    const float* pp = pos_emb + ((size_t)q * SKL + n) * DD + eg;
                    float2 p0 = *(const float2*)pp;
                    float2 p1 = *(const float2*)(pp + 8);
                    uint32_t bh0, bl0, bh1, bl1;
                    split2(p0.x, p0.y, bh0, bl0);
                    split2(p1.x, p1.y, bh1, bl1);
                    #pragma unroll
                    for (int mi = 0; mi < 2; mi++) {
                        MMA_BF16(acc[mi][nj], ah[mi], bh0, bh1);
                        MMA_BF16(acc[mi][nj], ah[mi], bl0, bl1);
                        MMA_BF16(acc[mi][nj], al[mi], bh0, bh1);
                    }
                }
            }
        }
        __syncthreads();
    }
    if (!act) return;
    #pragma unroll
    for (int mi = 0; mi < 2; mi++) {
        #pragma unroll
        for (int rr = 0; rr < 2; rr++) {
            int bh = mi * 16 + r + rr * 8;
            int b = bh >> 3, h = bh & 7;
            float cc = g_c[((size_t)b * SQL + q) * HH + h];
            float* srow = score + ((size_t)bh * SQL + q) * SKL;
            #pragma unroll
            for (int nj = 0; nj < 8; nj++) {
                int k = wn * 64 + nj * 8 + t4 * 2;
                float2 s2 = *(float2*)(srow + k);
                s2.x = (s2.x + acc[mi][nj][rr * 2 + 0] + cc) * 0.125f;
                s2.y = (s2.y + acc[mi][nj][rr * 2 + 1] + cc) * 0.125f;
                *(float2*)(srow + k) = s2;
            }
        }
    }
}

// ===========================================================================
__global__ void softmax_kernel(float* __restrict__ score)
{
    int row = blockIdx.x;
    int q = row & 511;
    int bh = row >> 9;
    int b = bh >> 3;
    int tid = threadIdx.x;         // 128
    float* s = score + (size_t)row * SKL;

    float4 v4 = *(float4*)(s + tid * 4);
    float vals[4] = {v4.x, v4.y, v4.z, v4.w};
    const unsigned char* amr = g_am + (size_t)q * SKL + tid * 4;
    const unsigned char* kpr = g_kpm + (size_t)b * SKL + tid * 4;
    #pragma unroll
    for (int j = 0; j < 4; j++)
        if (amr[j] || kpr[j]) vals[j] = -INFINITY;

    float mx = fmaxf(fmaxf(vals[0], vals[1]), fmaxf(vals[2], vals[3]));
    #pragma unroll
    for (int off = 16; off; off >>= 1)
        mx = fmaxf(mx, __shfl_xor_sync(0xffffffffu, mx, off));
    __shared__ float sm[4], ssum[4];
    int wid = tid >> 5, lane = tid & 31;
    if (lane == 0) sm[wid] = mx;
    __syncthreads();
    mx = fmaxf(fmaxf(sm[0], sm[1]), fmaxf(sm[2], sm[3]));

    float e[4]; float sum = 0.f;
    #pragma unroll
    for (int j = 0; j < 4; j++) {
        e[j] = (vals[j] == -INFINITY) ? 0.f : __expf(vals[j] - mx);
        sum += e[j];
    }
    #pragma unroll
    for (int off = 16; off; off >>= 1)
        sum += __shfl_xor_sync(0xffffffffu, sum, off);
    if (lane == 0) ssum[wid] = sum;
    __syncthreads();
    sum = ssum[0] + ssum[1] + ssum[2] + ssum[3];
    float inv = (sum > 0.f) ? 1.f / sum : 0.f;
    float4 o = {e[0] * inv, e[1] * inv, e[2] * inv, e[3] * inv};
    *(float4*)(s + tid * 4) = o;
}

// ===========================================================================
// av (scalar R2) + fused hi/lo split of the output
// ===========================================================================
__global__ void av_kernel(const float* __restrict__ score)
{
    __shared__ float As[16][64];
    __shared__ float Ws[16][64];
    int bh = blockIdx.y, b = bh >> 3, h = bh & 7, hoff = h * DHH;
    int q0 = blockIdx.x * 64;
    int tid = threadIdx.x;
    int tx = tid & 15, ty = tid >> 4;
    float acc[4][4] = {};

    int la_q = tid >> 2, la_k = (tid & 3) * 4;
    int lw_k = tid >> 4, lw_d = (tid & 15) * 4;

    for (int k0 = 0; k0 < SKL; k0 += 16) {
        const unsigned char* rp = g_am + (size_t)(q0 + (tid >> 2)) * SKL + k0 + (tid & 3) * 4;
        int allm = (rp[0] && rp[1] && rp[2] && rp[3]);
        if (__syncthreads_and(allm)) continue;

        float4 a4 = *(const float4*)(score + ((size_t)bh * SQL + q0 + la_q) * SKL + k0 + la_k);
        As[la_k + 0][la_q] = a4.x;
        As[la_k + 1][la_q] = a4.y;
        As[la_k + 2][la_q] = a4.z;
        As[la_k + 3][la_q] = a4.w;
        float4 w4 = *(const float4*)(g_vh + ((size_t)b * SQL + k0 + lw_k) * DD + hoff + lw_d);
        *(float4*)&Ws[lw_k][lw_d] = w4;
        __syncthreads();
        #pragma unroll
        for (int kk = 0; kk < 16; kk++) {
            float a[4], bv[4];
            #pragma unroll
            for (int i = 0; i < 4; i++) a[i] = As[kk][ty * 4 + i];
            #pragma unroll
            for (int j = 0; j < 4; j++) bv[j] = Ws[kk][tx * 4 + j];
            #pragma unroll
            for (int i = 0; i < 4; i++)
                #pragma unroll
                for (int j = 0; j < 4; j++)
                    acc[i][j] += a[i] * bv[j];
        }
        __syncthreads();
    }
    #pragma unroll
    for (int i = 0; i < 4; i++) {
        size_t oi = ((size_t)b * SQL + q0 + ty * 4 + i) * DD + hoff + tx * 4;
        float4 sv = {acc[i][0], acc[i][1], acc[i][2], acc[i][3]};
        *(float4*)(g_att + oi) = sv;
        uint32_t h0, l0, h1, l1;
        split2(sv.x, sv.y, h0, l0);
        split2(sv.z, sv.w, h1, l1);
        *(uint2*)((uint16_t*)g_at_h + oi) = make_uint2(h0, h1);
        *(uint2*)((uint16_t*)g_at_l + oi) = make_uint2(l0, l1);
    }
}

// ===========================================================================
__global__ void ln_kernel(const float* __restrict__ X, const float* __restrict__ gamma,
                          const float* __restrict__ beta, float* __restrict__ out)
{
    int row = blockIdx.x;
    int tid = threadIdx.x;  // 256
    const float* x = X + (size_t)row * DD;
    float2 v = *(const float2*)(x + tid * 2);
    float s = v.x + v.y;
    float s2 = v.x * v.x + v.y * v.y;
    #pragma unroll
    for (int off = 16; off; off >>= 1) {
        s  += __shfl_xor_sync(0xffffffffu, s, off);
        s2 += __shfl_xor_sync(0xffffffffu, s2, off);
    }
    __shared__ float rs[8], rs2[8];
    int wid = tid >> 5, lane = tid & 31;
    if (lane == 0) { rs[wid] = s; rs2[wid] = s2; }
    __syncthreads();
    s = 0.f; s2 = 0.f;
    #pragma unroll
    for (int i = 0; i < 8; i++) { s += rs[i]; s2 += rs2[i]; }
    float mean = s * (1.f / DD);
    float var = s2 * (1.f / DD) - mean * mean;
    float inv = rsqrtf(var + 1e-5f);
    float2 g2 = *(const float2*)(gamma + tid * 2);
    float2 b2 = *(const float2*)(beta + tid * 2);
    float2 o;
    o.x = (v.x - mean) * inv * g2.x + b2.x;
    o.y = (v.y - mean) * inv * g2.y + b2.y;
    *(float2*)(out + (size_t)row * DD + tid * 2) = o;
}

// ===========================================================================
extern "C" void kernel_launch(void* const* d_in, const int* in_sizes, int n_in,
                              void* d_out, int out_size)
{
    const float* q  = (const float*)d_in[0];
    const float* k  = (const float*)d_in[1];
    const float* v  = (const float*)d_in[2];
    const float* pe = (const float*)d_in[3];
    const unsigned char* kpm = (const unsigned char*)d_in[4];
    const unsigned char* am  = (const unsigned char*)d_in[5];
    const float* Wq = (const float*)d_in[6];
    const float* bq = (const float*)d_in[7];
    const float* Wk = (const float*)d_in[8];
    const float* bk = (const float*)d_in[9];
    const float* Wv = (const float*)d_in[10];
    const float* bv = (const float*)d_in[11];
    const float* Wo = (const float*)d_in[12];
    const float* bo = (const float*)d_in[13];
    const float* Wr = (const float*)d_in[14];
    const float* br = (const float*)d_in[15];
    const float* ub = (const float*)d_in[16];
    const float* vb = (const float*)d_in[17];
    const float* lg = (const float*)d_in[18];
    const float* lb = (const float*)d_in[19];

    float* normed = (float*)d_out;
    float* attnw  = normed + (size_t)BB * SQL * DD;

    float *o2;
    cudaGetSymbolAddress((void**)&o2,  g_o2);
    __nv_bfloat16 *woh, *wol, *ath, *atl;
    cudaGetSymbolAddress((void**)&woh, g_wo_h); cudaGetSymbolAddress((void**)&wol, g_wo_l);
    cudaGetSymbolAddress((void**)&ath, g_at_h); cudaGetSymbolAddress((void**)&atl, g_at_l);

    // mask normalization
    mask_detect<<<1, 1024>>>(am);
    mask_convert<<<64, 256>>>(am, kpm);

    // operand conversions
    conv_inputs<<<dim3(MR * DD / 4 / 256, 1, 3), 256>>>(q, k, v);
    conv_w<<<dim3(16, 16, 4), dim3(32, 32)>>>(Wq, Wk, Wv, Wo);
    conv_wr<<<DD * DD / 4 / 256, 256>>>(Wr);

    // fused Q/K/V projections (tensor); Q also emits split(qh+vb)
    mma_qkv<<<dim3(8, 32, 3), 256>>>(bq, bk, bv, vb);

    c_kernel<<<(MR * HH + 255) / 256, 256>>>(vb, br);
    t_mma<<<dim3(8, 32, 8), 256>>>();

    ac_kernel<<<dim3(8, 8, 32), 256>>>(ub, attnw);
    bd_mma<<<512, 256>>>(pe, attnw);
    softmax_kernel<<<BHH * SQL, 128>>>(attnw);

    av_kernel<<<dim3(8, 32), 256>>>(attnw);

    mma2<<<dim3(8, 32), 256>>>(ath, atl, woh, wol, bo, q, o2);
    ln_kernel<<<MR, 256>>>(o2, lg, lb, normed);
}

// round 11
// speedup vs baseline: 1.0884x; 1.0120x over previous
#include <cuda_runtime.h>
#include <cuda_bf16.h>
#include <math.h>
#include <stdint.h>

#define BB   4
#define SQL  512
#define SKL  512
#define DD   512
#define HH   8
#define DHH  64
#define BHH  32
#define MR   2048

// ---------------- f32 scratch ----------------
__device__ float g_qh[MR * DD];
__device__ float g_kh[MR * DD];
__device__ float g_vh[MR * DD];
__device__ float g_c [MR * HH];
__device__ float g_att[MR * DD];
__device__ float g_o2 [MR * DD];

// ---------------- bf16 hi/lo scratch ----------------
__device__ __nv_bfloat16 g_qi_h[MR * DD], g_qi_l[MR * DD];
__device__ __nv_bfloat16 g_ki_h[MR * DD], g_ki_l[MR * DD];
__device__ __nv_bfloat16 g_vi_h[MR * DD], g_vi_l[MR * DD];
__device__ __nv_bfloat16 g_wq_h[DD * DD], g_wq_l[DD * DD];
__device__ __nv_bfloat16 g_wk_h[DD * DD], g_wk_l[DD * DD];
__device__ __nv_bfloat16 g_wv_h[DD * DD], g_wv_l[DD * DD];
__device__ __nv_bfloat16 g_wo_h[DD * DD], g_wo_l[DD * DD];
__device__ __nv_bfloat16 g_wr_h[DD * DD], g_wr_l[DD * DD];
__device__ __nv_bfloat16 g_qv_h[MR * DD], g_qv_l[MR * DD];   // split(qh + v_bias)
__device__ __nv_bfloat16 g_T_h[SQL * BHH * DD], g_T_l[SQL * BHH * DD]; // [q][bh][e]
__device__ __nv_bfloat16 g_at_h[MR * DD], g_at_l[MR * DD];

__device__ unsigned char g_am [SQL * SKL];
__device__ unsigned char g_kpm[BB * SKL];
__device__ unsigned int g_or1, g_or23;

// ===========================================================================
// helpers
// ===========================================================================
__device__ __forceinline__ uint32_t smem_u32(const void* p) {
    uint32_t a;
    asm("{ .reg .u64 t; cvta.to.shared.u64 t, %1; cvt.u32.u64 %0, t; }" : "=r"(a) : "l"(p));
    return a;
}
__device__ __forceinline__ uint32_t pack_bf16x2(float x, float y) {
    uint32_t r;
    asm("cvt.rn.bf16x2.f32 %0, %1, %2;" : "=r"(r) : "f"(y), "f"(x));
    return r;
}
__device__ __forceinline__ float bf_lo(uint32_t w) { return __uint_as_float(w << 16); }
__device__ __forceinline__ float bf_hi(uint32_t w) { return __uint_as_float(w & 0xffff0000u); }

#define MMA_BF16(c, a, b0, b1) \
    asm volatile("mma.sync.aligned.m16n8k16.row.col.f32.bf16.bf16.f32 " \
        "{%0,%1,%2,%3}, {%4,%5,%6,%7}, {%8,%9}, {%0,%1,%2,%3};" \
        : "+f"((c)[0]), "+f"((c)[1]), "+f"((c)[2]), "+f"((c)[3]) \
        : "r"((a)[0]), "r"((a)[1]), "r"((a)[2]), "r"((a)[3]), "r"(b0), "r"(b1))

__device__ __forceinline__ void cpa16(const void* s, const void* g) {
    asm volatile("cp.async.ca.shared.global [%0], [%1], 16;" :: "r"(smem_u32(s)), "l"(g));
}
__device__ __forceinline__ void split2(float x, float y, uint32_t& h, uint32_t& l) {
    h = pack_bf16x2(x, y);
    l = pack_bf16x2(x - bf_lo(h), y - bf_hi(h));
}

// ===========================================================================
// Conversion kernels
// ===========================================================================
__global__ void conv_inputs(const float* __restrict__ q, const float* __restrict__ k,
                            const float* __restrict__ v)
{
    const float* src = (blockIdx.z == 0) ? q : (blockIdx.z == 1) ? k : v;
    __nv_bfloat16* dh = (blockIdx.z == 0) ? g_qi_h : (blockIdx.z == 1) ? g_ki_h : g_vi_h;
    __nv_bfloat16* dl = (blockIdx.z == 0) ? g_qi_l : (blockIdx.z == 1) ? g_ki_l : g_vi_l;
    int idx = (blockIdx.x * blockDim.x + threadIdx.x) * 4;
    if (idx >= MR * DD) return;
    float4 a = *(const float4*)(src + idx);
    uint32_t h0, l0, h1, l1;
    split2(a.x, a.y, h0, l0);
    split2(a.z, a.w, h1, l1);
    *(uint2*)((uint16_t*)dh + idx) = make_uint2(h0, h1);
    *(uint2*)((uint16_t*)dl + idx) = make_uint2(l0, l1);
}

// W[k][n] -> out[n][k] hi/lo (transpose)
__global__ void conv_w(const float* __restrict__ Wq, const float* __restrict__ Wk,
                       const float* __restrict__ Wv, const float* __restrict__ Wo)
{
    __shared__ float s[32][33];
    const float* W = (blockIdx.z == 0) ? Wq : (blockIdx.z == 1) ? Wk : (blockIdx.z == 2) ? Wv : Wo;
    __nv_bfloat16* dh = (blockIdx.z == 0) ? g_wq_h : (blockIdx.z == 1) ? g_wk_h : (blockIdx.z == 2) ? g_wv_h : g_wo_h;
    __nv_bfloat16* dl = (blockIdx.z == 0) ? g_wq_l : (blockIdx.z == 1) ? g_wk_l : (blockIdx.z == 2) ? g_wv_l : g_wo_l;
    int k0 = blockIdx.y * 32, n0 = blockIdx.x * 32;
    int tx = threadIdx.x, ty = threadIdx.y;
    s[ty][tx] = W[(size_t)(k0 + ty) * DD + n0 + tx];
    __syncthreads();
    float vv = s[tx][ty];
    __nv_bfloat16 hb = __float2bfloat16_rn(vv);
    __nv_bfloat16 lb = __float2bfloat16_rn(vv - __bfloat162float(hb));
    dh[(size_t)(n0 + ty) * DD + k0 + tx] = hb;
    dl[(size_t)(n0 + ty) * DD + k0 + tx] = lb;
}

__global__ void conv_wr(const float* __restrict__ Wr)
{
    int idx = (blockIdx.x * blockDim.x + threadIdx.x) * 4;
    if (idx >= DD * DD) return;
    float4 a = *(const float4*)(Wr + idx);
    uint32_t h0, l0, h1, l1;
    split2(a.x, a.y, h0, l0);
    split2(a.z, a.w, h1, l1);
    *(uint2*)((uint16_t*)g_wr_h + idx) = make_uint2(h0, h1);
    *(uint2*)((uint16_t*)g_wr_l + idx) = make_uint2(l0, l1);
}

// ===========================================================================
// Mask normalization
// ===========================================================================
__global__ void mask_detect(const unsigned char* __restrict__ am)
{
    unsigned int or1 = 0, or23 = 0;
    const uint4* p = (const uint4*)am;
    int n16 = SQL * SKL / 16;
    for (int i = threadIdx.x; i < n16; i += blockDim.x) {
        uint4 v = p[i];
        or1  |= (v.x & 0x0000FF00u) | (v.y & 0x0000FF00u) | (v.z & 0x0000FF00u) | (v.w & 0x0000FF00u);
        or23 |= (v.x & 0xFFFF0000u) | (v.y & 0xFFFF0000u) | (v.z & 0xFFFF0000u) | (v.w & 0xFFFF0000u);
    }
    int a1  = __syncthreads_or((int)(or1 != 0));
    int a23 = __syncthreads_or((int)(or23 != 0));
    if (threadIdx.x == 0) { g_or1 = a1 ? 1u : 0u; g_or23 = a23 ? 1u : 0u; }
}

__global__ void mask_convert(const unsigned char* __restrict__ am,
                             const unsigned char* __restrict__ kpm)
{
    int mode = g_or1 ? 1 : (g_or23 ? 2 : 0);
    int stride = gridDim.x * blockDim.x;
    int tid = blockIdx.x * blockDim.x + threadIdx.x;
    for (int i = tid; i < SQL * SKL; i += stride) {
        unsigned char v;
        if (mode == 1)      v = (am[i] != 0);
        else if (mode == 2) v = (((const float*)am)[i] != 0.0f);
        else                v = (((const int*)am)[i] != 0);
        g_am[i] = v;
    }
    for (int i = tid; i < BB * SKL; i += stride) {
        unsigned char v;
        if (mode == 1)      v = (kpm[i] != 0);
        else if (mode == 2) v = (((const float*)kpm)[i] != 0.0f);
        else                v = (((const int*)kpm)[i] != 0);
        g_kpm[i] = v;
    }
}

// ===========================================================================
// Shared mma projection body (BM=64 BN=64 BK=32, cp.async double buffer)
// ===========================================================================
__device__ __forceinline__ void mma_body(
    const __nv_bfloat16* __restrict__ Ahg, const __nv_bfloat16* __restrict__ Alg,
    const __nv_bfloat16* __restrict__ Bhg, const __nv_bfloat16* __restrict__ Blg,
    const float* __restrict__ bias, const float* __restrict__ resid,
    float* __restrict__ C,
    __nv_bfloat16* __restrict__ o2h, __nv_bfloat16* __restrict__ o2l,
    const float* __restrict__ rowbias,
    __nv_bfloat16 (*sA)[2][64][40], __nv_bfloat16 (*sB)[2][64][40],
    int row0, int n0)
{
    int tid = threadIdx.x, lane = tid & 31, wid = tid >> 5;
    int wm = wid >> 2, wn = wid & 3;
    int r = lane >> 2, t4 = lane & 3;
    float acc[2][2][4] = {};
    int lrow = tid >> 2, lco = (tid & 3) * 8;

    {
        int k0 = 0;
        cpa16(&sA[0][0][lrow][lco], (const uint16_t*)Ahg + (size_t)(row0 + lrow) * DD + k0 + lco);
        cpa16(&sA[0][1][lrow][lco], (const uint16_t*)Alg + (size_t)(row0 + lrow) * DD + k0 + lco);
        cpa16(&sB[0][0][lrow][lco], (const uint16_t*)Bhg + (size_t)(n0 + lrow) * DD + k0 + lco);
        cpa16(&sB[0][1][lrow][lco], (const uint16_t*)Blg + (size_t)(n0 + lrow) * DD + k0 + lco);
        asm volatile("cp.async.commit_group;");
    }
    #pragma unroll 1
    for (int it = 0; it < 16; it++) {
        if (it + 1 < 16) {
            int st = (it + 1) & 1, k0 = (it + 1) * 32;
            cpa16(&sA[st][0][lrow][lco], (const uint16_t*)Ahg + (size_t)(row0 + lrow) * DD + k0 + lco);
            cpa16(&sA[st][1][lrow][lco], (const uint16_t*)Alg + (size_t)(row0 + lrow) * DD + k0 + lco);
            cpa16(&sB[st][0][lrow][lco], (const uint16_t*)Bhg + (size_t)(n0 + lrow) * DD + k0 + lco);
            cpa16(&sB[st][1][lrow][lco], (const uint16_t*)Blg + (size_t)(n0 + lrow) * DD + k0 + lco);
            asm volatile("cp.async.commit_group;");
            asm volatile("cp.async.wait_group 1;");
        } else {
            asm volatile("cp.async.wait_group 0;");
        }
        __syncthreads();
        int st = it & 1;
        #pragma unroll
        for (int ks = 0; ks < 2; ks++) {
            uint32_t ah[2][4], al[2][4];
            #pragma unroll
            for (int mi = 0; mi < 2; mi++) {
                int row = wm * 32 + mi * 16 + r;
                const __nv_bfloat16* ph = &sA[st][0][row][ks * 16 + t4 * 2];
                const __nv_bfloat16* pl = &sA[st][1][row][ks * 16 + t4 * 2];
                ah[mi][0] = *(const uint32_t*)ph;
                ah[mi][1] = *(const uint32_t*)(ph + 8 * 40);
                ah[mi][2] = *(const uint32_t*)(ph + 8);
                ah[mi][3] = *(const uint32_t*)(ph + 8 * 40 + 8);
                al[mi][0] = *(const uint32_t*)pl;
                al[mi][1] = *(const uint32_t*)(pl + 8 * 40);
                al[mi][2] = *(const uint32_t*)(pl + 8);
                al[mi][3] = *(const uint32_t*)(pl + 8 * 40 + 8);
            }
            #pragma unroll
            for (int nj = 0; nj < 2; nj++) {
                int n = wn * 16 + nj * 8 + r;
                const __nv_bfloat16* qh = &sB[st][0][n][ks * 16 + t4 * 2];
                const __nv_bfloat16* ql = &sB[st][1][n][ks * 16 + t4 * 2];
                uint32_t bh0 = *(const uint32_t*)qh, bh1 = *(const uint32_t*)(qh + 8);
                uint32_t bl0 = *(const uint32_t*)ql, bl1 = *(const uint32_t*)(ql + 8);
                #pragma unroll
                for (int mi = 0; mi < 2; mi++) {
                    MMA_BF16(acc[mi][nj], ah[mi], bh0, bh1);
                    MMA_BF16(acc[mi][nj], ah[mi], bl0, bl1);
                    MMA_BF16(acc[mi][nj], al[mi], bh0, bh1);
                }
            }
        }
        __syncthreads();
    }
    #pragma unroll
    for (int mi = 0; mi < 2; mi++) {
        #pragma unroll
        for (int nj = 0; nj < 2; nj++) {
            int col = n0 + wn * 16 + nj * 8 + t4 * 2;
            float b0 = bias[col], b1 = bias[col + 1];
            float rb0 = rowbias ? rowbias[col] : 0.f;
            float rb1 = rowbias ? rowbias[col + 1] : 0.f;
            #pragma unroll
            for (int rr = 0; rr < 2; rr++) {
                int row = row0 + wm * 32 + mi * 16 + r + rr * 8;
                float v0 = acc[mi][nj][rr * 2 + 0] + b0;
                float v1 = acc[mi][nj][rr * 2 + 1] + b1;
                if (resid) {
                    float2 r2 = *(const float2*)(resid + (size_t)row * DD + col);
                    v0 += r2.x; v1 += r2.y;
                }
                *(float2*)(C + (size_t)row * DD + col) = make_float2(v0, v1);
                if (o2h) {
                    uint32_t h, l;
                    split2(v0 + rb0, v1 + rb1, h, l);
                    *(uint32_t*)((uint16_t*)o2h + (size_t)row * DD + col) = h;
                    *(uint32_t*)((uint16_t*)o2l + (size_t)row * DD + col) = l;
                }
            }
        }
    }
}

// Fused Q/K/V projections: one launch, z selects the problem.
__global__ void __launch_bounds__(256, 2)
mma_qkv(const float* __restrict__ bq, const float* __restrict__ bk,
        const float* __restrict__ bv, const float* __restrict__ vb)
{
    __shared__ __align__(16) __nv_bfloat16 sA[2][2][64][40];
    __shared__ __align__(16) __nv_bfloat16 sB[2][2][64][40];
    int z = blockIdx.z;
    const __nv_bfloat16 *Ah, *Al, *Bh, *Bl;
    const float* bias;
    float* C;
    __nv_bfloat16 *o2h = nullptr, *o2l = nullptr;
    const float* rb = nullptr;
    if (z == 0) {
        Ah = g_qi_h; Al = g_qi_l; Bh = g_wq_h; Bl = g_wq_l;
        bias = bq; C = g_qh; o2h = g_qv_h; o2l = g_qv_l; rb = vb;
    } else if (z == 1) {
        Ah = g_ki_h; Al = g_ki_l; Bh = g_wk_h; Bl = g_wk_l;
        bias = bk; C = g_kh;
    } else {
        Ah = g_vi_h; Al = g_vi_l; Bh = g_wv_h; Bl = g_wv_l;
        bias = bv; C = g_vh;
    }
    mma_body(Ah, Al, Bh, Bl, bias, nullptr, C, o2h, o2l, rb,
             sA, sB, blockIdx.y * 64, blockIdx.x * 64);
}

// Generic single-GEMM wrapper (used for Wo projection)
__global__ void __launch_bounds__(256, 2)
mma2(const __nv_bfloat16* __restrict__ Ahg, const __nv_bfloat16* __restrict__ Alg,
     const __nv_bfloat16* __restrict__ Bhg, const __nv_bfloat16* __restrict__ Blg,
     const float* __restrict__ bias, const float* __restrict__ resid,
     float* __restrict__ C)
{
    __shared__ __align__(16) __nv_bfloat16 sA[2][2][64][40];
    __shared__ __align__(16) __nv_bfloat16 sB[2][2][64][40];
    mma_body(Ahg, Alg, Bhg, Blg, bias, resid, C, nullptr, nullptr, nullptr,
             sA, sB, blockIdx.y * 64, blockIdx.x * 64);
}

// ===========================================================================
// t_mma: T[q][bh][e] (hi/lo) = (qh + v_bias) @ Wr_h^T, per head.
// ===========================================================================
__global__ void __launch_bounds__(256, 2)
t_mma()
{
    __shared__ __align__(16) __nv_bfloat16 tA[2][64][72];
    __shared__ __align__(16) __nv_bfloat16 tB[2][64][72];
    int tid = threadIdx.x, lane = tid & 31, wid = tid >> 5;
    int wm = wid >> 2, wn = wid & 3;
    int h = blockIdx.z, hoff = h * DHH;
    int m0 = blockIdx.y * 64, e0 = blockIdx.x * 64;
    int r = lane >> 2, t4 = lane & 3;
    float acc[2][2][4] = {};

    #pragma unroll
    for (int j = 0; j < 2; j++) {
        int c = tid + j * 256;
        int row = c >> 3, off = (c & 7) * 8;
        *(uint4*)&tA[0][row][off] = *(const uint4*)((const uint16_t*)g_qv_h + (size_t)(m0 + row) * DD + hoff + off);
        *(uint4*)&tA[1][row][off] = *(const uint4*)((const uint16_t*)g_qv_l + (size_t)(m0 + row) * DD + hoff + off);
        *(uint4*)&tB[0][row][off] = *(const uint4*)((const uint16_t*)g_wr_h + (size_t)(e0 + row) * DD + hoff + off);
        *(uint4*)&tB[1][row][off] = *(const uint4*)((const uint16_t*)g_wr_l + (size_t)(e0 + row) * DD + hoff + off);
    }
    __syncthreads();

    #pragma unroll
    for (int ks = 0; ks < 4; ks++) {
        uint32_t ah[2][4], al[2][4];
        #pragma unroll
        for (int mi = 0; mi < 2; mi++) {
            int row = wm * 32 + mi * 16 + r;
            const __nv_bfloat16* ph = &tA[0][row][ks * 16 + t4 * 2];
            const __nv_bfloat16* pl = &tA[1][row][ks * 16 + t4 * 2];
            ah[mi][0] = *(const uint32_t*)ph;
            ah[mi][1] = *(const uint32_t*)(ph + 8 * 72);
            ah[mi][2] = *(const uint32_t*)(ph + 8);
            ah[mi][3] = *(const uint32_t*)(ph + 8 * 72 + 8);
            al[mi][0] = *(const uint32_t*)pl;
            al[mi][1] = *(const uint32_t*)(pl + 8 * 72);
            al[mi][2] = *(const uint32_t*)(pl + 8);
            al[mi][3] = *(const uint32_t*)(pl + 8 * 72 + 8);
        }
        #pragma unroll
        for (int nj = 0; nj < 2; nj++) {
            int n = wn * 16 + nj * 8 + r;
            const __nv_bfloat16* qh = &tB[0][n][ks * 16 + t4 * 2];
            const __nv_bfloat16* ql = &tB[1][n][ks * 16 + t4 * 2];
            uint32_t bh0 = *(const uint32_t*)qh, bh1 = *(const uint32_t*)(qh + 8);
            uint32_t bl0 = *(const uint32_t*)ql, bl1 = *(const uint32_t*)(ql + 8);
            #pragma unroll
            for (int mi = 0; mi < 2; mi++) {
                MMA_BF16(acc[mi][nj], ah[mi], bh0, bh1);
                MMA_BF16(acc[mi][nj], ah[mi], bl0, bl1);
                MMA_BF16(acc[mi][nj], al[mi], bh0, bh1);
            }
        }
    }
    #pragma unroll
    for (int mi = 0; mi < 2; mi++) {
        #pragma unroll
        for (int nj = 0; nj < 2; nj++) {
            int e = e0 + wn * 16 + nj * 8 + t4 * 2;
            #pragma unroll
            for (int rr = 0; rr < 2; rr++) {
                int m = m0 + wm * 32 + mi * 16 + r + rr * 8;
                int q = m & 511, b = m >> 9;
                int bh = b * HH + h;
                uint32_t hh, ll;
                split2(acc[mi][nj][rr * 2 + 0], acc[mi][nj][rr * 2 + 1], hh, ll);
                size_t di = ((size_t)q * BHH + bh) * DD + e;
                *(uint32_t*)((uint16_t*)g_T_h + di) = hh;
                *(uint32_t*)((uint16_t*)g_T_l + di) = ll;
            }
        }
    }
}

// c[b,q,h] = sum_d (qh+v_bias)*br_h
__global__ void c_kernel(const float* __restrict__ vb, const float* __restrict__ br)
{
    int idx = blockIdx.x * blockDim.x + threadIdx.x;
    if (idx >= MR * HH) return;
    int h = idx & 7;
    int m = idx >> 3;
    int hoff = h * DHH;
    const float* qrow = g_qh + (size_t)m * DD + hoff;
    float s = 0.f;
    #pragma unroll 8
    for (int d = 0; d < DHH; d++)
        s += (qrow[d] + vb[hoff + d]) * br[hoff + d];
    g_c[idx] = s;
}

// ===========================================================================
// ac (scalar, R2): score[bh,q,k] = sum_d (qh+u)*kh
// ===========================================================================
__global__ void ac_kernel(const float* __restrict__ ub, float* __restrict__ score)
{
    __shared__ float As[16][64];
    __shared__ float Ks[16][64];
    int bh = blockIdx.z, b = bh >> 3, h = bh & 7, hoff = h * DHH;
    int q0 = blockIdx.y * 64, k0 = blockIdx.x * 64;
    int tid = threadIdx.x;
    int tx = tid & 15, ty = tid >> 4;

    const unsigned char* rp = g_am + (size_t)(q0 + (tid >> 2)) * SKL + k0 + (tid & 3) * 16;
    int allm = 1;
    #pragma unroll
    for (int j = 0; j < 16; j++) allm &= (rp[j] != 0);
    if (__syncthreads_and(allm)) return;

    int lr = tid >> 2, lc = (tid & 3) * 4;
    float acc[4][4] = {};
    for (int d0 = 0; d0 < DHH; d0 += 16) {
        float4 a4 = *(const float4*)(g_qh + ((size_t)b * SQL + q0 + lr) * DD + hoff + d0 + lc);
        float4 u4 = *(const float4*)(ub + hoff + d0 + lc);
        As[lc + 0][lr] = a4.x + u4.x;
        As[lc + 1][lr] = a4.y + u4.y;
        As[lc + 2][lr] = a4.z + u4.z;
        As[lc + 3][lr] = a4.w + u4.w;
        float4 k4 = *(const float4*)(g_kh + ((size_t)b * SQL + k0 + lr) * DD + hoff + d0 + lc);
        Ks[lc + 0][lr] = k4.x;
        Ks[lc + 1][lr] = k4.y;
        Ks[lc + 2][lr] = k4.z;
        Ks[lc + 3][lr] = k4.w;
        __syncthreads();
        #pragma unroll
        for (int kk = 0; kk < 16; kk++) {
            float a[4], bv[4];
            #pragma unroll
            for (int i = 0; i < 4; i++) a[i] = As[kk][ty * 4 + i];
            #pragma unroll
            for (int j = 0; j < 4; j++) bv[j] = Ks[kk][tx * 4 + j];
            #pragma unroll
            for (int i = 0; i < 4; i++)
                #pragma unroll
                for (int j = 0; j < 4; j++)
                    acc[i][j] += a[i] * bv[j];
        }
        __syncthreads();
    }
    #pragma unroll
    for (int i = 0; i < 4; i++) {
        float4 sv = {acc[i][0], acc[i][1], acc[i][2], acc[i][3]};
        *(float4*)(score + ((size_t)bh * SQL + q0 + ty * 4 + i) * SKL + k0 + tx * 4) = sv;
    }
}

// ===========================================================================
// bd_sm_mma: score -> attn_weights fused.
//   s[bh,q,k] = (ac + T[q,bh,:]@pos_emb[q,k,:] + c)/8, masked softmax over k,
//   written in place. One block per q: 32 bh rows x full 512 k.
// ===========================================================================
__global__ void __launch_bounds__(256)
bd_sm_mma(const float* __restrict__ pos_emb, float* __restrict__ score)
{
    __shared__ __align__(16) __nv_bfloat16 sT[2][32][136];
    __shared__ unsigned char cmask[BB][SKL];
    __shared__ float smax[BHH][9], ssum[BHH][9];
    int q = blockIdx.x;
    int tid = threadIdx.x, lane = tid & 31, wn = tid >> 5;
    int r = lane >> 2, t4 = lane & 3;

    // combined mask per (b, k): am[q][k] | kpm[b][k]
    #pragma unroll
    for (int j = 0; j < 8; j++) {
        int i = tid + j * 256;          // 2048 entries
        int b = i >> 9, kk = i & 511;
        cmask[b][kk] = g_am[(size_t)q * SKL + kk] | g_kpm[(size_t)b * SKL + kk];
    }

    // warp activity (causal skip of the MMA work only)
    int k_a = wn * 64 + lane * 2;
    unsigned char ma = g_am[(size_t)q * SKL + k_a];
    unsigned char mb = g_am[(size_t)q * SKL + k_a + 1];
    int act = __ballot_sync(0xffffffffu, (ma == 0) || (mb == 0)) != 0;

    float acc[2][8][4] = {};

    #pragma unroll 1
    for (int ec = 0; ec < 4; ec++) {
        #pragma unroll
        for (int j = 0; j < 2; j++) {
            int c = tid + j * 256;
            int row = c >> 4, off = (c & 15) * 8;
            size_t gi = ((size_t)q * BHH + row) * DD + ec * 128 + off;
            *(uint4*)&sT[0][row][off] = *(const uint4*)((const uint16_t*)g_T_h + gi);
            *(uint4*)&sT[1][row][off] = *(const uint4*)((const uint16_t*)g_T_l + gi);
        }
        __syncthreads();
        if (act) {
            #pragma unroll 1
            for (int ks = 0; ks < 8; ks++) {
                uint32_t ah[2][4], al[2][4];
                #pragma unroll
                for (int mi = 0; mi < 2; mi++) {
                    int row = mi * 16 + r;
                    const __nv_bfloat16* ph = &sT[0][row][ks * 16 + t4 * 2];
                    const __nv_bfloat16* pl = &sT[1][row][ks * 16 + t4 * 2];
                    ah[mi][0] = *(const uint32_t*)ph;
                    ah[mi][1] = *(const uint32_t*)(ph + 8 * 136);
                    ah[mi][2] = *(const uint32_t*)(ph + 8);
                    ah[mi][3] = *(const uint32_t*)(ph + 8 * 136 + 8);
                    al[mi][0] = *(const uint32_t*)pl;
                    al[mi][1] = *(const uint32_t*)(pl + 8 * 136);
                    al[mi][2] = *(const uint32_t*)(pl + 8);
                    al[mi][3] = *(const uint32_t*)(pl + 8 * 136 + 8);
                }
                int eg = ec * 128 + ks * 16 + t4 * 2;
                #pragma unroll
                for (int nj = 0; nj < 8; nj++) {
                    int n = wn * 64 + nj * 8 + r;
                    const float* pp = pos_emb + ((size_t)q * SKL + n) * DD + eg;
                    float2 p0 = *(const float2*)pp;
                    float2 p1 = *(const float2*)(pp + 8);
                    uint32_t bh0, bl0, bh1, bl1;
                    split2(p0.x, p0.y, bh0, bl0);
                    split2(p1.x, p1.y, bh1, bl1);
                    #pragma unroll
                    for (int mi = 0; mi < 2; mi++) {
                        MMA_BF16(acc[mi][nj], ah[mi], bh0, bh1);
                        MMA_BF16(acc[mi][nj], ah[mi], bl0, bl1);
                        MMA_BF16(acc[mi][nj], al[mi], bh0, bh1);
                    }
                }
            }
        }
        __syncthreads();
    }

    // ---- fused epilogue: masked scores + row softmax + write weights ----
    float rmax[2][2] = {{-INFINITY, -INFINITY}, {-INFINITY, -INFINITY}};
    #pragma unroll
    for (int mi = 0; mi < 2; mi++) {
        #pragma unroll
        for (int rr = 0; rr < 2; rr++) {
            int bh = mi * 16 + r + rr * 8;
            int b = bh >> 3, h = bh & 7;
            float cc = g_c[((size_t)b * SQL + q) * HH + h];
            const float* srow = score + ((size_t)bh * SQL + q) * SKL;
            #pragma unroll
            for (int nj = 0; nj < 8; nj++) {
                int k = wn * 64 + nj * 8 + t4 * 2;
                float2 s2 = *(const float2*)(srow + k);
                float v0 = (s2.x + acc[mi][nj][rr * 2 + 0] + cc) * 0.125f;
                float v1 = (s2.y + acc[mi][nj][rr * 2 + 1] + cc) * 0.125f;
                if (cmask[b][k])     v0 = -INFINITY;
                if (cmask[b][k + 1]) v1 = -INFINITY;
                acc[mi][nj][rr * 2 + 0] = v0;
                acc[mi][nj][rr * 2 + 1] = v1;
                rmax[mi][rr] = fmaxf(rmax[mi][rr], fmaxf(v0, v1));
            }
        }
    }
    // reduce max over the t4 quad (lanes with same r)
    #pragma unroll
    for (int mi = 0; mi < 2; mi++)
        #pragma unroll
        for (int rr = 0; rr < 2; rr++) {
            rmax[mi][rr] = fmaxf(rmax[mi][rr], __shfl_xor_sync(0xffffffffu, rmax[mi][rr], 1));
            rmax[mi][rr] = fmaxf(rmax[mi][rr], __shfl_xor_sync(0xffffffffu, rmax[mi][rr], 2));
        }
    if (t4 == 0) {
        #pragma unroll
        for (int mi = 0; mi < 2; mi++)
            #pragma unroll
            for (int rr = 0; rr < 2; rr++)
                smax[mi * 16 + r + rr * 8][wn] = rmax[mi][rr];
    }
    __syncthreads();

    float rsum[2][2];
    #pragma unroll
    for (int mi = 0; mi < 2; mi++) {
        #pragma unroll
        for (int rr = 0; rr < 2; rr++) {
            int bh = mi * 16 + r + rr * 8;
            float gm = smax[bh][0];
            #pragma unroll
            for (int w = 1; w < 8; w++) gm = fmaxf(gm, smax[bh][w]);
            float sum = 0.f;
            #pragma unroll
            for (int nj = 0; nj < 8; nj++) {
                #pragma unroll
                for (int c = 0; c < 2; c++) {
                    float v = acc[mi][nj][rr * 2 + c];
                    float e = (v == -INFINITY) ? 0.f : __expf(v - gm);
                    acc[mi][nj][rr * 2 + c] = e;
                    sum += e;
                }
            }
            sum += __shfl_xor_sync(0xffffffffu, sum, 1);
            sum += __shfl_xor_sync(0xffffffffu, sum, 2);
            rsum[mi][rr] = sum;
        }
    }
    if (t4 == 0) {
        #pragma unroll
        for (int mi = 0; mi < 2; mi++)
            #pragma unroll
            for (int rr = 0; rr < 2; rr++)
                ssum[mi * 16 + r + rr * 8][wn] = rsum[mi][rr];
    }
    __syncthreads();

    #pragma unroll
    for (int mi = 0; mi < 2; mi++) {
        #pragma unroll
        for (int rr = 0; rr < 2; rr++) {
            int bh = mi * 16 + r + rr * 8;
            float tot = 0.f;
            #pragma unroll
            for (int w = 0; w < 8; w++) tot += ssum[bh][w];
            float inv = (tot > 0.f) ? 1.f / tot : 0.f;
            float* srow = score + ((size_t)bh * SQL + q) * SKL;
            #pragma unroll
            for (int nj = 0; nj < 8; nj++) {
                int k = wn * 64 + nj * 8 + t4 * 2;
                *(float2*)(srow + k) = make_float2(acc[mi][nj][rr * 2 + 0] * inv,
                                                   acc[mi][nj][rr * 2 + 1] * inv);
            }
        }
    }
}

// ===========================================================================
// av (scalar R2) + fused hi/lo split of the output
// ===========================================================================
__global__ void av_kernel(const float* __restrict__ score)
{
    __shared__ float As[16][64];
    __shared__ float Ws[16][64];
    int bh = blockIdx.y, b = bh >> 3, h = bh & 7, hoff = h * DHH;
    int q0 = blockIdx.x * 64;
    int tid = threadIdx.x;
    int tx = tid & 15, ty = tid >> 4;
    float acc[4][4] = {};

    int la_q = tid >> 2, la_k = (tid & 3) * 4;
    int lw_k = tid >> 4, lw_d = (tid & 15) * 4;

    for (int k0 = 0; k0 < SKL; k0 += 16) {
        const unsigned char* rp = g_am + (size_t)(q0 + (tid >> 2)) * SKL + k0 + (tid & 3) * 4;
        int allm = (rp[0] && rp[1] && rp[2] && rp[3]);
        if (__syncthreads_and(allm)) continue;

        float4 a4 = *(const float4*)(score + ((size_t)bh * SQL + q0 + la_q) * SKL + k0 + la_k);
        As[la_k + 0][la_q] = a4.x;
        As[la_k + 1][la_q] = a4.y;
        As[la_k + 2][la_q] = a4.z;
        As[la_k + 3][la_q] = a4.w;
        float4 w4 = *(const float4*)(g_vh + ((size_t)b * SQL + k0 + lw_k) * DD + hoff + lw_d);
        *(float4*)&Ws[lw_k][lw_d] = w4;
        __syncthreads();
        #pragma unroll
        for (int kk = 0; kk < 16; kk++) {
            float a[4], bv[4];
            #pragma unroll
            for (int i = 0; i < 4; i++) a[i] = As[kk][ty * 4 + i];
            #pragma unroll
            for (int j = 0; j < 4; j++) bv[j] = Ws[kk][tx * 4 + j];
            #pragma unroll
            for (int i = 0; i < 4; i++)
                #pragma unroll
                for (int j = 0; j < 4; j++)
                    acc[i][j] += a[i] * bv[j];
        }
        __syncthreads();
    }
    #pragma unroll
    for (int i = 0; i < 4; i++) {
        size_t oi = ((size_t)b * SQL + q0 + ty * 4 + i) * DD + hoff + tx * 4;
        float4 sv = {acc[i][0], acc[i][1], acc[i][2], acc[i][3]};
        *(float4*)(g_att + oi) = sv;
        uint32_t h0, l0, h1, l1;
        split2(sv.x, sv.y, h0, l0);
        split2(sv.z, sv.w, h1, l1);
        *(uint2*)((uint16_t*)g_at_h + oi) = make_uint2(h0, h1);
        *(uint2*)((uint16_t*)g_at_l + oi) = make_uint2(l0, l1);
    }
}

// ===========================================================================
__global__ void ln_kernel(const float* __restrict__ X, const float* __restrict__ gamma,
                          const float* __restrict__ beta, float* __restrict__ out)
{
    int row = blockIdx.x;
    int tid = threadIdx.x;  // 256
    const float* x = X + (size_t)row * DD;
    float2 v = *(const float2*)(x + tid * 2);
    float s = v.x + v.y;
    float s2 = v.x * v.x + v.y * v.y;
    #pragma unroll
    for (int off = 16; off; off >>= 1) {
        s  += __shfl_xor_sync(0xffffffffu, s, off);
        s2 += __shfl_xor_sync(0xffffffffu, s2, off);
    }
    __shared__ float rs[8], rs2[8];
    int wid = tid >> 5, lane = tid & 31;
    if (lane == 0) { rs[wid] = s; rs2[wid] = s2; }
    __syncthreads();
    s = 0.f; s2 = 0.f;
    #pragma unroll
    for (int i = 0; i < 8; i++) { s += rs[i]; s2 += rs2[i]; }
    float mean = s * (1.f / DD);
    float var = s2 * (1.f / DD) - mean * mean;
    float inv = rsqrtf(var + 1e-5f);
    float2 g2 = *(const float2*)(gamma + tid * 2);
    float2 b2 = *(const float2*)(beta + tid * 2);
    float2 o;
    o.x = (v.x - mean) * inv * g2.x + b2.x;
    o.y = (v.y - mean) * inv * g2.y + b2.y;
    *(float2*)(out + (size_t)row * DD + tid * 2) = o;
}

// ===========================================================================
extern "C" void kernel_launch(void* const* d_in, const int* in_sizes, int n_in,
                              void* d_out, int out_size)
{
    const float* q  = (const float*)d_in[0];
    const float* k  = (const float*)d_in[1];
    const float* v  = (const float*)d_in[2];
    const float* pe = (const float*)d_in[3];
    const unsigned char* kpm = (const unsigned char*)d_in[4];
    const unsigned char* am  = (const unsigned char*)d_in[5];
    const float* Wq = (const float*)d_in[6];
    const float* bq = (const float*)d_in[7];
    const float* Wk = (const float*)d_in[8];
    const float* bk = (const float*)d_in[9];
    const float* Wv = (const float*)d_in[10];
    const float* bv = (const float*)d_in[11];
    const float* Wo = (const float*)d_in[12];
    const float* bo = (const float*)d_in[13];
    const float* Wr = (const float*)d_in[14];
    const float* br = (const float*)d_in[15];
    const float* ub = (const float*)d_in[16];
    const float* vb = (const float*)d_in[17];
    const float* lg = (const float*)d_in[18];
    const float* lb = (const float*)d_in[19];

    float* normed = (float*)d_out;
    float* attnw  = normed + (size_t)BB * SQL * DD;

    float *o2;
    cudaGetSymbolAddress((void**)&o2,  g_o2);
    __nv_bfloat16 *woh, *wol, *ath, *atl;
    cudaGetSymbolAddress((void**)&woh, g_wo_h); cudaGetSymbolAddress((void**)&wol, g_wo_l);
    cudaGetSymbolAddress((void**)&ath, g_at_h); cudaGetSymbolAddress((void**)&atl, g_at_l);

    // mask normalization
    mask_detect<<<1, 1024>>>(am);
    mask_convert<<<64, 256>>>(am, kpm);

    // operand conversions
    conv_inputs<<<dim3(MR * DD / 4 / 256, 1, 3), 256>>>(q, k, v);
    conv_w<<<dim3(16, 16, 4), dim3(32, 32)>>>(Wq, Wk, Wv, Wo);
    conv_wr<<<DD * DD / 4 / 256, 256>>>(Wr);

    // fused Q/K/V projections (tensor); Q also emits split(qh+vb)
    mma_qkv<<<dim3(8, 32, 3), 256>>>(bq, bk, bv, vb);

    c_kernel<<<(MR * HH + 255) / 256, 256>>>(vb, br);
    t_mma<<<dim3(8, 32, 8), 256>>>();

    ac_kernel<<<dim3(8, 8, 32), 256>>>(ub, attnw);
    bd_sm_mma<<<512, 256>>>(pe, attnw);

    av_kernel<<<dim3(8, 32), 256>>>(attnw);

    mma2<<<dim3(8, 32), 256>>>(ath, atl, woh, wol, bo, q, o2);
    ln_kernel<<<MR, 256>>>(o2, lg, lb, normed);
}

// round 14
// speedup vs baseline: 1.1404x; 1.0478x over previous
#include <cuda_runtime.h>
#include <cuda_bf16.h>
#include <math.h>
#include <stdint.h>

#define BB   4
#define SQL  512
#define SKL  512
#define DD   512
#define HH   8
#define DHH  64
#define BHH  32
#define MR   2048

// ---------------- f32 scratch ----------------
__device__ float g_qh[MR * DD];
__device__ float g_kh[MR * DD];
__device__ float g_vh[MR * DD];
__device__ float g_c [MR * HH];
__device__ float g_att[MR * DD];
__device__ float g_o2 [MR * DD];

// ---------------- bf16 hi/lo scratch ----------------
__device__ __nv_bfloat16 g_qi_h[MR * DD], g_qi_l[MR * DD];
__device__ __nv_bfloat16 g_ki_h[MR * DD], g_ki_l[MR * DD];
__device__ __nv_bfloat16 g_vi_h[MR * DD], g_vi_l[MR * DD];
__device__ __nv_bfloat16 g_wq_h[DD * DD], g_wq_l[DD * DD];
__device__ __nv_bfloat16 g_wk_h[DD * DD], g_wk_l[DD * DD];
__device__ __nv_bfloat16 g_wv_h[DD * DD], g_wv_l[DD * DD];
__device__ __nv_bfloat16 g_wo_h[DD * DD], g_wo_l[DD * DD];
__device__ __nv_bfloat16 g_wr_h[DD * DD], g_wr_l[DD * DD];
__device__ __nv_bfloat16 g_qv_h[MR * DD], g_qv_l[MR * DD];   // split(qh + v_bias)
__device__ __nv_bfloat16 g_qu_h[MR * DD], g_qu_l[MR * DD];   // split(qh + u_bias)
__device__ __nv_bfloat16 g_kh_h[MR * DD], g_kh_l[MR * DD];   // split(kh)
__device__ __nv_bfloat16 g_T_h[SQL * BHH * DD], g_T_l[SQL * BHH * DD]; // [q][bh][e]
__device__ __nv_bfloat16 g_at_h[MR * DD], g_at_l[MR * DD];

__device__ unsigned char g_am [SQL * SKL];
__device__ unsigned char g_kpm[BB * SKL];
__device__ unsigned int g_or1, g_or23;

// ===========================================================================
// helpers
// ===========================================================================
__device__ __forceinline__ uint32_t smem_u32(const void* p) {
    uint32_t a;
    asm("{ .reg .u64 t; cvta.to.shared.u64 t, %1; cvt.u32.u64 %0, t; }" : "=r"(a) : "l"(p));
    return a;
}
__device__ __forceinline__ uint32_t pack_bf16x2(float x, float y) {
    uint32_t r;
    asm("cvt.rn.bf16x2.f32 %0, %1, %2;" : "=r"(r) : "f"(y), "f"(x));
    return r;
}
__device__ __forceinline__ float bf_lo(uint32_t w) { return __uint_as_float(w << 16); }
__device__ __forceinline__ float bf_hi(uint32_t w) { return __uint_as_float(w & 0xffff0000u); }

#define MMA_BF16(c, a, b0, b1) \
    asm volatile("mma.sync.aligned.m16n8k16.row.col.f32.bf16.bf16.f32 " \
        "{%0,%1,%2,%3}, {%4,%5,%6,%7}, {%8,%9}, {%0,%1,%2,%3};" \
        : "+f"((c)[0]), "+f"((c)[1]), "+f"((c)[2]), "+f"((c)[3]) \
        : "r"((a)[0]), "r"((a)[1]), "r"((a)[2]), "r"((a)[3]), "r"(b0), "r"(b1))

__device__ __forceinline__ void cpa16(const void* s, const void* g) {
    asm volatile("cp.async.ca.shared.global [%0], [%1], 16;" :: "r"(smem_u32(s)), "l"(g));
}
__device__ __forceinline__ void split2(float x, float y, uint32_t& h, uint32_t& l) {
    h = pack_bf16x2(x, y);
    l = pack_bf16x2(x - bf_lo(h), y - bf_hi(h));
}
__device__ __forceinline__ int bytes_all_nz(unsigned int v)
{
    return (((v - 0x01010101u) & ~v) & 0x80808080u) == 0u;
}

// ===========================================================================
// Conversion kernels
// ===========================================================================
__global__ void conv_inputs(const float* __restrict__ q, const float* __restrict__ k,
                            const float* __restrict__ v)
{
    const float* src = (blockIdx.z == 0) ? q : (blockIdx.z == 1) ? k : v;
    __nv_bfloat16* dh = (blockIdx.z == 0) ? g_qi_h : (blockIdx.z == 1) ? g_ki_h : g_vi_h;
    __nv_bfloat16* dl = (blockIdx.z == 0) ? g_qi_l : (blockIdx.z == 1) ? g_ki_l : g_vi_l;
    int idx = (blockIdx.x * blockDim.x + threadIdx.x) * 4;
    if (idx >= MR * DD) return;
    float4 a = *(const float4*)(src + idx);
    uint32_t h0, l0, h1, l1;
    split2(a.x, a.y, h0, l0);
    split2(a.z, a.w, h1, l1);
    *(uint2*)((uint16_t*)dh + idx) = make_uint2(h0, h1);
    *(uint2*)((uint16_t*)dl + idx) = make_uint2(l0, l1);
}

// W[k][n] -> out[n][k] hi/lo (transpose)
__global__ void conv_w(const float* __restrict__ Wq, const float* __restrict__ Wk,
                       const float* __restrict__ Wv, const float* __restrict__ Wo)
{
    __shared__ float s[32][33];
    const float* W = (blockIdx.z == 0) ? Wq : (blockIdx.z == 1) ? Wk : (blockIdx.z == 2) ? Wv : Wo;
    __nv_bfloat16* dh = (blockIdx.z == 0) ? g_wq_h : (blockIdx.z == 1) ? g_wk_h : (blockIdx.z == 2) ? g_wv_h : g_wo_h;
    __nv_bfloat16* dl = (blockIdx.z == 0) ? g_wq_l : (blockIdx.z == 1) ? g_wk_l : (blockIdx.z == 2) ? g_wv_l : g_wo_l;
    int k0 = blockIdx.y * 32, n0 = blockIdx.x * 32;
    int tx = threadIdx.x, ty = threadIdx.y;
    s[ty][tx] = W[(size_t)(k0 + ty) * DD + n0 + tx];
    __syncthreads();
    float vv = s[tx][ty];
    __nv_bfloat16 hb = __float2bfloat16_rn(vv);
    __nv_bfloat16 lb = __float2bfloat16_rn(vv - __bfloat162float(hb));
    dh[(size_t)(n0 + ty) * DD + k0 + tx] = hb;
    dl[(size_t)(n0 + ty) * DD + k0 + tx] = lb;
}

__global__ void conv_wr(const float* __restrict__ Wr)
{
    int idx = (blockIdx.x * blockDim.x + threadIdx.x) * 4;
    if (idx >= DD * DD) return;
    float4 a = *(const float4*)(Wr + idx);
    uint32_t h0, l0, h1, l1;
    split2(a.x, a.y, h0, l0);
    split2(a.z, a.w, h1, l1);
    *(uint2*)((uint16_t*)g_wr_h + idx) = make_uint2(h0, h1);
    *(uint2*)((uint16_t*)g_wr_l + idx) = make_uint2(l0, l1);
}

// ===========================================================================
// Mask normalization
// ===========================================================================
__global__ void mask_detect(const unsigned char* __restrict__ am)
{
    unsigned int or1 = 0, or23 = 0;
    const uint4* p = (const uint4*)am;
    int n16 = SQL * SKL / 16;
    for (int i = threadIdx.x; i < n16; i += blockDim.x) {
        uint4 v = p[i];
        or1  |= (v.x & 0x0000FF00u) | (v.y & 0x0000FF00u) | (v.z & 0x0000FF00u) | (v.w & 0x0000FF00u);
        or23 |= (v.x & 0xFFFF0000u) | (v.y & 0xFFFF0000u) | (v.z & 0xFFFF0000u) | (v.w & 0xFFFF0000u);
    }
    int a1  = __syncthreads_or((int)(or1 != 0));
    int a23 = __syncthreads_or((int)(or23 != 0));
    if (threadIdx.x == 0) { g_or1 = a1 ? 1u : 0u; g_or23 = a23 ? 1u : 0u; }
}

__global__ void mask_convert(const unsigned char* __restrict__ am,
                             const unsigned char* __restrict__ kpm)
{
    int mode = g_or1 ? 1 : (g_or23 ? 2 : 0);
    int stride = gridDim.x * blockDim.x;
    int tid = blockIdx.x * blockDim.x + threadIdx.x;
    for (int i = tid; i < SQL * SKL; i += stride) {
        unsigned char v;
        if (mode == 1)      v = (am[i] != 0);
        else if (mode == 2) v = (((const float*)am)[i] != 0.0f);
        else                v = (((const int*)am)[i] != 0);
        g_am[i] = v;
    }
    for (int i = tid; i < BB * SKL; i += stride) {
        unsigned char v;
        if (mode == 1)      v = (kpm[i] != 0);
        else if (mode == 2) v = (((const float*)kpm)[i] != 0.0f);
        else                v = (((const int*)kpm)[i] != 0);
        g_kpm[i] = v;
    }
}

// ===========================================================================
// Shared mma projection body (BM=64 BN=64 BK=32, cp.async double buffer)
// Optional dual split outputs: o2 = split(C+rb2), o3 = split(C+rb3)
// ===========================================================================
__device__ __forceinline__ void mma_body(
    const __nv_bfloat16* __restrict__ Ahg, const __nv_bfloat16* __restrict__ Alg,
    const __nv_bfloat16* __restrict__ Bhg, const __nv_bfloat16* __restrict__ Blg,
    const float* __restrict__ bias, const float* __restrict__ resid,
    float* __restrict__ C,
    __nv_bfloat16* __restrict__ o2h, __nv_bfloat16* __restrict__ o2l,
    const float* __restrict__ rb2,
    __nv_bfloat16* __restrict__ o3h, __nv_bfloat16* __restrict__ o3l,
    const float* __restrict__ rb3,
    __nv_bfloat16 (*sA)[2][64][40], __nv_bfloat16 (*sB)[2][64][40],
    int row0, int n0)
{
    int tid = threadIdx.x, lane = tid & 31, wid = tid >> 5;
    int wm = wid >> 2, wn = wid & 3;
    int r = lane >> 2, t4 = lane & 3;
    float acc[2][2][4] = {};
    int lrow = tid >> 2, lco = (tid & 3) * 8;

    {
        int k0 = 0;
        cpa16(&sA[0][0][lrow][lco], (const uint16_t*)Ahg + (size_t)(row0 + lrow) * DD + k0 + lco);
        cpa16(&sA[0][1][lrow][lco], (const uint16_t*)Alg + (size_t)(row0 + lrow) * DD + k0 + lco);
        cpa16(&sB[0][0][lrow][lco], (const uint16_t*)Bhg + (size_t)(n0 + lrow) * DD + k0 + lco);
        cpa16(&sB[0][1][lrow][lco], (const uint16_t*)Blg + (size_t)(n0 + lrow) * DD + k0 + lco);
        asm volatile("cp.async.commit_group;");
    }
    #pragma unroll 1
    for (int it = 0; it < 16; it++) {
        if (it + 1 < 16) {
            int st = (it + 1) & 1, k0 = (it + 1) * 32;
            cpa16(&sA[st][0][lrow][lco], (const uint16_t*)Ahg + (size_t)(row0 + lrow) * DD + k0 + lco);
            cpa16(&sA[st][1][lrow][lco], (const uint16_t*)Alg + (size_t)(row0 + lrow) * DD + k0 + lco);
            cpa16(&sB[st][0][lrow][lco], (const uint16_t*)Bhg + (size_t)(n0 + lrow) * DD + k0 + lco);
            cpa16(&sB[st][1][lrow][lco], (const uint16_t*)Blg + (size_t)(n0 + lrow) * DD + k0 + lco);
            asm volatile("cp.async.commit_group;");
            asm volatile("cp.async.wait_group 1;");
        } else {
            asm volatile("cp.async.wait_group 0;");
        }
        __syncthreads();
        int st = it & 1;
        #pragma unroll
        for (int ks = 0; ks < 2; ks++) {
            uint32_t ah[2][4], al[2][4];
            #pragma unroll
            for (int mi = 0; mi < 2; mi++) {
                int row = wm * 32 + mi * 16 + r;
                const __nv_bfloat16* ph = &sA[st][0][row][ks * 16 + t4 * 2];
                const __nv_bfloat16* pl = &sA[st][1][row][ks * 16 + t4 * 2];
                ah[mi][0] = *(const uint32_t*)ph;
                ah[mi][1] = *(const uint32_t*)(ph + 8 * 40);
                ah[mi][2] = *(const uint32_t*)(ph + 8);
                ah[mi][3] = *(const uint32_t*)(ph + 8 * 40 + 8);
                al[mi][0] = *(const uint32_t*)pl;
                al[mi][1] = *(const uint32_t*)(pl + 8 * 40);
                al[mi][2] = *(const uint32_t*)(pl + 8);
                al[mi][3] = *(const uint32_t*)(pl + 8 * 40 + 8);
            }
            #pragma unroll
            for (int nj = 0; nj < 2; nj++) {
                int n = wn * 16 + nj * 8 + r;
                const __nv_bfloat16* qh = &sB[st][0][n][ks * 16 + t4 * 2];
                const __nv_bfloat16* ql = &sB[st][1][n][ks * 16 + t4 * 2];
                uint32_t bh0 = *(const uint32_t*)qh, bh1 = *(const uint32_t*)(qh + 8);
                uint32_t bl0 = *(const uint32_t*)ql, bl1 = *(const uint32_t*)(ql + 8);
                #pragma unroll
                for (int mi = 0; mi < 2; mi++) {
                    MMA_BF16(acc[mi][nj], ah[mi], bh0, bh1);
                    MMA_BF16(acc[mi][nj], ah[mi], bl0, bl1);
                    MMA_BF16(acc[mi][nj], al[mi], bh0, bh1);
                }
            }
        }
        __syncthreads();
    }
    #pragma unroll
    for (int mi = 0; mi < 2; mi++) {
        #pragma unroll
        for (int nj = 0; nj < 2; nj++) {
            int col = n0 + wn * 16 + nj * 8 + t4 * 2;
            float b0 = bias[col], b1 = bias[col + 1];
            float rb20 = rb2 ? rb2[col] : 0.f;
            float rb21 = rb2 ? rb2[col + 1] : 0.f;
            float rb30 = rb3 ? rb3[col] : 0.f;
            float rb31 = rb3 ? rb3[col + 1] : 0.f;
            #pragma unroll
            for (int rr = 0; rr < 2; rr++) {
                int row = row0 + wm * 32 + mi * 16 + r + rr * 8;
                float v0 = acc[mi][nj][rr * 2 + 0] + b0;
                float v1 = acc[mi][nj][rr * 2 + 1] + b1;
                if (resid) {
                    float2 r2 = *(const float2*)(resid + (size_t)row * DD + col);
                    v0 += r2.x; v1 += r2.y;
                }
                *(float2*)(C + (size_t)row * DD + col) = make_float2(v0, v1);
                if (o2h) {
                    uint32_t h, l;
                    split2(v0 + rb20, v1 + rb21, h, l);
                    *(uint32_t*)((uint16_t*)o2h + (size_t)row * DD + col) = h;
                    *(uint32_t*)((uint16_t*)o2l + (size_t)row * DD + col) = l;
                }
                if (o3h) {
                    uint32_t h, l;
                    split2(v0 + rb30, v1 + rb31, h, l);
                    *(uint32_t*)((uint16_t*)o3h + (size_t)row * DD + col) = h;
                    *(uint32_t*)((uint16_t*)o3l + (size_t)row * DD + col) = l;
                }
            }
        }
    }
}

// Fused Q/K/V projections: one launch, z selects the problem.
// Q emits split(qh+vb) and split(qh+ub); K emits split(kh).
__global__ void __launch_bounds__(256, 2)
mma_qkv(const float* __restrict__ bq, const float* __restrict__ bk,
        const float* __restrict__ bv, const float* __restrict__ vb,
        const float* __restrict__ ub)
{
    __shared__ __align__(16) __nv_bfloat16 sA[2][2][64][40];
    __shared__ __align__(16) __nv_bfloat16 sB[2][2][64][40];
    int z = blockIdx.z;
    const __nv_bfloat16 *Ah, *Al, *Bh, *Bl;
    const float* bias;
    float* C;
    __nv_bfloat16 *o2h = nullptr, *o2l = nullptr, *o3h = nullptr, *o3l = nullptr;
    const float *rb2 = nullptr, *rb3 = nullptr;
    if (z == 0) {
        Ah = g_qi_h; Al = g_qi_l; Bh = g_wq_h; Bl = g_wq_l;
        bias = bq; C = g_qh;
        o2h = g_qv_h; o2l = g_qv_l; rb2 = vb;
        o3h = g_qu_h; o3l = g_qu_l; rb3 = ub;
    } else if (z == 1) {
        Ah = g_ki_h; Al = g_ki_l; Bh = g_wk_h; Bl = g_wk_l;
        bias = bk; C = g_kh;
        o2h = g_kh_h; o2l = g_kh_l; rb2 = nullptr;
    } else {
        Ah = g_vi_h; Al = g_vi_l; Bh = g_wv_h; Bl = g_wv_l;
        bias = bv; C = g_vh;
    }
    mma_body(Ah, Al, Bh, Bl, bias, nullptr, C, o2h, o2l, rb2, o3h, o3l, rb3,
             sA, sB, blockIdx.y * 64, blockIdx.x * 64);
}

// Generic single-GEMM wrapper (used for Wo projection)
__global__ void __launch_bounds__(256, 2)
mma2(const __nv_bfloat16* __restrict__ Ahg, const __nv_bfloat16* __restrict__ Alg,
     const __nv_bfloat16* __restrict__ Bhg, const __nv_bfloat16* __restrict__ Blg,
     const float* __restrict__ bias, const float* __restrict__ resid,
     float* __restrict__ C)
{
    __shared__ __align__(16) __nv_bfloat16 sA[2][2][64][40];
    __shared__ __align__(16) __nv_bfloat16 sB[2][2][64][40];
    mma_body(Ahg, Alg, Bhg, Blg, bias, resid, C, nullptr, nullptr, nullptr,
             nullptr, nullptr, nullptr, sA, sB, blockIdx.y * 64, blockIdx.x * 64);
}

// ===========================================================================
// t_mma: T[q][bh][e] (hi/lo) = (qh + v_bias) @ Wr_h^T, per head.
// ===========================================================================
__global__ void __launch_bounds__(256, 2)
t_mma()
{
    __shared__ __align__(16) __nv_bfloat16 tA[2][64][72];
    __shared__ __align__(16) __nv_bfloat16 tB[2][64][72];
    int tid = threadIdx.x, lane = tid & 31, wid = tid >> 5;
    int wm = wid >> 2, wn = wid & 3;
    int h = blockIdx.z, hoff = h * DHH;
    int m0 = blockIdx.y * 64, e0 = blockIdx.x * 64;
    int r = lane >> 2, t4 = lane & 3;
    float acc[2][2][4] = {};

    #pragma unroll
    for (int j = 0; j < 2; j++) {
        int c = tid + j * 256;
        int row = c >> 3, off = (c & 7) * 8;
        *(uint4*)&tA[0][row][off] = *(const uint4*)((const uint16_t*)g_qv_h + (size_t)(m0 + row) * DD + hoff + off);
        *(uint4*)&tA[1][row][off] = *(const uint4*)((const uint16_t*)g_qv_l + (size_t)(m0 + row) * DD + hoff + off);
        *(uint4*)&tB[0][row][off] = *(const uint4*)((const uint16_t*)g_wr_h + (size_t)(e0 + row) * DD + hoff + off);
        *(uint4*)&tB[1][row][off] = *(const uint4*)((const uint16_t*)g_wr_l + (size_t)(e0 + row) * DD + hoff + off);
    }
    __syncthreads();

    #pragma unroll
    for (int ks = 0; ks < 4; ks++) {
        uint32_t ah[2][4], al[2][4];
        #pragma unroll
        for (int mi = 0; mi < 2; mi++) {
            int row = wm * 32 + mi * 16 + r;
            const __nv_bfloat16* ph = &tA[0][row][ks * 16 + t4 * 2];
            const __nv_bfloat16* pl = &tA[1][row][ks * 16 + t4 * 2];
            ah[mi][0] = *(const uint32_t*)ph;
            ah[mi][1] = *(const uint32_t*)(ph + 8 * 72);
            ah[mi][2] = *(const uint32_t*)(ph + 8);
            ah[mi][3] = *(const uint32_t*)(ph + 8 * 72 + 8);
            al[mi][0] = *(const uint32_t*)pl;
            al[mi][1] = *(const uint32_t*)(pl + 8 * 72);
            al[mi][2] = *(const uint32_t*)(pl + 8);
            al[mi][3] = *(const uint32_t*)(pl + 8 * 72 + 8);
        }
        #pragma unroll
        for (int nj = 0; nj < 2; nj++) {
            int n = wn * 16 + nj * 8 + r;
            const __nv_bfloat16* qh = &tB[0][n][ks * 16 + t4 * 2];
            const __nv_bfloat16* ql = &tB[1][n][ks * 16 + t4 * 2];
            uint32_t bh0 = *(const uint32_t*)qh, bh1 = *(const uint32_t*)(qh + 8);
            uint32_t bl0 = *(const uint32_t*)ql, bl1 = *(const uint32_t*)(ql + 8);
            #pragma unroll
            for (int mi = 0; mi < 2; mi++) {
                MMA_BF16(acc[mi][nj], ah[mi], bh0, bh1);
                MMA_BF16(acc[mi][nj], ah[mi], bl0, bl1);
                MMA_BF16(acc[mi][nj], al[mi], bh0, bh1);
            }
        }
    }
    #pragma unroll
    for (int mi = 0; mi < 2; mi++) {
        #pragma unroll
        for (int nj = 0; nj < 2; nj++) {
            int e = e0 + wn * 16 + nj * 8 + t4 * 2;
            #pragma unroll
            for (int rr = 0; rr < 2; rr++) {
                int m = m0 + wm * 32 + mi * 16 + r + rr * 8;
                int q = m & 511, b = m >> 9;
                int bh = b * HH + h;
                uint32_t hh, ll;
                split2(acc[mi][nj][rr * 2 + 0], acc[mi][nj][rr * 2 + 1], hh, ll);
                size_t di = ((size_t)q * BHH + bh) * DD + e;
                *(uint32_t*)((uint16_t*)g_T_h + di) = hh;
                *(uint32_t*)((uint16_t*)g_T_l + di) = ll;
            }
        }
    }
}

// c[b,q,h] = sum_d (qh+v_bias)*br_h
__global__ void c_kernel(const float* __restrict__ vb, const float* __restrict__ br)
{
    int idx = blockIdx.x * blockDim.x + threadIdx.x;
    if (idx >= MR * HH) return;
    int h = idx & 7;
    int m = idx >> 3;
    int hoff = h * DHH;
    const float* qrow = g_qh + (size_t)m * DD + hoff;
    float s = 0.f;
    #pragma unroll 8
    for (int d = 0; d < DHH; d++)
        s += (qrow[d] + vb[hoff + d]) * br[hoff + d];
    g_c[idx] = s;
}

// ===========================================================================
// ac_mma: score[bh,q,k] = (qh+u).kh raw, t_mma-style smem-staged tiles.
// M=64(q) N=64(k) K=64(d). Skips fully-masked 64x64 tiles (verified exact).
// ===========================================================================
__global__ void __launch_bounds__(256, 2)
ac_mma(float* __restrict__ score)
{
    __shared__ __align__(16) __nv_bfloat16 tA[2][64][72];  // [hi/lo][q][d]
    __shared__ __align__(16) __nv_bfloat16 tB[2][64][72];  // [hi/lo][k][d]
    int bh = blockIdx.z, b = bh >> 3, h = bh & 7, hoff = h * DHH;
    int q0 = blockIdx.y * 64, k0 = blockIdx.x * 64;
    int tid = threadIdx.x, lane = tid & 31, wid = tid >> 5;
    int wm = wid >> 2, wn = wid & 3;
    int r = lane >> 2, t4 = lane & 3;

    {   // 64x64 full-tile mask check
        const uint4* mp = (const uint4*)(g_am + (size_t)(q0 + (tid >> 1)) * SKL + k0 + (tid & 1) * 32);
        uint4 m1 = mp[0], m2 = mp[1];
        int allm = bytes_all_nz(m1.x) & bytes_all_nz(m1.y) & bytes_all_nz(m1.z) & bytes_all_nz(m1.w)
                 & bytes_all_nz(m2.x) & bytes_all_nz(m2.y) & bytes_all_nz(m2.z) & bytes_all_nz(m2.w);
        if (__syncthreads_and(allm)) return;
    }

    float acc[2][2][4] = {};
    // stage tiles (t_mma pattern): A rows = q0.., B rows = k0.., cols = hoff..+64
    #pragma unroll
    for (int j = 0; j < 2; j++) {
        int c = tid + j * 256;
        int row = c >> 3, off = (c & 7) * 8;
        *(uint4*)&tA[0][row][off] = *(const uint4*)((const uint16_t*)g_qu_h + (size_t)(b * SQL + q0 + row) * DD + hoff + off);
        *(uint4*)&tA[1][row][off] = *(const uint4*)((const uint16_t*)g_qu_l + (size_t)(b * SQL + q0 + row) * DD + hoff + off);
        *(uint4*)&tB[0][row][off] = *(const uint4*)((const uint16_t*)g_kh_h + (size_t)(b * SQL + k0 + row) * DD + hoff + off);
        *(uint4*)&tB[1][row][off] = *(const uint4*)((const uint16_t*)g_kh_l + (size_t)(b * SQL + k0 + row) * DD + hoff + off);
    }
    __syncthreads();

    #pragma unroll
    for (int ks = 0; ks < 4; ks++) {
        uint32_t ah[2][4], al[2][4];
        #pragma unroll
        for (int mi = 0; mi < 2; mi++) {
            int row = wm * 32 + mi * 16 + r;
            const __nv_bfloat16* ph = &tA[0][row][ks * 16 + t4 * 2];
            const __nv_bfloat16* pl = &tA[1][row][ks * 16 + t4 * 2];
            ah[mi][0] = *(const uint32_t*)ph;
            ah[mi][1] = *(const uint32_t*)(ph + 8 * 72);
            ah[mi][2] = *(const uint32_t*)(ph + 8);
            ah[mi][3] = *(const uint32_t*)(ph + 8 * 72 + 8);
            al[mi][0] = *(const uint32_t*)pl;
            al[mi][1] = *(const uint32_t*)(pl + 8 * 72);
            al[mi][2] = *(const uint32_t*)(pl + 8);
            al[mi][3] = *(const uint32_t*)(pl + 8 * 72 + 8);
        }
        #pragma unroll
        for (int nj = 0; nj < 2; nj++) {
            int n = wn * 16 + nj * 8 + r;
            const __nv_bfloat16* qh = &tB[0][n][ks * 16 + t4 * 2];
            const __nv_bfloat16* ql = &tB[1][n][ks * 16 + t4 * 2];
            uint32_t bh0 = *(const uint32_t*)qh, bh1 = *(const uint32_t*)(qh + 8);
            uint32_t bl0 = *(const uint32_t*)ql, bl1 = *(const uint32_t*)(ql + 8);
            #pragma unroll
            for (int mi = 0; mi < 2; mi++) {
                MMA_BF16(acc[mi][nj], ah[mi], bh0, bh1);
                MMA_BF16(acc[mi][nj], ah[mi], bl0, bl1);
                MMA_BF16(acc[mi][nj], al[mi], bh0, bh1);
            }
        }
    }
    // epilogue: raw scores
    #pragma unroll
    for (int mi = 0; mi < 2; mi++) {
        #pragma unroll
        for (int nj = 0; nj < 2; nj++) {
            int k = k0 + wn * 16 + nj * 8 + t4 * 2;
            #pragma unroll
            for (int rr = 0; rr < 2; rr++) {
                int q = q0 + wm * 32 + mi * 16 + r + rr * 8;
                *(float2*)(score + ((size_t)bh * SQL + q) * SKL + k) =
                    make_float2(acc[mi][nj][rr * 2 + 0], acc[mi][nj][rr * 2 + 1]);
            }
        }
    }
}

// ===========================================================================
// bd_sm_mma: score -> attn_weights fused (bd + masked softmax in place).
// ===========================================================================
__global__ void __launch_bounds__(256)
bd_sm_mma(const float* __restrict__ pos_emb, float* __restrict__ score)
{
    __shared__ __align__(16) __nv_bfloat16 sT[2][32][136];
    __shared__ unsigned char cmask[BB][SKL];
    __shared__ float smax[BHH][9], ssum[BHH][9];
    int q = blockIdx.x;
    int tid = threadIdx.x, lane = tid & 31, wn = tid >> 5;
    int r = lane >> 2, t4 = lane & 3;

    #pragma unroll
    for (int j = 0; j < 8; j++) {
        int i = tid + j * 256;
        int b = i >> 9, kk = i & 511;
        cmask[b][kk] = g_am[(size_t)q * SKL + kk] | g_kpm[(size_t)b * SKL + kk];
    }

    int k_a = wn * 64 + lane * 2;
    unsigned char ma = g_am[(size_t)q * SKL + k_a];
    unsigned char mb = g_am[(size_t)q * SKL + k_a + 1];
    int act = __ballot_sync(0xffffffffu, (ma == 0) || (mb == 0)) != 0;

    float acc[2][8][4] = {};

    #pragma unroll 1
    for (int ec = 0; ec < 4; ec++) {
        #pragma unroll
        for (int j = 0; j < 2; j++) {
            int c = tid + j * 256;
            int row = c >> 4, off = (c & 15) * 8;
            size_t gi = ((size_t)q * BHH + row) * DD + ec * 128 + off;
            *(uint4*)&sT[0][row][off] = *(const uint4*)((const uint16_t*)g_T_h + gi);
            *(uint4*)&sT[1][row][off] = *(const uint4*)((const uint16_t*)g_T_l + gi);
        }
        __syncthreads();
        if (act) {
            #pragma unroll 1
            for (int ks = 0; ks < 8; ks++) {
                uint32_t ah[2][4], al[2][4];
                #pragma unroll
                for (int mi = 0; mi < 2; mi++) {
                    int row = mi * 16 + r;
                    const __nv_bfloat16* ph = &sT[0][row][ks * 16 + t4 * 2];
                    const __nv_bfloat16* pl = &sT[1][row][ks * 16 + t4 * 2];
                    ah[mi][0] = *(const uint32_t*)ph;
                    ah[mi][1] = *(const uint32_t*)(ph + 8 * 136);
                    ah[mi][2] = *(const uint32_t*)(ph + 8);
                    ah[mi][3] = *(const uint32_t*)(ph + 8 * 136 + 8);
                    al[mi][0] = *(const uint32_t*)pl;
                    al[mi][1] = *(const uint32_t*)(pl + 8 * 136);
                    al[mi][2] = *(const uint32_t*)(pl + 8);
                    al[mi][3] = *(const uint32_t*)(pl + 8 * 136 + 8);
                }
                int eg = ec * 128 + ks * 16 + t4 * 2;
                #pragma unroll
                for (int nj = 0; nj < 8; nj++) {
                    int n = wn * 64 + nj * 8 + r;
                    const float* pp = pos_emb + ((size_t)q * SKL + n) * DD + eg;
                    float2 p0 = *(const float2*)pp;
                    float2 p1 = *(const float2*)(pp + 8);
                    uint32_t bh0, bl0, bh1, bl1;
                    split2(p0.x, p0.y, bh0, bl0);
                    split2(p1.x, p1.y, bh1, bl1);
                    #pragma unroll
                    for (int mi = 0; mi < 2; mi++) {
                        MMA_BF16(acc[mi][nj], ah[mi], bh0, bh1);
                        MMA_BF16(acc[mi][nj], ah[mi], bl0, bl1);
                        MMA_BF16(acc[mi][nj], al[mi], bh0, bh1);
                    }
                }
            }
        }
        __syncthreads();
    }

    float rmax[2][2] = {{-INFINITY, -INFINITY}, {-INFINITY, -INFINITY}};
    #pragma unroll
    for (int mi = 0; mi < 2; mi++) {
        #pragma unroll
        for (int rr = 0; rr < 2; rr++) {
            int bh = mi * 16 + r + rr * 8;
            int b = bh >> 3, h = bh & 7;
            float cc = g_c[((size_t)b * SQL + q) * HH + h];
            const float* srow = score + ((size_t)bh * SQL + q) * SKL;
            #pragma unroll
            for (int nj = 0; nj < 8; nj++) {
                int k = wn * 64 + nj * 8 + t4 * 2;
                float2 s2 = *(const float2*)(srow + k);
                float v0 = (s2.x + acc[mi][nj][rr * 2 + 0] + cc) * 0.125f;
                float v1 = (s2.y + acc[mi][nj][rr * 2 + 1] + cc) * 0.125f;
                if (cmask[b][k])     v0 = -INFINITY;
                if (cmask[b][k + 1]) v1 = -INFINITY;
                acc[mi][nj][rr * 2 + 0] = v0;
                acc[mi][nj][rr * 2 + 1] = v1;
                rmax[mi][rr] = fmaxf(rmax[mi][rr], fmaxf(v0, v1));
            }
        }
    }
    #pragma unroll
    for (int mi = 0; mi < 2; mi++)
        #pragma unroll
        for (int rr = 0; rr < 2; rr++) {
            rmax[mi][rr] = fmaxf(rmax[mi][rr], __shfl_xor_sync(0xffffffffu, rmax[mi][rr], 1));
            rmax[mi][rr] = fmaxf(rmax[mi][rr], __shfl_xor_sync(0xffffffffu, rmax[mi][rr], 2));
        }
    if (t4 == 0) {
        #pragma unroll
        for (int mi = 0; mi < 2; mi++)
            #pragma unroll
            for (int rr = 0; rr < 2; rr++)
                smax[mi * 16 + r + rr * 8][wn] = rmax[mi][rr];
    }
    __syncthreads();

    float rsum[2][2];
    #pragma unroll
    for (int mi = 0; mi < 2; mi++) {
        #pragma unroll
        for (int rr = 0; rr < 2; rr++) {
            int bh = mi * 16 + r + rr * 8;
            float gm = smax[bh][0];
            #pragma unroll
            for (int w = 1; w < 8; w++) gm = fmaxf(gm, smax[bh][w]);
            float sum = 0.f;
            #pragma unroll
            for (int nj = 0; nj < 8; nj++) {
                #pragma unroll
                for (int c = 0; c < 2; c++) {
                    float v = acc[mi][nj][rr * 2 + c];
                    float e = (v == -INFINITY) ? 0.f : __expf(v - gm);
                    acc[mi][nj][rr * 2 + c] = e;
                    sum += e;
                }
            }
            sum += __shfl_xor_sync(0xffffffffu, sum, 1);
            sum += __shfl_xor_sync(0xffffffffu, sum, 2);
            rsum[mi][rr] = sum;
        }
    }
    if (t4 == 0) {
        #pragma unroll
        for (int mi = 0; mi < 2; mi++)
            #pragma unroll
            for (int rr = 0; rr < 2; rr++)
                ssum[mi * 16 + r + rr * 8][wn] = rsum[mi][rr];
    }
    __syncthreads();

    #pragma unroll
    for (int mi = 0; mi < 2; mi++) {
        #pragma unroll
        for (int rr = 0; rr < 2; rr++) {
            int bh = mi * 16 + r + rr * 8;
            float tot = 0.f;
            #pragma unroll
            for (int w = 0; w < 8; w++) tot += ssum[bh][w];
            float inv = (tot > 0.f) ? 1.f / tot : 0.f;
            float* srow = score + ((size_t)bh * SQL + q) * SKL;
            #pragma unroll
            for (int nj = 0; nj < 8; nj++) {
                int k = wn * 64 + nj * 8 + t4 * 2;
                *(float2*)(srow + k) = make_float2(acc[mi][nj][rr * 2 + 0] * inv,
                                                   acc[mi][nj][rr * 2 + 1] * inv);
            }
        }
    }
}

// ===========================================================================
// av (scalar R2) + fused hi/lo split of the output
// ===========================================================================
__global__ void av_kernel(const float* __restrict__ score)
{
    __shared__ float As[16][64];
    __shared__ float Ws[16][64];
    int bh = blockIdx.y, b = bh >> 3, h = bh & 7, hoff = h * DHH;
    int q0 = blockIdx.x * 64;
    int tid = threadIdx.x;
    int tx = tid & 15, ty = tid >> 4;
    float acc[4][4] = {};

    int la_q = tid >> 2, la_k = (tid & 3) * 4;
    int lw_k = tid >> 4, lw_d = (tid & 15) * 4;

    for (int k0 = 0; k0 < SKL; k0 += 16) {
        const unsigned char* rp = g_am + (size_t)(q0 + (tid >> 2)) * SKL + k0 + (tid & 3) * 4;
        int allm = (rp[0] && rp[1] && rp[2] && rp[3]);
        if (__syncthreads_and(allm)) continue;

        float4 a4 = *(const float4*)(score + ((size_t)bh * SQL + q0 + la_q) * SKL + k0 + la_k);
        As[la_k + 0][la_q] = a4.x;
        As[la_k + 1][la_q] = a4.y;
        As[la_k + 2][la_q] = a4.z;
        As[la_k + 3][la_q] = a4.w;
        float4 w4 = *(const float4*)(g_vh + ((size_t)b * SQL + k0 + lw_k) * DD + hoff + lw_d);
        *(float4*)&Ws[lw_k][lw_d] = w4;
        __syncthreads();
        #pragma unroll
        for (int kk = 0; kk < 16; kk++) {
            float a[4], bv[4];
            #pragma unroll
            for (int i = 0; i < 4; i++) a[i] = As[kk][ty * 4 + i];
            #pragma unroll
            for (int j = 0; j < 4; j++) bv[j] = Ws[kk][tx * 4 + j];
            #pragma unroll
            for (int i = 0; i < 4; i++)
                #pragma unroll
                for (int j = 0; j < 4; j++)
                    acc[i][j] += a[i] * bv[j];
        }
        __syncthreads();
    }
    #pragma unroll
    for (int i = 0; i < 4; i++) {
        size_t oi = ((size_t)b * SQL + q0 + ty * 4 + i) * DD + hoff + tx * 4;
        float4 sv = {acc[i][0], acc[i][1], acc[i][2], acc[i][3]};
        *(float4*)(g_att + oi) = sv;
        uint32_t h0, l0, h1, l1;
        split2(sv.x, sv.y, h0, l0);
        split2(sv.z, sv.w, h1, l1);
        *(uint2*)((uint16_t*)g_at_h + oi) = make_uint2(h0, h1);
        *(uint2*)((uint16_t*)g_at_l + oi) = make_uint2(l0, l1);
    }
}

// ===========================================================================
__global__ void ln_kernel(const float* __restrict__ X, const float* __restrict__ gamma,
                          const float* __restrict__ beta, float* __restrict__ out)
{
    int row = blockIdx.x;
    int tid = threadIdx.x;  // 256
    const float* x = X + (size_t)row * DD;
    float2 v = *(const float2*)(x + tid * 2);
    float s = v.x + v.y;
    float s2 = v.x * v.x + v.y * v.y;
    #pragma unroll
    for (int off = 16; off; off >>= 1) {
        s  += __shfl_xor_sync(0xffffffffu, s, off);
        s2 += __shfl_xor_sync(0xffffffffu, s2, off);
    }
    __shared__ float rs[8], rs2[8];
    int wid = tid >> 5, lane = tid & 31;
    if (lane == 0) { rs[wid] = s; rs2[wid] = s2; }
    __syncthreads();
    s = 0.f; s2 = 0.f;
    #pragma unroll
    for (int i = 0; i < 8; i++) { s += rs[i]; s2 += rs2[i]; }
    float mean = s * (1.f / DD);
    float var = s2 * (1.f / DD) - mean * mean;
    float inv = rsqrtf(var + 1e-5f);
    float2 g2 = *(const float2*)(gamma + tid * 2);
    float2 b2 = *(const float2*)(beta + tid * 2);
    float2 o;
    o.x = (v.x - mean) * inv * g2.x + b2.x;
    o.y = (v.y - mean) * inv * g2.y + b2.y;
    *(float2*)(out + (size_t)row * DD + tid * 2) = o;
}

// ===========================================================================
extern "C" void kernel_launch(void* const* d_in, const int* in_sizes, int n_in,
                              void* d_out, int out_size)
{
    const float* q  = (const float*)d_in[0];
    const float* k  = (const float*)d_in[1];
    const float* v  = (const float*)d_in[2];
    const float* pe = (const float*)d_in[3];
    const unsigned char* kpm = (const unsigned char*)d_in[4];
    const unsigned char* am  = (const unsigned char*)d_in[5];
    const float* Wq = (const float*)d_in[6];
    const float* bq = (const float*)d_in[7];
    const float* Wk = (const float*)d_in[8];
    const float* bk = (const float*)d_in[9];
    const float* Wv = (const float*)d_in[10];
    const float* bv = (const float*)d_in[11];
    const float* Wo = (const float*)d_in[12];
    const float* bo = (const float*)d_in[13];
    const float* Wr = (const float*)d_in[14];
    const float* br = (const float*)d_in[15];
    const float* ub = (const float*)d_in[16];
    const float* vb = (const float*)d_in[17];
    const float* lg = (const float*)d_in[18];
    const float* lb = (const float*)d_in[19];

    float* normed = (float*)d_out;
    float* attnw  = normed + (size_t)BB * SQL * DD;

    float *o2;
    cudaGetSymbolAddress((void**)&o2,  g_o2);
    __nv_bfloat16 *woh, *wol, *ath, *atl;
    cudaGetSymbolAddress((void**)&woh, g_wo_h); cudaGetSymbolAddress((void**)&wol, g_wo_l);
    cudaGetSymbolAddress((void**)&ath, g_at_h); cudaGetSymbolAddress((void**)&atl, g_at_l);

    // mask normalization
    mask_detect<<<1, 1024>>>(am);
    mask_convert<<<64, 256>>>(am, kpm);

    // operand conversions
    conv_inputs<<<dim3(MR * DD / 4 / 256, 1, 3), 256>>>(q, k, v);
    conv_w<<<dim3(16, 16, 4), dim3(32, 32)>>>(Wq, Wk, Wv, Wo);
    conv_wr<<<DD * DD / 4 / 256, 256>>>(Wr);

    // fused Q/K/V projections; Q emits split(qh+vb) + split(qh+ub), K emits split(kh)
    mma_qkv<<<dim3(8, 32, 3), 256>>>(bq, bk, bv, vb, ub);

    c_kernel<<<(MR * HH + 255) / 256, 256>>>(vb, br);
    t_mma<<<dim3(8, 32, 8), 256>>>();

    ac_mma<<<dim3(8, 8, 32), 256>>>(attnw);
    bd_sm_mma<<<512, 256>>>(pe, attnw);

    av_kernel<<<dim3(8, 32), 256>>>(attnw);

    mma2<<<dim3(8, 32), 256>>>(ath, atl, woh, wol, bo, q, o2);
    ln_kernel<<<MR, 256>>>(o2, lg, lb, normed);
}

// round 17
// speedup vs baseline: 1.2262x; 1.0752x over previous
#include <cuda_runtime.h>
#include <cuda_bf16.h>
#include <math.h>
#include <stdint.h>

#define BB   4
#define SQL  512
#define SKL  512
#define DD   512
#define HH   8
#define DHH  64
#define BHH  32
#define MR   2048

// ---------------- f32 scratch ----------------
__device__ float g_qh[MR * DD];
__device__ float g_kh[MR * DD];
__device__ float g_vh[MR * DD];
__device__ float g_c [MR * HH];
__device__ float g_att[MR * DD];
__device__ float g_o2 [MR * DD];

// ---------------- bf16 hi/lo scratch ----------------
__device__ __nv_bfloat16 g_qi_h[MR * DD], g_qi_l[MR * DD];
__device__ __nv_bfloat16 g_ki_h[MR * DD], g_ki_l[MR * DD];
__device__ __nv_bfloat16 g_vi_h[MR * DD], g_vi_l[MR * DD];
__device__ __nv_bfloat16 g_wq_h[DD * DD], g_wq_l[DD * DD];
__device__ __nv_bfloat16 g_wk_h[DD * DD], g_wk_l[DD * DD];
__device__ __nv_bfloat16 g_wv_h[DD * DD], g_wv_l[DD * DD];
__device__ __nv_bfloat16 g_wo_h[DD * DD], g_wo_l[DD * DD];
__device__ __nv_bfloat16 g_wr_h[DD * DD], g_wr_l[DD * DD];
__device__ __nv_bfloat16 g_qv_h[MR * DD], g_qv_l[MR * DD];   // split(qh + v_bias)
__device__ __nv_bfloat16 g_qu_h[MR * DD], g_qu_l[MR * DD];   // split(qh + u_bias)
__device__ __nv_bfloat16 g_kh_h[MR * DD], g_kh_l[MR * DD];   // split(kh)
__device__ __nv_bfloat16 g_T_h[SQL * BHH * DD], g_T_l[SQL * BHH * DD]; // [q][bh][e]
__device__ __nv_bfloat16 g_at_h[MR * DD], g_at_l[MR * DD];

__device__ unsigned char g_am [SQL * SKL];
__device__ unsigned char g_kpm[BB * SKL];
__device__ unsigned int g_or1, g_or23;

// ===========================================================================
// helpers
// ===========================================================================
__device__ __forceinline__ uint32_t smem_u32(const void* p) {
    uint32_t a;
    asm("{ .reg .u64 t; cvta.to.shared.u64 t, %1; cvt.u32.u64 %0, t; }" : "=r"(a) : "l"(p));
    return a;
}
__device__ __forceinline__ uint32_t pack_bf16x2(float x, float y) {
    uint32_t r;
    asm("cvt.rn.bf16x2.f32 %0, %1, %2;" : "=r"(r) : "f"(y), "f"(x));
    return r;
}
__device__ __forceinline__ float bf_lo(uint32_t w) { return __uint_as_float(w << 16); }
__device__ __forceinline__ float bf_hi(uint32_t w) { return __uint_as_float(w & 0xffff0000u); }

#define MMA_BF16(c, a, b0, b1) \
    asm volatile("mma.sync.aligned.m16n8k16.row.col.f32.bf16.bf16.f32 " \
        "{%0,%1,%2,%3}, {%4,%5,%6,%7}, {%8,%9}, {%0,%1,%2,%3};" \
        : "+f"((c)[0]), "+f"((c)[1]), "+f"((c)[2]), "+f"((c)[3]) \
        : "r"((a)[0]), "r"((a)[1]), "r"((a)[2]), "r"((a)[3]), "r"(b0), "r"(b1))

__device__ __forceinline__ void cpa16(const void* s, const void* g) {
    asm volatile("cp.async.ca.shared.global [%0], [%1], 16;" :: "r"(smem_u32(s)), "l"(g));
}
__device__ __forceinline__ void split2(float x, float y, uint32_t& h, uint32_t& l) {
    h = pack_bf16x2(x, y);
    l = pack_bf16x2(x - bf_lo(h), y - bf_hi(h));
}
__device__ __forceinline__ int bytes_all_nz(unsigned int v)
{
    return (((v - 0x01010101u) & ~v) & 0x80808080u) == 0u;
}

// ===========================================================================
// Conversion kernels
// ===========================================================================
__global__ void conv_inputs(const float* __restrict__ q, const float* __restrict__ k,
                            const float* __restrict__ v)
{
    const float* src = (blockIdx.z == 0) ? q : (blockIdx.z == 1) ? k : v;
    __nv_bfloat16* dh = (blockIdx.z == 0) ? g_qi_h : (blockIdx.z == 1) ? g_ki_h : g_vi_h;
    __nv_bfloat16* dl = (blockIdx.z == 0) ? g_qi_l : (blockIdx.z == 1) ? g_ki_l : g_vi_l;
    int idx = (blockIdx.x * blockDim.x + threadIdx.x) * 4;
    if (idx >= MR * DD) return;
    float4 a = *(const float4*)(src + idx);
    uint32_t h0, l0, h1, l1;
    split2(a.x, a.y, h0, l0);
    split2(a.z, a.w, h1, l1);
    *(uint2*)((uint16_t*)dh + idx) = make_uint2(h0, h1);
    *(uint2*)((uint16_t*)dl + idx) = make_uint2(l0, l1);
}

// W[k][n] -> out[n][k] hi/lo (transpose)
__global__ void conv_w(const float* __restrict__ Wq, const float* __restrict__ Wk,
                       const float* __restrict__ Wv, const float* __restrict__ Wo)
{
    __shared__ float s[32][33];
    const float* W = (blockIdx.z == 0) ? Wq : (blockIdx.z == 1) ? Wk : (blockIdx.z == 2) ? Wv : Wo;
    __nv_bfloat16* dh = (blockIdx.z == 0) ? g_wq_h : (blockIdx.z == 1) ? g_wk_h : (blockIdx.z == 2) ? g_wv_h : g_wo_h;
    __nv_bfloat16* dl = (blockIdx.z == 0) ? g_wq_l : (blockIdx.z == 1) ? g_wk_l : (blockIdx.z == 2) ? g_wv_l : g_wo_l;
    int k0 = blockIdx.y * 32, n0 = blockIdx.x * 32;
    int tx = threadIdx.x, ty = threadIdx.y;
    s[ty][tx] = W[(size_t)(k0 + ty) * DD + n0 + tx];
    __syncthreads();
    float vv = s[tx][ty];
    __nv_bfloat16 hb = __float2bfloat16_rn(vv);
    __nv_bfloat16 lb = __float2bfloat16_rn(vv - __bfloat162float(hb));
    dh[(size_t)(n0 + ty) * DD + k0 + tx] = hb;
    dl[(size_t)(n0 + ty) * DD + k0 + tx] = lb;
}

__global__ void conv_wr(const float* __restrict__ Wr)
{
    int idx = (blockIdx.x * blockDim.x + threadIdx.x) * 4;
    if (idx >= DD * DD) return;
    float4 a = *(const float4*)(Wr + idx);
    uint32_t h0, l0, h1, l1;
    split2(a.x, a.y, h0, l0);
    split2(a.z, a.w, h1, l1);
    *(uint2*)((uint16_t*)g_wr_h + idx) = make_uint2(h0, h1);
    *(uint2*)((uint16_t*)g_wr_l + idx) = make_uint2(l0, l1);
}

// ===========================================================================
// Mask normalization
// ===========================================================================
__global__ void mask_detect(const unsigned char* __restrict__ am)
{
    unsigned int or1 = 0, or23 = 0;
    const uint4* p = (const uint4*)am;
    int n16 = SQL * SKL / 16;
    for (int i = threadIdx.x; i < n16; i += blockDim.x) {
        uint4 v = p[i];
        or1  |= (v.x & 0x0000FF00u) | (v.y & 0x0000FF00u) | (v.z & 0x0000FF00u) | (v.w & 0x0000FF00u);
        or23 |= (v.x & 0xFFFF0000u) | (v.y & 0xFFFF0000u) | (v.z & 0xFFFF0000u) | (v.w & 0xFFFF0000u);
    }
    int a1  = __syncthreads_or((int)(or1 != 0));
    int a23 = __syncthreads_or((int)(or23 != 0));
    if (threadIdx.x == 0) { g_or1 = a1 ? 1u : 0u; g_or23 = a23 ? 1u : 0u; }
}

__global__ void mask_convert(const unsigned char* __restrict__ am,
                             const unsigned char* __restrict__ kpm)
{
    int mode = g_or1 ? 1 : (g_or23 ? 2 : 0);
    int stride = gridDim.x * blockDim.x;
    int tid = blockIdx.x * blockDim.x + threadIdx.x;
    for (int i = tid; i < SQL * SKL; i += stride) {
        unsigned char v;
        if (mode == 1)      v = (am[i] != 0);
        else if (mode == 2) v = (((const float*)am)[i] != 0.0f);
        else                v = (((const int*)am)[i] != 0);
        g_am[i] = v;
    }
    for (int i = tid; i < BB * SKL; i += stride) {
        unsigned char v;
        if (mode == 1)      v = (kpm[i] != 0);
        else if (mode == 2) v = (((const float*)kpm)[i] != 0.0f);
        else                v = (((const int*)kpm)[i] != 0);
        g_kpm[i] = v;
    }
}

// ===========================================================================
// Shared mma projection body (BM=64 BN=64 BK=32, cp.async double buffer)
// Optional dual split outputs: o2 = split(C+rb2), o3 = split(C+rb3)
// ===========================================================================
__device__ __forceinline__ void mma_body(
    const __nv_bfloat16* __restrict__ Ahg, const __nv_bfloat16* __restrict__ Alg,
    const __nv_bfloat16* __restrict__ Bhg, const __nv_bfloat16* __restrict__ Blg,
    const float* __restrict__ bias, const float* __restrict__ resid,
    float* __restrict__ C,
    __nv_bfloat16* __restrict__ o2h, __nv_bfloat16* __restrict__ o2l,
    const float* __restrict__ rb2,
    __nv_bfloat16* __restrict__ o3h, __nv_bfloat16* __restrict__ o3l,
    const float* __restrict__ rb3,
    __nv_bfloat16 (*sA)[2][64][40], __nv_bfloat16 (*sB)[2][64][40],
    int row0, int n0)
{
    int tid = threadIdx.x, lane = tid & 31, wid = tid >> 5;
    int wm = wid >> 2, wn = wid & 3;
    int r = lane >> 2, t4 = lane & 3;
    float acc[2][2][4] = {};
    int lrow = tid >> 2, lco = (tid & 3) * 8;

    {
        int k0 = 0;
        cpa16(&sA[0][0][lrow][lco], (const uint16_t*)Ahg + (size_t)(row0 + lrow) * DD + k0 + lco);
        cpa16(&sA[0][1][lrow][lco], (const uint16_t*)Alg + (size_t)(row0 + lrow) * DD + k0 + lco);
        cpa16(&sB[0][0][lrow][lco], (const uint16_t*)Bhg + (size_t)(n0 + lrow) * DD + k0 + lco);
        cpa16(&sB[0][1][lrow][lco], (const uint16_t*)Blg + (size_t)(n0 + lrow) * DD + k0 + lco);
        asm volatile("cp.async.commit_group;");
    }
    #pragma unroll 1
    for (int it = 0; it < 16; it++) {
        if (it + 1 < 16) {
            int st = (it + 1) & 1, k0 = (it + 1) * 32;
            cpa16(&sA[st][0][lrow][lco], (const uint16_t*)Ahg + (size_t)(row0 + lrow) * DD + k0 + lco);
            cpa16(&sA[st][1][lrow][lco], (const uint16_t*)Alg + (size_t)(row0 + lrow) * DD + k0 + lco);
            cpa16(&sB[st][0][lrow][lco], (const uint16_t*)Bhg + (size_t)(n0 + lrow) * DD + k0 + lco);
            cpa16(&sB[st][1][lrow][lco], (const uint16_t*)Blg + (size_t)(n0 + lrow) * DD + k0 + lco);
            asm volatile("cp.async.commit_group;");
            asm volatile("cp.async.wait_group 1;");
        } else {
            asm volatile("cp.async.wait_group 0;");
        }
        __syncthreads();
        int st = it & 1;
        #pragma unroll
        for (int ks = 0; ks < 2; ks++) {
            uint32_t ah[2][4], al[2][4];
            #pragma unroll
            for (int mi = 0; mi < 2; mi++) {
                int row = wm * 32 + mi * 16 + r;
                const __nv_bfloat16* ph = &sA[st][0][row][ks * 16 + t4 * 2];
                const __nv_bfloat16* pl = &sA[st][1][row][ks * 16 + t4 * 2];
                ah[mi][0] = *(const uint32_t*)ph;
                ah[mi][1] = *(const uint32_t*)(ph + 8 * 40);
                ah[mi][2] = *(const uint32_t*)(ph + 8);
                ah[mi][3] = *(const uint32_t*)(ph + 8 * 40 + 8);
                al[mi][0] = *(const uint32_t*)pl;
                al[mi][1] = *(const uint32_t*)(pl + 8 * 40);
                al[mi][2] = *(const uint32_t*)(pl + 8);
                al[mi][3] = *(const uint32_t*)(pl + 8 * 40 + 8);
            }
            #pragma unroll
            for (int nj = 0; nj < 2; nj++) {
                int n = wn * 16 + nj * 8 + r;
                const __nv_bfloat16* qh = &sB[st][0][n][ks * 16 + t4 * 2];
                const __nv_bfloat16* ql = &sB[st][1][n][ks * 16 + t4 * 2];
                uint32_t bh0 = *(const uint32_t*)qh, bh1 = *(const uint32_t*)(qh + 8);
                uint32_t bl0 = *(const uint32_t*)ql, bl1 = *(const uint32_t*)(ql + 8);
                #pragma unroll
                for (int mi = 0; mi < 2; mi++) {
                    MMA_BF16(acc[mi][nj], ah[mi], bh0, bh1);
                    MMA_BF16(acc[mi][nj], ah[mi], bl0, bl1);
                    MMA_BF16(acc[mi][nj], al[mi], bh0, bh1);
                }
            }
        }
        __syncthreads();
    }
    #pragma unroll
    for (int mi = 0; mi < 2; mi++) {
        #pragma unroll
        for (int nj = 0; nj < 2; nj++) {
            int col = n0 + wn * 16 + nj * 8 + t4 * 2;
            float b0 = bias[col], b1 = bias[col + 1];
            float rb20 = rb2 ? rb2[col] : 0.f;
            float rb21 = rb2 ? rb2[col + 1] : 0.f;
            float rb30 = rb3 ? rb3[col] : 0.f;
            float rb31 = rb3 ? rb3[col + 1] : 0.f;
            #pragma unroll
            for (int rr = 0; rr < 2; rr++) {
                int row = row0 + wm * 32 + mi * 16 + r + rr * 8;
                float v0 = acc[mi][nj][rr * 2 + 0] + b0;
                float v1 = acc[mi][nj][rr * 2 + 1] + b1;
                if (resid) {
                    float2 r2 = *(const float2*)(resid + (size_t)row * DD + col);
                    v0 += r2.x; v1 += r2.y;
                }
                *(float2*)(C + (size_t)row * DD + col) = make_float2(v0, v1);
                if (o2h) {
                    uint32_t h, l;
                    split2(v0 + rb20, v1 + rb21, h, l);
                    *(uint32_t*)((uint16_t*)o2h + (size_t)row * DD + col) = h;
                    *(uint32_t*)((uint16_t*)o2l + (size_t)row * DD + col) = l;
                }
                if (o3h) {
                    uint32_t h, l;
                    split2(v0 + rb30, v1 + rb31, h, l);
                    *(uint32_t*)((uint16_t*)o3h + (size_t)row * DD + col) = h;
                    *(uint32_t*)((uint16_t*)o3l + (size_t)row * DD + col) = l;
                }
            }
        }
    }
}

// Fused Q/K/V projections: one launch, z selects the problem.
__global__ void __launch_bounds__(256, 2)
mma_qkv(const float* __restrict__ bq, const float* __restrict__ bk,
        const float* __restrict__ bv, const float* __restrict__ vb,
        const float* __restrict__ ub)
{
    __shared__ __align__(16) __nv_bfloat16 sA[2][2][64][40];
    __shared__ __align__(16) __nv_bfloat16 sB[2][2][64][40];
    int z = blockIdx.z;
    const __nv_bfloat16 *Ah, *Al, *Bh, *Bl;
    const float* bias;
    float* C;
    __nv_bfloat16 *o2h = nullptr, *o2l = nullptr, *o3h = nullptr, *o3l = nullptr;
    const float *rb2 = nullptr, *rb3 = nullptr;
    if (z == 0) {
        Ah = g_qi_h; Al = g_qi_l; Bh = g_wq_h; Bl = g_wq_l;
        bias = bq; C = g_qh;
        o2h = g_qv_h; o2l = g_qv_l; rb2 = vb;
        o3h = g_qu_h; o3l = g_qu_l; rb3 = ub;
    } else if (z == 1) {
        Ah = g_ki_h; Al = g_ki_l; Bh = g_wk_h; Bl = g_wk_l;
        bias = bk; C = g_kh;
        o2h = g_kh_h; o2l = g_kh_l; rb2 = nullptr;
    } else {
        Ah = g_vi_h; Al = g_vi_l; Bh = g_wv_h; Bl = g_wv_l;
        bias = bv; C = g_vh;
    }
    mma_body(Ah, Al, Bh, Bl, bias, nullptr, C, o2h, o2l, rb2, o3h, o3l, rb3,
             sA, sB, blockIdx.y * 64, blockIdx.x * 64);
}

// Generic single-GEMM wrapper (used for Wo projection)
__global__ void __launch_bounds__(256, 2)
mma2(const __nv_bfloat16* __restrict__ Ahg, const __nv_bfloat16* __restrict__ Alg,
     const __nv_bfloat16* __restrict__ Bhg, const __nv_bfloat16* __restrict__ Blg,
     const float* __restrict__ bias, const float* __restrict__ resid,
     float* __restrict__ C)
{
    __shared__ __align__(16) __nv_bfloat16 sA[2][2][64][40];
    __shared__ __align__(16) __nv_bfloat16 sB[2][2][64][40];
    mma_body(Ahg, Alg, Bhg, Blg, bias, resid, C, nullptr, nullptr, nullptr,
             nullptr, nullptr, nullptr, sA, sB, blockIdx.y * 64, blockIdx.x * 64);
}

// ===========================================================================
// t_mma: T[q][bh][e] (hi/lo) = (qh + v_bias) @ Wr_h^T, per head.
// ===========================================================================
__global__ void __launch_bounds__(256, 2)
t_mma()
{
    __shared__ __align__(16) __nv_bfloat16 tA[2][64][72];
    __shared__ __align__(16) __nv_bfloat16 tB[2][64][72];
    int tid = threadIdx.x, lane = tid & 31, wid = tid >> 5;
    int wm = wid >> 2, wn = wid & 3;
    int h = blockIdx.z, hoff = h * DHH;
    int m0 = blockIdx.y * 64, e0 = blockIdx.x * 64;
    int r = lane >> 2, t4 = lane & 3;
    float acc[2][2][4] = {};

    #pragma unroll
    for (int j = 0; j < 2; j++) {
        int c = tid + j * 256;
        int row = c >> 3, off = (c & 7) * 8;
        *(uint4*)&tA[0][row][off] = *(const uint4*)((const uint16_t*)g_qv_h + (size_t)(m0 + row) * DD + hoff + off);
        *(uint4*)&tA[1][row][off] = *(const uint4*)((const uint16_t*)g_qv_l + (size_t)(m0 + row) * DD + hoff + off);
        *(uint4*)&tB[0][row][off] = *(const uint4*)((const uint16_t*)g_wr_h + (size_t)(e0 + row) * DD + hoff + off);
        *(uint4*)&tB[1][row][off] = *(const uint4*)((const uint16_t*)g_wr_l + (size_t)(e0 + row) * DD + hoff + off);
    }
    __syncthreads();

    #pragma unroll
    for (int ks = 0; ks < 4; ks++) {
        uint32_t ah[2][4], al[2][4];
        #pragma unroll
        for (int mi = 0; mi < 2; mi++) {
            int row = wm * 32 + mi * 16 + r;
            const __nv_bfloat16* ph = &tA[0][row][ks * 16 + t4 * 2];
            const __nv_bfloat16* pl = &tA[1][row][ks * 16 + t4 * 2];
            ah[mi][0] = *(const uint32_t*)ph;
            ah[mi][1] = *(const uint32_t*)(ph + 8 * 72);
            ah[mi][2] = *(const uint32_t*)(ph + 8);
            ah[mi][3] = *(const uint32_t*)(ph + 8 * 72 + 8);
            al[mi][0] = *(const uint32_t*)pl;
            al[mi][1] = *(const uint32_t*)(pl + 8 * 72);
            al[mi][2] = *(const uint32_t*)(pl + 8);
            al[mi][3] = *(const uint32_t*)(pl + 8 * 72 + 8);
        }
        #pragma unroll
        for (int nj = 0; nj < 2; nj++) {
            int n = wn * 16 + nj * 8 + r;
            const __nv_bfloat16* qh = &tB[0][n][ks * 16 + t4 * 2];
            const __nv_bfloat16* ql = &tB[1][n][ks * 16 + t4 * 2];
            uint32_t bh0 = *(const uint32_t*)qh, bh1 = *(const uint32_t*)(qh + 8);
            uint32_t bl0 = *(const uint32_t*)ql, bl1 = *(const uint32_t*)(ql + 8);
            #pragma unroll
            for (int mi = 0; mi < 2; mi++) {
                MMA_BF16(acc[mi][nj], ah[mi], bh0, bh1);
                MMA_BF16(acc[mi][nj], ah[mi], bl0, bl1);
                MMA_BF16(acc[mi][nj], al[mi], bh0, bh1);
            }
        }
    }
    #pragma unroll
    for (int mi = 0; mi < 2; mi++) {
        #pragma unroll
        for (int nj = 0; nj < 2; nj++) {
            int e = e0 + wn * 16 + nj * 8 + t4 * 2;
            #pragma unroll
            for (int rr = 0; rr < 2; rr++) {
                int m = m0 + wm * 32 + mi * 16 + r + rr * 8;
                int q = m & 511, b = m >> 9;
                int bh = b * HH + h;
                uint32_t hh, ll;
                split2(acc[mi][nj][rr * 2 + 0], acc[mi][nj][rr * 2 + 1], hh, ll);
                size_t di = ((size_t)q * BHH + bh) * DD + e;
                *(uint32_t*)((uint16_t*)g_T_h + di) = hh;
                *(uint32_t*)((uint16_t*)g_T_l + di) = ll;
            }
        }
    }
}

// c[b,q,h] = sum_d (qh+v_bias)*br_h
__global__ void c_kernel(const float* __restrict__ vb, const float* __restrict__ br)
{
    int idx = blockIdx.x * blockDim.x + threadIdx.x;
    if (idx >= MR * HH) return;
    int h = idx & 7;
    int m = idx >> 3;
    int hoff = h * DHH;
    const float* qrow = g_qh + (size_t)m * DD + hoff;
    float s = 0.f;
    #pragma unroll 8
    for (int d = 0; d < DHH; d++)
        s += (qrow[d] + vb[hoff + d]) * br[hoff + d];
    g_c[idx] = s;
}

// ===========================================================================
// ac_mma: score[bh,q,k] = (qh+u).kh raw, smem-staged tiles.
// ===========================================================================
__global__ void __launch_bounds__(256, 2)
ac_mma(float* __restrict__ score)
{
    __shared__ __align__(16) __nv_bfloat16 tA[2][64][72];
    __shared__ __align__(16) __nv_bfloat16 tB[2][64][72];
    int bh = blockIdx.z, b = bh >> 3, h = bh & 7, hoff = h * DHH;
    int q0 = blockIdx.y * 64, k0 = blockIdx.x * 64;
    int tid = threadIdx.x, lane = tid & 31, wid = tid >> 5;
    int wm = wid >> 2, wn = wid & 3;
    int r = lane >> 2, t4 = lane & 3;

    {
        const uint4* mp = (const uint4*)(g_am + (size_t)(q0 + (tid >> 1)) * SKL + k0 + (tid & 1) * 32);
        uint4 m1 = mp[0], m2 = mp[1];
        int allm = bytes_all_nz(m1.x) & bytes_all_nz(m1.y) & bytes_all_nz(m1.z) & bytes_all_nz(m1.w)
                 & bytes_all_nz(m2.x) & bytes_all_nz(m2.y) & bytes_all_nz(m2.z) & bytes_all_nz(m2.w);
        if (__syncthreads_and(allm)) return;
    }

    float acc[2][2][4] = {};
    #pragma unroll
    for (int j = 0; j < 2; j++) {
        int c = tid + j * 256;
        int row = c >> 3, off = (c & 7) * 8;
        *(uint4*)&tA[0][row][off] = *(const uint4*)((const uint16_t*)g_qu_h + (size_t)(b * SQL + q0 + row) * DD + hoff + off);
        *(uint4*)&tA[1][row][off] = *(const uint4*)((const uint16_t*)g_qu_l + (size_t)(b * SQL + q0 + row) * DD + hoff + off);
        *(uint4*)&tB[0][row][off] = *(const uint4*)((const uint16_t*)g_kh_h + (size_t)(b * SQL + k0 + row) * DD + hoff + off);
        *(uint4*)&tB[1][row][off] = *(const uint4*)((const uint16_t*)g_kh_l + (size_t)(b * SQL + k0 + row) * DD + hoff + off);
    }
    __syncthreads();

    #pragma unroll
    for (int ks = 0; ks < 4; ks++) {
        uint32_t ah[2][4], al[2][4];
        #pragma unroll
        for (int mi = 0; mi < 2; mi++) {
            int row = wm * 32 + mi * 16 + r;
            const __nv_bfloat16* ph = &tA[0][row][ks * 16 + t4 * 2];
            const __nv_bfloat16* pl = &tA[1][row][ks * 16 + t4 * 2];
            ah[mi][0] = *(const uint32_t*)ph;
            ah[mi][1] = *(const uint32_t*)(ph + 8 * 72);
            ah[mi][2] = *(const uint32_t*)(ph + 8);
            ah[mi][3] = *(const uint32_t*)(ph + 8 * 72 + 8);
            al[mi][0] = *(const uint32_t*)pl;
            al[mi][1] = *(const uint32_t*)(pl + 8 * 72);
            al[mi][2] = *(const uint32_t*)(pl + 8);
            al[mi][3] = *(const uint32_t*)(pl + 8 * 72 + 8);
        }
        #pragma unroll
        for (int nj = 0; nj < 2; nj++) {
            int n = wn * 16 + nj * 8 + r;
            const __nv_bfloat16* qh = &tB[0][n][ks * 16 + t4 * 2];
            const __nv_bfloat16* ql = &tB[1][n][ks * 16 + t4 * 2];
            uint32_t bh0 = *(const uint32_t*)qh, bh1 = *(const uint32_t*)(qh + 8);
            uint32_t bl0 = *(const uint32_t*)ql, bl1 = *(const uint32_t*)(ql + 8);
            #pragma unroll
            for (int mi = 0; mi < 2; mi++) {
                MMA_BF16(acc[mi][nj], ah[mi], bh0, bh1);
                MMA_BF16(acc[mi][nj], ah[mi], bl0, bl1);
                MMA_BF16(acc[mi][nj], al[mi], bh0, bh1);
            }
        }
    }
    #pragma unroll
    for (int mi = 0; mi < 2; mi++) {
        #pragma unroll
        for (int nj = 0; nj < 2; nj++) {
            int k = k0 + wn * 16 + nj * 8 + t4 * 2;
            #pragma unroll
            for (int rr = 0; rr < 2; rr++) {
                int q = q0 + wm * 32 + mi * 16 + r + rr * 8;
                *(float2*)(score + ((size_t)bh * SQL + q) * SKL + k) =
                    make_float2(acc[mi][nj][rr * 2 + 0], acc[mi][nj][rr * 2 + 1]);
            }
        }
    }
}

// ===========================================================================
// bd_sm_mma: score -> attn_weights fused (bd + masked softmax in place).
// ===========================================================================
__global__ void __launch_bounds__(256)
bd_sm_mma(const float* __restrict__ pos_emb, float* __restrict__ score)
{
    __shared__ __align__(16) __nv_bfloat16 sT[2][32][136];
    __shared__ unsigned char cmask[BB][SKL];
    __shared__ float smax[BHH][9], ssum[BHH][9];
    int q = blockIdx.x;
    int tid = threadIdx.x, lane = tid & 31, wn = tid >> 5;
    int r = lane >> 2, t4 = lane & 3;

    #pragma unroll
    for (int j = 0; j < 8; j++) {
        int i = tid + j * 256;
        int b = i >> 9, kk = i & 511;
        cmask[b][kk] = g_am[(size_t)q * SKL + kk] | g_kpm[(size_t)b * SKL + kk];
    }

    int k_a = wn * 64 + lane * 2;
    unsigned char ma = g_am[(size_t)q * SKL + k_a];
    unsigned char mb = g_am[(size_t)q * SKL + k_a + 1];
    int act = __ballot_sync(0xffffffffu, (ma == 0) || (mb == 0)) != 0;

    float acc[2][8][4] = {};

    #pragma unroll 1
    for (int ec = 0; ec < 4; ec++) {
        #pragma unroll
        for (int j = 0; j < 2; j++) {
            int c = tid + j * 256;
            int row = c >> 4, off = (c & 15) * 8;
            size_t gi = ((size_t)q * BHH + row) * DD + ec * 128 + off;
            *(uint4*)&sT[0][row][off] = *(const uint4*)((const uint16_t*)g_T_h + gi);
            *(uint4*)&sT[1][row][off] = *(const uint4*)((const uint16_t*)g_T_l + gi);
        }
        __syncthreads();
        if (act) {
            #pragma unroll 1
            for (int ks = 0; ks < 8; ks++) {
                uint32_t ah[2][4], al[2][4];
                #pragma unroll
                for (int mi = 0; mi < 2; mi++) {
                    int row = mi * 16 + r;
                    const __nv_bfloat16* ph = &sT[0][row][ks * 16 + t4 * 2];
                    const __nv_bfloat16* pl = &sT[1][row][ks * 16 + t4 * 2];
                    ah[mi][0] = *(const uint32_t*)ph;
                    ah[mi][1] = *(const uint32_t*)(ph + 8 * 136);
                    ah[mi][2] = *(const uint32_t*)(ph + 8);
                    ah[mi][3] = *(const uint32_t*)(ph + 8 * 136 + 8);
                    al[mi][0] = *(const uint32_t*)pl;
                    al[mi][1] = *(const uint32_t*)(pl + 8 * 136);
                    al[mi][2] = *(const uint32_t*)(pl + 8);
                    al[mi][3] = *(const uint32_t*)(pl + 8 * 136 + 8);
                }
                int eg = ec * 128 + ks * 16 + t4 * 2;
                #pragma unroll
                for (int nj = 0; nj < 8; nj++) {
                    int n = wn * 64 + nj * 8 + r;
                    const float* pp = pos_emb + ((size_t)q * SKL + n) * DD + eg;
                    float2 p0 = *(const float2*)pp;
                    float2 p1 = *(const float2*)(pp + 8);
                    uint32_t bh0, bl0, bh1, bl1;
                    split2(p0.x, p0.y, bh0, bl0);
                    split2(p1.x, p1.y, bh1, bl1);
                    #pragma unroll
                    for (int mi = 0; mi < 2; mi++) {
                        MMA_BF16(acc[mi][nj], ah[mi], bh0, bh1);
                        MMA_BF16(acc[mi][nj], ah[mi], bl0, bl1);
                        MMA_BF16(acc[mi][nj], al[mi], bh0, bh1);
                    }
                }
            }
        }
        __syncthreads();
    }

    float rmax[2][2] = {{-INFINITY, -INFINITY}, {-INFINITY, -INFINITY}};
    #pragma unroll
    for (int mi = 0; mi < 2; mi++) {
        #pragma unroll
        for (int rr = 0; rr < 2; rr++) {
            int bh = mi * 16 + r + rr * 8;
            int b = bh >> 3, h = bh & 7;
            float cc = g_c[((size_t)b * SQL + q) * HH + h];
            const float* srow = score + ((size_t)bh * SQL + q) * SKL;
            #pragma unroll
            for (int nj = 0; nj < 8; nj++) {
                int k = wn * 64 + nj * 8 + t4 * 2;
                float2 s2 = *(const float2*)(srow + k);
                float v0 = (s2.x + acc[mi][nj][rr * 2 + 0] + cc) * 0.125f;
                float v1 = (s2.y + acc[mi][nj][rr * 2 + 1] + cc) * 0.125f;
                if (cmask[b][k])     v0 = -INFINITY;
                if (cmask[b][k + 1]) v1 = -INFINITY;
                acc[mi][nj][rr * 2 + 0] = v0;
                acc[mi][nj][rr * 2 + 1] = v1;
                rmax[mi][rr] = fmaxf(rmax[mi][rr], fmaxf(v0, v1));
            }
        }
    }
    #pragma unroll
    for (int mi = 0; mi < 2; mi++)
        #pragma unroll
        for (int rr = 0; rr < 2; rr++) {
            rmax[mi][rr] = fmaxf(rmax[mi][rr], __shfl_xor_sync(0xffffffffu, rmax[mi][rr], 1));
            rmax[mi][rr] = fmaxf(rmax[mi][rr], __shfl_xor_sync(0xffffffffu, rmax[mi][rr], 2));
        }
    if (t4 == 0) {
        #pragma unroll
        for (int mi = 0; mi < 2; mi++)
            #pragma unroll
            for (int rr = 0; rr < 2; rr++)
                smax[mi * 16 + r + rr * 8][wn] = rmax[mi][rr];
    }
    __syncthreads();

    float rsum[2][2];
    #pragma unroll
    for (int mi = 0; mi < 2; mi++) {
        #pragma unroll
        for (int rr = 0; rr < 2; rr++) {
            int bh = mi * 16 + r + rr * 8;
            float gm = smax[bh][0];
            #pragma unroll
            for (int w = 1; w < 8; w++) gm = fmaxf(gm, smax[bh][w]);
            float sum = 0.f;
            #pragma unroll
            for (int nj = 0; nj < 8; nj++) {
                #pragma unroll
                for (int c = 0; c < 2; c++) {
                    float v = acc[mi][nj][rr * 2 + c];
                    float e = (v == -INFINITY) ? 0.f : __expf(v - gm);
                    acc[mi][nj][rr * 2 + c] = e;
                    sum += e;
                }
            }
            sum += __shfl_xor_sync(0xffffffffu, sum, 1);
            sum += __shfl_xor_sync(0xffffffffu, sum, 2);
            rsum[mi][rr] = sum;
        }
    }
    if (t4 == 0) {
        #pragma unroll
        for (int mi = 0; mi < 2; mi++)
            #pragma unroll
            for (int rr = 0; rr < 2; rr++)
                ssum[mi * 16 + r + rr * 8][wn] = rsum[mi][rr];
    }
    __syncthreads();

    #pragma unroll
    for (int mi = 0; mi < 2; mi++) {
        #pragma unroll
        for (int rr = 0; rr < 2; rr++) {
            int bh = mi * 16 + r + rr * 8;
            float tot = 0.f;
            #pragma unroll
            for (int w = 0; w < 8; w++) tot += ssum[bh][w];
            float inv = (tot > 0.f) ? 1.f / tot : 0.f;
            float* srow = score + ((size_t)bh * SQL + q) * SKL;
            #pragma unroll
            for (int nj = 0; nj < 8; nj++) {
                int k = wn * 64 + nj * 8 + t4 * 2;
                *(float2*)(srow + k) = make_float2(acc[mi][nj][rr * 2 + 0] * inv,
                                                   acc[mi][nj][rr * 2 + 1] * inv);
            }
        }
    }
}

// ===========================================================================
// av_mma: att[b,q,hoff+d] = sum_k w[bh,q,k] * vh[b,k,hoff+d], tensorized.
// M=64(q) N=64(d), K-loop over 8 chunks of 64 with exact mask skip.
// Weights split on the fly into smem; vh transposed+split during staging.
// ===========================================================================
__global__ void __launch_bounds__(256, 2)
av_mma(const float* __restrict__ score)
{
    __shared__ __align__(16) __nv_bfloat16 tA[2][64][72];  // [hi/lo][q][kseq]
    __shared__ __align__(16) __nv_bfloat16 tB[2][64][72];  // [hi/lo][d][kseq]
    int bh = blockIdx.y, b = bh >> 3, h = bh & 7, hoff = h * DHH;
    int q0 = blockIdx.x * 64;
    int tid = threadIdx.x, lane = tid & 31, wid = tid >> 5;
    int wm = wid >> 2, wn = wid & 3;
    int r = lane >> 2, t4 = lane & 3;
    float acc[2][2][4] = {};

    int arow = tid >> 2;            // 0..63 (q row / also used for A staging)
    int ac0  = (tid & 3) * 16;      // 0..48 (k col base, 16 floats)
    int srow = tid & 63;            // 0..63 (seq row for B staging)
    int dg   = tid >> 6;            // 0..3  (d col group of 16)

    #pragma unroll 1
    for (int kc = 0; kc < 8; kc++) {
        int k0 = kc * 64;
        // exact 64x64 mask-tile skip (this barrier also separates prev compute
        // from this chunk's staging)
        {
            const uint4* mp = (const uint4*)(g_am + (size_t)(q0 + (tid >> 1)) * SKL + k0 + (tid & 1) * 32);
            uint4 m1 = mp[0], m2 = mp[1];
            int allm = bytes_all_nz(m1.x) & bytes_all_nz(m1.y) & bytes_all_nz(m1.z) & bytes_all_nz(m1.w)
                     & bytes_all_nz(m2.x) & bytes_all_nz(m2.y) & bytes_all_nz(m2.z) & bytes_all_nz(m2.w);
            if (__syncthreads_and(allm)) continue;
        }
        // stage A: weights f32 -> hi/lo smem. 16 floats per thread.
        {
            const float* wp = score + ((size_t)bh * SQL + q0 + arow) * SKL + k0 + ac0;
            #pragma unroll
            for (int i = 0; i < 4; i++) {
                float4 w4 = *(const float4*)(wp + i * 4);
                uint32_t h0, l0, h1, l1;
                split2(w4.x, w4.y, h0, l0);
                split2(w4.z, w4.w, h1, l1);
                *(uint32_t*)&tA[0][arow][ac0 + i * 4]     = h0;
                *(uint32_t*)&tA[0][arow][ac0 + i * 4 + 2] = h1;
                *(uint32_t*)&tA[1][arow][ac0 + i * 4]     = l0;
                *(uint32_t*)&tA[1][arow][ac0 + i * 4 + 2] = l1;
            }
        }
        // stage B: vh[b][k0+srow][hoff+d] -> tB[d][srow] hi/lo (transpose+split)
        {
            const float* vp = g_vh + ((size_t)b * SQL + k0 + srow) * DD + hoff + dg * 16;
            #pragma unroll
            for (int i = 0; i < 4; i++) {
                float4 v4 = *(const float4*)(vp + i * 4);
                float vv[4] = {v4.x, v4.y, v4.z, v4.w};
                #pragma unroll
                for (int j = 0; j < 4; j++) {
                    int d = dg * 16 + i * 4 + j;
                    __nv_bfloat16 hb = __float2bfloat16_rn(vv[j]);
                    __nv_bfloat16 lb = __float2bfloat16_rn(vv[j] - __bfloat162float(hb));
                    tB[0][d][srow] = hb;
                    tB[1][d][srow] = lb;
                }
            }
        }
        __syncthreads();

        #pragma unroll
        for (int ks = 0; ks < 4; ks++) {
            uint32_t ah[2][4], al[2][4];
            #pragma unroll
            for (int mi = 0; mi < 2; mi++) {
                int row = wm * 32 + mi * 16 + r;
                const __nv_bfloat16* ph = &tA[0][row][ks * 16 + t4 * 2];
                const __nv_bfloat16* pl = &tA[1][row][ks * 16 + t4 * 2];
                ah[mi][0] = *(const uint32_t*)ph;
                ah[mi][1] = *(const uint32_t*)(ph + 8 * 72);
                ah[mi][2] = *(const uint32_t*)(ph + 8);
                ah[mi][3] = *(const uint32_t*)(ph + 8 * 72 + 8);
                al[mi][0] = *(const uint32_t*)pl;
                al[mi][1] = *(const uint32_t*)(pl + 8 * 72);
                al[mi][2] = *(const uint32_t*)(pl + 8);
                al[mi][3] = *(const uint32_t*)(pl + 8 * 72 + 8);
            }
            #pragma unroll
            for (int nj = 0; nj < 2; nj++) {
                int n = wn * 16 + nj * 8 + r;
                const __nv_bfloat16* qh = &tB[0][n][ks * 16 + t4 * 2];
                const __nv_bfloat16* ql = &tB[1][n][ks * 16 + t4 * 2];
                uint32_t bh0 = *(const uint32_t*)qh, bh1 = *(const uint32_t*)(qh + 8);
                uint32_t bl0 = *(const uint32_t*)ql, bl1 = *(const uint32_t*)(ql + 8);
                #pragma unroll
                for (int mi = 0; mi < 2; mi++) {
                    MMA_BF16(acc[mi][nj], ah[mi], bh0, bh1);
                    MMA_BF16(acc[mi][nj], ah[mi], bl0, bl1);
                    MMA_BF16(acc[mi][nj], al[mi], bh0, bh1);
                }
            }
        }
        __syncthreads();
    }

    // epilogue: write g_att + fused hi/lo split for the Wo projection
    #pragma unroll
    for (int mi = 0; mi < 2; mi++) {
        #pragma unroll
        for (int nj = 0; nj < 2; nj++) {
            int dcol = hoff + wn * 16 + nj * 8 + t4 * 2;
            #pragma unroll
            for (int rr = 0; rr < 2; rr++) {
                int q = q0 + wm * 32 + mi * 16 + r + rr * 8;
                size_t oi = ((size_t)b * SQL + q) * DD + dcol;
                float v0 = acc[mi][nj][rr * 2 + 0], v1 = acc[mi][nj][rr * 2 + 1];
                *(float2*)(g_att + oi) = make_float2(v0, v1);
                uint32_t hh, ll;
                split2(v0, v1, hh, ll);
                *(uint32_t*)((uint16_t*)g_at_h + oi) = hh;
                *(uint32_t*)((uint16_t*)g_at_l + oi) = ll;
            }
        }
    }
}

// ===========================================================================
__global__ void ln_kernel(const float* __restrict__ X, const float* __restrict__ gamma,
                          const float* __restrict__ beta, float* __restrict__ out)
{
    int row = blockIdx.x;
    int tid = threadIdx.x;  // 256
    const float* x = X + (size_t)row * DD;
    float2 v = *(const float2*)(x + tid * 2);
    float s = v.x + v.y;
    float s2 = v.x * v.x + v.y * v.y;
    #pragma unroll
    for (int off = 16; off; off >>= 1) {
        s  += __shfl_xor_sync(0xffffffffu, s, off);
        s2 += __shfl_xor_sync(0xffffffffu, s2, off);
    }
    __shared__ float rs[8], rs2[8];
    int wid = tid >> 5, lane = tid & 31;
    if (lane == 0) { rs[wid] = s; rs2[wid] = s2; }
    __syncthreads();
    s = 0.f; s2 = 0.f;
    #pragma unroll
    for (int i = 0; i < 8; i++) { s += rs[i]; s2 += rs2[i]; }
    float mean = s * (1.f / DD);
    float var = s2 * (1.f / DD) - mean * mean;
    float inv = rsqrtf(var + 1e-5f);
    float2 g2 = *(const float2*)(gamma + tid * 2);
    float2 b2 = *(const float2*)(beta + tid * 2);
    float2 o;
    o.x = (v.x - mean) * inv * g2.x + b2.x;
    o.y = (v.y - mean) * inv * g2.y + b2.y;
    *(float2*)(out + (size_t)row * DD + tid * 2) = o;
}

// ===========================================================================
extern "C" void kernel_launch(void* const* d_in, const int* in_sizes, int n_in,
                              void* d_out, int out_size)
{
    const float* q  = (const float*)d_in[0];
    const float* k  = (const float*)d_in[1];
    const float* v  = (const float*)d_in[2];
    const float* pe = (const float*)d_in[3];
    const unsigned char* kpm = (const unsigned char*)d_in[4];
    const unsigned char* am  = (const unsigned char*)d_in[5];
    const float* Wq = (const float*)d_in[6];
    const float* bq = (const float*)d_in[7];
    const float* Wk = (const float*)d_in[8];
    const float* bk = (const float*)d_in[9];
    const float* Wv = (const float*)d_in[10];
    const float* bv = (const float*)d_in[11];
    const float* Wo = (const float*)d_in[12];
    const float* bo = (const float*)d_in[13];
    const float* Wr = (const float*)d_in[14];
    const float* br = (const float*)d_in[15];
    const float* ub = (const float*)d_in[16];
    const float* vb = (const float*)d_in[17];
    const float* lg = (const float*)d_in[18];
    const float* lb = (const float*)d_in[19];

    float* normed = (float*)d_out;
    float* attnw  = normed + (size_t)BB * SQL * DD;

    float *o2;
    cudaGetSymbolAddress((void**)&o2,  g_o2);
    __nv_bfloat16 *woh, *wol, *ath, *atl;
    cudaGetSymbolAddress((void**)&woh, g_wo_h); cudaGetSymbolAddress((void**)&wol, g_wo_l);
    cudaGetSymbolAddress((void**)&ath, g_at_h); cudaGetSymbolAddress((void**)&atl, g_at_l);

    // mask normalization
    mask_detect<<<1, 1024>>>(am);
    mask_convert<<<64, 256>>>(am, kpm);

    // operand conversions
    conv_inputs<<<dim3(MR * DD / 4 / 256, 1, 3), 256>>>(q, k, v);
    conv_w<<<dim3(16, 16, 4), dim3(32, 32)>>>(Wq, Wk, Wv, Wo);
    conv_wr<<<DD * DD / 4 / 256, 256>>>(Wr);

    // fused Q/K/V projections; Q emits split(qh+vb) + split(qh+ub), K emits split(kh)
    mma_qkv<<<dim3(8, 32, 3), 256>>>(bq, bk, bv, vb, ub);

    c_kernel<<<(MR * HH + 255) / 256, 256>>>(vb, br);
    t_mma<<<dim3(8, 32, 8), 256>>>();

    ac_mma<<<dim3(8, 8, 32), 256>>>(attnw);
    bd_sm_mma<<<512, 256>>>(pe, attnw);

    av_mma<<<dim3(8, 32), 256>>>(attnw);

    mma2<<<dim3(8, 32), 256>>>(ath, atl, woh, wol, bo, q, o2);
    ln_kernel<<<MR, 256>>>(o2, lg, lb, normed);
}